// round 2
// baseline (speedup 1.0000x reference)
#include <cuda_runtime.h>
#include <cuda_bf16.h>
#include <math.h>

#define NN 64
#define BB 32
#define HH 512
#define KK 128
#define VV 32000
#define TT 256
#define SS 32
#define AA 5
#define AN 20
#define M2 (NN*BB)          // 2048 rows
#define CIN (3*HH+KK)       // 1664
#define GIN (2*HH+AN)       // 1044
#define NASP 2000

// ---------------- scratch (static device globals; no runtime alloc) ----------------
__device__ __align__(16) float g_emb[M2*HH];
__device__ __align__(16) float g_gi[M2*3*HH];
__device__ __align__(16) float g_hbuf0[BB*HH];
__device__ __align__(16) float g_hbuf1[BB*HH];
__device__ __align__(16) float g_rnn[M2*HH];
__device__ float g_u1[HH], g_u1e[HH], g_u3[HH], g_u3e[KK], g_bv[2];
__device__ float g_a1[M2], g_a3[M2];
__device__ float g_c1[TT*BB], g_c2[SS*BB], g_c3[AA*BB];
__device__ __align__(16) float g_ctx1[M2*HH];
__device__ __align__(16) float g_ctx2[M2*HH];
__device__ __align__(16) float g_ctx3[M2*KK];
__device__ __align__(16) float g_cin[M2*CIN];
__device__ __align__(16) float g_cout[M2*HH];
__device__ float g_e4[BB*AN];
__device__ __align__(16) float g_gin[M2*GIN];
__device__ int g_first[NASP], g_next[NASP];

// ---------------- kernels ----------------

__global__ void k_embed(const int* __restrict__ seq, const float* __restrict__ emb) {
    int i = blockIdx.x * blockDim.x + threadIdx.x;           // N*B*H
    if (i < M2*HH) {
        int m = i / HH, h = i - m*HH;
        g_emb[i] = emb[(long)seq[m]*HH + h];
    }
}

// C[M,Nc] = A[M,K] * W[Nc,K]^T (+bias) (opt tanh). M%64==0, Nc%64==0, K%16==0.
__global__ void k_gemm_nt(const float* __restrict__ A, const float* __restrict__ W,
                          const float* __restrict__ bias, float* __restrict__ C,
                          int M, int Nc, int Kd, int act) {
    __shared__ float As[16][65];
    __shared__ float Ws[16][65];
    int tid = threadIdx.x;
    int tx = tid & 15, ty = tid >> 4;
    int m0 = blockIdx.y * 64, n0 = blockIdx.x * 64;
    float acc[4][4] = {};
    int r  = tid >> 2;
    int kc = (tid & 3) * 4;
    for (int k0 = 0; k0 < Kd; k0 += 16) {
        float4 av = *(const float4*)(A + (long)(m0 + r)*Kd + k0 + kc);
        As[kc+0][r] = av.x; As[kc+1][r] = av.y; As[kc+2][r] = av.z; As[kc+3][r] = av.w;
        float4 wv = *(const float4*)(W + (long)(n0 + r)*Kd + k0 + kc);
        Ws[kc+0][r] = wv.x; Ws[kc+1][r] = wv.y; Ws[kc+2][r] = wv.z; Ws[kc+3][r] = wv.w;
        __syncthreads();
#pragma unroll
        for (int kk = 0; kk < 16; kk++) {
            float a[4], w[4];
#pragma unroll
            for (int i = 0; i < 4; i++) { a[i] = As[kk][ty*4+i]; w[i] = Ws[kk][tx*4+i]; }
#pragma unroll
            for (int i = 0; i < 4; i++)
#pragma unroll
                for (int j = 0; j < 4; j++) acc[i][j] += a[i]*w[j];
        }
        __syncthreads();
    }
#pragma unroll
    for (int i = 0; i < 4; i++) {
        int m = m0 + ty*4 + i;
#pragma unroll
        for (int j = 0; j < 4; j++) {
            int n = n0 + tx*4 + j;
            float v = acc[i][j] + (bias ? bias[n] : 0.f);
            if (act) v = tanhf(v);
            C[(long)m*Nc + n] = v;
        }
    }
}

// one GRU step: block = (b, 64-element h-chunk). 256 blocks, 256 threads.
__global__ void k_gru_step(const float* __restrict__ hprev, float* __restrict__ hcur,
                           const float* __restrict__ Whh, const float* __restrict__ bhh,
                           int n) {
    int b  = blockIdx.x >> 3;
    int h0 = (blockIdx.x & 7) * 64;
    __shared__ float sh[HH];
    __shared__ float sg[3][64];
    int tid = threadIdx.x;
    for (int k = tid; k < HH; k += 256) sh[k] = hprev[b*HH + k];
    __syncthreads();
    int warp = tid >> 5, lane = tid & 31;
    for (int d = warp; d < 192; d += 8) {
        int g = d >> 6;
        int j = h0 + (d & 63);
        int row = g*HH + j;
        const float* w = Whh + (long)row*HH;
        float s = 0.f;
#pragma unroll
        for (int k = lane; k < HH; k += 32) s += w[k]*sh[k];
#pragma unroll
        for (int o = 16; o > 0; o >>= 1) s += __shfl_xor_sync(0xffffffffu, s, o);
        if (lane == 0) sg[g][d & 63] = s + bhh[row];
    }
    __syncthreads();
    if (tid < 64) {
        int j = h0 + tid;
        const float* gi = g_gi + ((long)n*BB + b)*3*HH;
        float ir  = gi[j], iz = gi[HH + j], inn = gi[2*HH + j];
        float rr  = 1.f/(1.f + expf(-(ir + sg[0][tid])));
        float zz  = 1.f/(1.f + expf(-(iz + sg[1][tid])));
        float nn  = tanhf(inn + rr*sg[2][tid]);
        float hn  = (1.f - zz)*nn + zz*sh[j];
        hcur[b*HH + j] = hn;
        g_rnn[((long)n*BB + b)*HH + j] = hn;
    }
}

// projected attention vectors u = W_part^T v and scalar b·v
__global__ void k_uvec(const float* __restrict__ attnW, const float* __restrict__ attnv,
                       const float* __restrict__ attnb, const float* __restrict__ attrW,
                       const float* __restrict__ attrv, const float* __restrict__ attrb) {
    int i = blockIdx.x * blockDim.x + threadIdx.x;
    if (i < HH) {
        float s = 0.f; for (int h = 0; h < HH; h++) s += attnW[(long)h*(2*HH) + i]*attnv[h];
        g_u1[i] = s;
    } else if (i < 2*HH) {
        int k = i - HH;
        float s = 0.f; for (int h = 0; h < HH; h++) s += attnW[(long)h*(2*HH) + HH + k]*attnv[h];
        g_u1e[k] = s;
    } else if (i < 3*HH) {
        int k = i - 2*HH;
        float s = 0.f; for (int h = 0; h < HH; h++) s += attrW[(long)h*(HH+KK) + k]*attrv[h];
        g_u3[k] = s;
    } else if (i < 3*HH + KK) {
        int k = i - 3*HH;
        float s = 0.f; for (int h = 0; h < HH; h++) s += attrW[(long)h*(HH+KK) + HH + k]*attrv[h];
        g_u3e[k] = s;
    } else if (i == 3*HH + KK) {
        float s = 0.f; for (int h = 0; h < HH; h++) s += attnb[h]*attnv[h]; g_bv[0] = s;
    } else if (i == 3*HH + KK + 1) {
        float s = 0.f; for (int h = 0; h < HH; h++) s += attrb[h]*attrv[h]; g_bv[1] = s;
    }
}

// all scalar attention dot products (warp per output)
__global__ void k_ac(const float* __restrict__ enc1, const float* __restrict__ enc2,
                     const float* __restrict__ enc3) {
    int gw = (blockIdx.x * blockDim.x + threadIdx.x) >> 5;
    int lane = threadIdx.x & 31;
    const int E_A1 = M2, E_A3 = 2*M2, E_C1 = E_A3 + TT*BB, E_C2 = E_C1 + SS*BB, E_C3 = E_C2 + AA*BB;
    if (gw >= E_C3) return;
    const float* x; const float* u; float* dst; int len = HH; float add = 0.f;
    if (gw < E_A1)      { x = g_rnn + (long)gw*HH;          u = g_u1;  dst = g_a1 + gw;          add = g_bv[0]; }
    else if (gw < E_A3) { int m = gw - E_A1;  x = g_rnn + (long)m*HH;  u = g_u3;  dst = g_a3 + m; add = g_bv[1]; }
    else if (gw < E_C1) { int m = gw - E_A3;  x = enc1 + (long)m*HH;   u = g_u1e; dst = g_c1 + m; }
    else if (gw < E_C2) { int m = gw - E_C1;  x = enc2 + (long)m*HH;   u = g_u1e; dst = g_c2 + m; }
    else                { int m = gw - E_C2;  x = enc3 + (long)m*KK;   u = g_u3e; dst = g_c3 + m; len = KK; }
    float s = 0.f;
    for (int k = lane; k < len; k += 32) s += x[k]*u[k];
#pragma unroll
    for (int o = 16; o > 0; o >>= 1) s += __shfl_xor_sync(0xffffffffu, s, o);
    if (lane == 0) *dst = s + add;
}

// aw1: block per (b,n), T=256 threads
__global__ void k_softmax1(float* __restrict__ aw1) {
    int bn = blockIdx.x;
    int b = bn / NN, n = bn - b*NN;
    int t = threadIdx.x;
    float e  = tanhf(g_a1[n*BB + b] + g_c1[t*BB + b]);
    float ex = expf(e);
    __shared__ float red[8];
    __shared__ float stot;
    float s = ex;
#pragma unroll
    for (int o = 16; o > 0; o >>= 1) s += __shfl_xor_sync(0xffffffffu, s, o);
    if ((t & 31) == 0) red[t >> 5] = s;
    __syncthreads();
    if (t == 0) { float tt = 0.f; for (int i = 0; i < 8; i++) tt += red[i]; stot = tt; }
    __syncthreads();
    aw1[(long)bn*TT + t] = ex / stot;
}

// aw2: warp per (b,n), lane = s
__global__ void k_softmax2(float* __restrict__ aw2) {
    int gw = (blockIdx.x * blockDim.x + threadIdx.x) >> 5;
    if (gw >= BB*NN) return;
    int b = gw / NN, n = gw - b*NN;
    int s = threadIdx.x & 31;
    float e  = tanhf(g_a1[n*BB + b] + g_c2[s*BB + b]);
    float ex = expf(e);
    float tot = ex;
#pragma unroll
    for (int o = 16; o > 0; o >>= 1) tot += __shfl_xor_sync(0xffffffffu, tot, o);
    aw2[(long)gw*SS + s] = ex / tot;
}

// aw3: thread per (b,n), loop A=5
__global__ void k_softmax3(float* __restrict__ aw3) {
    int bn = blockIdx.x * blockDim.x + threadIdx.x;
    if (bn >= BB*NN) return;
    int b = bn / NN, n = bn - b*NN;
    float ex[AA]; float tot = 0.f;
#pragma unroll
    for (int a = 0; a < AA; a++) {
        ex[a] = expf(tanhf(g_a3[n*BB + b] + g_c3[a*BB + b]));
        tot += ex[a];
    }
#pragma unroll
    for (int a = 0; a < AA; a++) aw3[(long)bn*AA + a] = ex[a] / tot;
}

// ctx[n,b,h] = sum_t aw[b,n,t] * enc[t,b,h]
__global__ void k_ctx(const float* __restrict__ aw, const float* __restrict__ enc,
                      float* __restrict__ dst, int L, int D) {
    int i = blockIdx.x * blockDim.x + threadIdx.x;
    if (i >= M2*D) return;
    int m = i / D, h = i - m*D;
    int n = m / BB, b = m - n*BB;
    const float* awp = aw + ((long)b*NN + n)*L;
    float s = 0.f;
    for (int t = 0; t < L; t++) s += awp[t]*enc[((long)t*BB + b)*D + h];
    dst[i] = s;
}

__global__ void k_concat() {
    int i = blockIdx.x * blockDim.x + threadIdx.x;
    if (i >= M2*CIN) return;
    int m = i / CIN, k = i - m*CIN;
    float v;
    if (k < HH)        v = g_rnn [m*HH + k];
    else if (k < 2*HH) v = g_ctx1[m*HH + k - HH];
    else if (k < 3*HH) v = g_ctx2[m*HH + k - 2*HH];
    else               v = g_ctx3[m*KK + k - 3*HH];
    g_cin[i] = v;
}

__global__ void k_e4(const float* __restrict__ enc4, const float* __restrict__ projW,
                     const float* __restrict__ projb) {
    int i = blockIdx.x * blockDim.x + threadIdx.x;
    if (i >= BB*AN) return;
    int b = i / AN, j = i - b*AN;
    float s = projb[j];
    for (int k = 0; k < AN; k++) s += enc4[(0*BB + b)*AN + k]*projW[j*2*AN + k];
    for (int k = 0; k < AN; k++) s += enc4[(1*BB + b)*AN + k]*projW[j*2*AN + AN + k];
    g_e4[i] = s;
}

__global__ void k_gin() {
    int i = blockIdx.x * blockDim.x + threadIdx.x;
    if (i >= M2*GIN) return;
    int m = i / GIN, k = i - m*GIN;
    int b = m % BB;
    float v;
    if (k < HH)        v = g_emb[m*HH + k];
    else if (k < 2*HH) v = g_rnn[m*HH + k - HH];
    else               v = g_e4[b*AN + k - 2*HH];
    g_gin[i] = v;
}

// gate: warp per (m, j)
__global__ void k_gate(const float* __restrict__ gateW, const float* __restrict__ gateb,
                       float* __restrict__ gateout) {
    int gw = (blockIdx.x * blockDim.x + threadIdx.x) >> 5;
    int lane = threadIdx.x & 31;
    if (gw >= M2*AN) return;
    int m = gw / AN, j = gw - m*AN;
    const float* x = g_gin + (long)m*GIN;
    const float* w = gateW + (long)j*GIN;
    float s = 0.f;
    for (int k = lane; k < GIN; k += 32) s += x[k]*w[k];
#pragma unroll
    for (int o = 16; o > 0; o >>= 1) s += __shfl_xor_sync(0xffffffffu, s, o);
    if (lane == 0) gateout[(long)m*AN + j] = tanhf(s + gateb[j]);
}

// duplicate-chain for deterministic scatter-add
__global__ void k_chain(const int* __restrict__ ids) {
    int j = blockIdx.x * blockDim.x + threadIdx.x;
    if (j >= NASP) return;
    int v = ids[j];
    int fst = 1;
    for (int j2 = 0; j2 < j; j2++) if (ids[j2] == v) { fst = 0; break; }
    int nxt = -1;
    for (int j2 = j + 1; j2 < NASP; j2++) if (ids[j2] == v) { nxt = j2; break; }
    g_first[j] = fst;
    g_next[j]  = nxt;
}

__global__ void k_scatter(const float* __restrict__ gate, const int* __restrict__ ids,
                          float* __restrict__ out0) {
    long i = (long)blockIdx.x * blockDim.x + threadIdx.x;
    if (i >= (long)M2*NASP) return;
    int m = (int)(i / NASP);
    int j = (int)(i - (long)m*NASP);
    if (!g_first[j]) return;
    float s = 0.f;
    int jj = j;
    while (jj >= 0) { s += gate[(long)m*AN + (jj % AN)]; jj = g_next[jj]; }
    out0[(long)m*VV + ids[j]] += s;
}

__global__ void k_hidden(float* __restrict__ dst) {
    int i = blockIdx.x * blockDim.x + threadIdx.x;
    if (i < BB*HH) dst[i] = g_rnn[(long)(NN-1)*BB*HH + i];
}

// ---------------- launcher ----------------
extern "C" void kernel_launch(void* const* d_in, const int* in_sizes, int n_in,
                              void* d_out, int out_size) {
    const int*   seq   = (const int*)  d_in[0];
    const float* lasth = (const float*)d_in[1];
    const float* enc1  = (const float*)d_in[2];
    const float* enc2  = (const float*)d_in[3];
    const float* enc3  = (const float*)d_in[4];
    const float* enc4  = (const float*)d_in[5];
    const int*   asp   = (const int*)  d_in[6];
    const float* emb   = (const float*)d_in[7];
    const float* Wih   = (const float*)d_in[8];
    const float* Whh   = (const float*)d_in[9];
    const float* bih   = (const float*)d_in[10];
    const float* bhh   = (const float*)d_in[11];
    const float* attnW = (const float*)d_in[12];
    const float* attnb = (const float*)d_in[13];
    const float* attnv = (const float*)d_in[14];
    const float* attrW = (const float*)d_in[15];
    const float* attrb = (const float*)d_in[16];
    const float* attrv = (const float*)d_in[17];
    const float* concW = (const float*)d_in[18];
    const float* concb = (const float*)d_in[19];
    const float* outW  = (const float*)d_in[20];
    const float* outb  = (const float*)d_in[21];
    const float* gateW = (const float*)d_in[22];
    const float* gateb = (const float*)d_in[23];
    const float* projW = (const float*)d_in[24];
    const float* projb = (const float*)d_in[25];
    float* out = (float*)d_out;

    // output layout: output, hidden, aw1, aw2, aw3, gate (reference tuple order)
    const long O_HID  = (long)M2*VV;
    const long O_AW1  = O_HID + (long)BB*HH;
    const long O_AW2  = O_AW1 + (long)BB*NN*TT;
    const long O_AW3  = O_AW2 + (long)BB*NN*SS;
    const long O_GATE = O_AW3 + (long)BB*NN*AA;

    float *p_emb, *p_gi, *p_cin, *p_cout, *p_ctx1, *p_ctx2, *p_ctx3, *p_h0, *p_h1;
    cudaGetSymbolAddress((void**)&p_emb,  g_emb);
    cudaGetSymbolAddress((void**)&p_gi,   g_gi);
    cudaGetSymbolAddress((void**)&p_cin,  g_cin);
    cudaGetSymbolAddress((void**)&p_cout, g_cout);
    cudaGetSymbolAddress((void**)&p_ctx1, g_ctx1);
    cudaGetSymbolAddress((void**)&p_ctx2, g_ctx2);
    cudaGetSymbolAddress((void**)&p_ctx3, g_ctx3);
    cudaGetSymbolAddress((void**)&p_h0,   g_hbuf0);
    cudaGetSymbolAddress((void**)&p_h1,   g_hbuf1);

    // 1) embedding
    k_embed<<<(M2*HH + 255)/256, 256>>>(seq, emb);

    // 2) gi = embedded @ Wih^T + bih   (2048 x 1536, K=512)
    k_gemm_nt<<<dim3(1536/64, M2/64), 256>>>(p_emb, Wih, bih, p_gi, M2, 3*HH, HH, 0);

    // 3) GRU scan (64 sequential steps)
    const float* hp = lasth;
    for (int n = 0; n < NN; n++) {
        float* hc = (n & 1) ? p_h1 : p_h0;
        k_gru_step<<<BB*(HH/64), 256>>>(hp, hc, Whh, bhh, n);
        hp = hc;
    }

    // 4) projected attention vectors + scalar dots
    k_uvec<<<(3*HH + KK + 2 + 255)/256, 256>>>(attnW, attnv, attnb, attrW, attrv, attrb);
    {
        int warps = 2*M2 + TT*BB + SS*BB + AA*BB;
        k_ac<<<(warps*32 + 255)/256, 256>>>(enc1, enc2, enc3);
    }

    // 5) softmaxes -> aw outputs
    k_softmax1<<<BB*NN, TT>>>(out + O_AW1);
    k_softmax2<<<(BB*NN*32 + 255)/256, 256>>>(out + O_AW2);
    k_softmax3<<<(BB*NN + 255)/256, 256>>>(out + O_AW3);

    // 6) contexts
    k_ctx<<<(M2*HH + 255)/256, 256>>>(out + O_AW1, enc1, p_ctx1, TT, HH);
    k_ctx<<<(M2*HH + 255)/256, 256>>>(out + O_AW2, enc2, p_ctx2, SS, HH);
    k_ctx<<<(M2*KK + 255)/256, 256>>>(out + O_AW3, enc3, p_ctx3, AA, KK);

    // 7) concat -> tanh GEMM -> big output GEMM
    k_concat<<<(M2*CIN + 255)/256, 256>>>();
    k_gemm_nt<<<dim3(HH/64, M2/64), 256>>>(p_cin, concW, concb, p_cout, M2, HH, CIN, 1);
    k_gemm_nt<<<dim3(VV/64, M2/64), 256>>>(p_cout, outW, outb, out, M2, VV, HH, 0);

    // 8) gate path
    k_e4<<<(BB*AN + 255)/256, 256>>>(enc4, projW, projb);
    k_gin<<<(M2*GIN + 255)/256, 256>>>();
    k_gate<<<(M2*AN*32 + 255)/256, 256>>>(gateW, gateb, out + O_GATE);

    // 9) deterministic scatter-add of tiled gate into output vocab slots
    k_chain<<<(NASP + 255)/256, 256>>>(asp);
    k_scatter<<<(int)(((long)M2*NASP + 255)/256), 256>>>(out + O_GATE, asp, out);

    // 10) hidden = final h
    k_hidden<<<(BB*HH + 255)/256, 256>>>(out + O_HID);
}

// round 4
// speedup vs baseline: 2.2867x; 2.2867x over previous
#include <cuda_runtime.h>
#include <cuda_bf16.h>
#include <math.h>
#include <stdint.h>

#define NN 64
#define BB 32
#define HH 512
#define KK 128
#define VV 32000
#define TT 256
#define SS 32
#define AA 5
#define AN 20
#define M2 (NN*BB)          // 2048 rows
#define CIN (3*HH+KK)       // 1664
#define GIN (2*HH+AN)       // 1044
#define NASP 2000
#define GRU_BLOCKS 128

// ---------------- scratch (static device globals; no runtime alloc) ----------------
__device__ __align__(16) float g_emb[M2*HH];
__device__ __align__(16) float g_gi[M2*3*HH];
__device__ __align__(16) float g_hA[HH*BB];
__device__ __align__(16) float g_hB[HH*BB];
__device__ __align__(16) float g_rnn[M2*HH];
__device__ float g_u1[HH], g_u1e[HH], g_u3[HH], g_u3e[KK], g_bv[2];
__device__ float g_a1[M2], g_a3[M2];
__device__ float g_c1[TT*BB], g_c2[SS*BB], g_c3[AA*BB];
__device__ __align__(16) float g_ctx1[M2*HH];
__device__ __align__(16) float g_ctx2[M2*HH];
__device__ __align__(16) float g_ctx3[M2*KK];
__device__ __align__(16) float g_cin[M2*CIN];
__device__ __align__(16) float g_cout[M2*HH];
__device__ float g_e4[BB*AN];
__device__ __align__(16) float g_gin[M2*GIN];
__device__ int g_first[NASP], g_next[NASP];
__device__ unsigned g_barcnt = 0;
__device__ unsigned g_bargen = 0;

// ---------------- small helpers ----------------
__device__ __forceinline__ void grid_barrier(unsigned nb) {
    __threadfence();
    __syncthreads();
    if (threadIdx.x == 0) {
        unsigned gen = *(volatile unsigned*)&g_bargen;
        if (atomicAdd(&g_barcnt, 1u) == nb - 1u) {
            *(volatile unsigned*)&g_barcnt = 0u;
            __threadfence();
            atomicAdd(&g_bargen, 1u);
        } else {
            while (*(volatile unsigned*)&g_bargen == gen) { __nanosleep(40); }
        }
    }
    __syncthreads();
}

// ---------------- kernels ----------------

__global__ void k_embed(const int* __restrict__ seq, const float* __restrict__ emb) {
    int i = blockIdx.x * blockDim.x + threadIdx.x;           // N*B*H
    if (i < M2*HH) {
        int m = i / HH, h = i - m*HH;
        g_emb[i] = emb[(long)seq[m]*HH + h];
    }
}

// fp32 SIMT GEMM: C[M,Nc] = A[M,K] * W[Nc,K]^T (+bias) (opt tanh).
__global__ void k_gemm_nt(const float* __restrict__ A, const float* __restrict__ W,
                          const float* __restrict__ bias, float* __restrict__ C,
                          int M, int Nc, int Kd, int act) {
    __shared__ float As[16][65];
    __shared__ float Ws[16][65];
    int tid = threadIdx.x;
    int tx = tid & 15, ty = tid >> 4;
    int m0 = blockIdx.y * 64, n0 = blockIdx.x * 64;
    float acc[4][4] = {};
    int r  = tid >> 2;
    int kc = (tid & 3) * 4;
    for (int k0 = 0; k0 < Kd; k0 += 16) {
        float4 av = *(const float4*)(A + (long)(m0 + r)*Kd + k0 + kc);
        As[kc+0][r] = av.x; As[kc+1][r] = av.y; As[kc+2][r] = av.z; As[kc+3][r] = av.w;
        float4 wv = *(const float4*)(W + (long)(n0 + r)*Kd + k0 + kc);
        Ws[kc+0][r] = wv.x; Ws[kc+1][r] = wv.y; Ws[kc+2][r] = wv.z; Ws[kc+3][r] = wv.w;
        __syncthreads();
#pragma unroll
        for (int kk = 0; kk < 16; kk++) {
            float a[4], w[4];
#pragma unroll
            for (int i = 0; i < 4; i++) { a[i] = As[kk][ty*4+i]; w[i] = Ws[kk][tx*4+i]; }
#pragma unroll
            for (int i = 0; i < 4; i++)
#pragma unroll
                for (int j = 0; j < 4; j++) acc[i][j] += a[i]*w[j];
        }
        __syncthreads();
    }
#pragma unroll
    for (int i = 0; i < 4; i++) {
        int m = m0 + ty*4 + i;
#pragma unroll
        for (int j = 0; j < 4; j++) {
            int n = n0 + tx*4 + j;
            float v = acc[i][j] + (bias ? bias[n] : 0.f);
            if (act) v = tanhf(v);
            C[(long)m*Nc + n] = v;
        }
    }
}

// ---------------- persistent GRU: all 64 steps, grid-barrier per step ----------------
__global__ __launch_bounds__(256, 1)
void k_gru_all(const float* __restrict__ lasth, const float* __restrict__ Whh,
               const float* __restrict__ bhh) {
    int tid = threadIdx.x, bk = blockIdx.x;
    int jl = (tid >> 5) & 3, b = tid & 31, kh = tid >> 7;
    int jg = bk*4 + jl;
    __shared__ __align__(16) float sw[3][4][HH];
    __shared__ float sb[3][4];
    __shared__ float part[3][128];

    // stage weight rows (once) — stays L1/smem resident for all 64 steps
    for (int r = 0; r < 12; r++) {
        int g = r / 4, j = r % 4;
        int row = g*HH + bk*4 + j;
        for (int k = tid; k < HH; k += 256) sw[g][j][k] = Whh[(long)row*HH + k];
    }
    if (tid < 12) sb[tid/4][tid%4] = bhh[(tid/4)*HH + bk*4 + (tid%4)];

    // transpose initial hidden into g_hA[k][b]
    if (tid < 128) {
        int idx = bk*128 + tid;           // 128*128 = 16384 = HH*BB
        int k = idx >> 5, bb = idx & 31;
        __stcg(&g_hA[idx], lasth[bb*HH + k]);
    }
    grid_barrier(GRU_BLOCKS);

    float* hp = g_hA;
    float* hc = g_hB;
    const float* wr = sw[0][jl];
    const float* wz = sw[1][jl];
    const float* wn = sw[2][jl];
    int k0 = kh * 256;

    for (int n = 0; n < NN; n++) {
        float sr = 0.f, sz = 0.f, sn = 0.f;
#pragma unroll 4
        for (int k = k0; k < k0 + 256; k += 4) {
            float4 r4 = *(const float4*)(wr + k);
            float4 z4 = *(const float4*)(wz + k);
            float4 n4 = *(const float4*)(wn + k);
            float h0 = __ldcg(hp + (k+0)*BB + b);
            float h1 = __ldcg(hp + (k+1)*BB + b);
            float h2 = __ldcg(hp + (k+2)*BB + b);
            float h3 = __ldcg(hp + (k+3)*BB + b);
            sr += r4.x*h0 + r4.y*h1 + r4.z*h2 + r4.w*h3;
            sz += z4.x*h0 + z4.y*h1 + z4.z*h2 + z4.w*h3;
            sn += n4.x*h0 + n4.y*h1 + n4.z*h2 + n4.w*h3;
        }
        if (kh == 1) {
            part[0][jl*32+b] = sr; part[1][jl*32+b] = sz; part[2][jl*32+b] = sn;
        }
        __syncthreads();
        if (kh == 0) {
            sr += part[0][jl*32+b]; sz += part[1][jl*32+b]; sn += part[2][jl*32+b];
            float hold = __ldcg(hp + jg*BB + b);
            const float* gi = g_gi + ((long)(n*BB + b))*(3*HH);
            float rr = 1.f/(1.f + expf(-(gi[jg]        + sr + sb[0][jl])));
            float zz = 1.f/(1.f + expf(-(gi[HH + jg]   + sz + sb[1][jl])));
            float nn = tanhf(gi[2*HH + jg] + rr*(sn + sb[2][jl]));
            float hn = (1.f - zz)*nn + zz*hold;
            __stcg(hc + jg*BB + b, hn);
            g_rnn[((long)(n*BB + b))*HH + jg] = hn;
        }
        grid_barrier(GRU_BLOCKS);
        float* t = hp; hp = hc; hc = t;
    }
}

// ---------------- tf32 tensor-core GEMM (out = cout @ outW^T + outb) ----------------
__device__ __forceinline__ uint32_t f2tf(float x) {
    uint32_t u; asm("cvt.rna.tf32.f32 %0, %1;" : "=r"(u) : "f"(x)); return u;
}
__device__ __forceinline__ void mma_tf32(float& c0, float& c1, float& c2, float& c3,
                                         uint32_t a0, uint32_t a1, uint32_t a2, uint32_t a3,
                                         uint32_t b0, uint32_t b1) {
    asm volatile("mma.sync.aligned.m16n8k8.row.col.f32.tf32.tf32.f32 "
                 "{%0,%1,%2,%3},{%4,%5,%6,%7},{%8,%9},{%0,%1,%2,%3};"
                 : "+f"(c0), "+f"(c1), "+f"(c2), "+f"(c3)
                 : "r"(a0), "r"(a1), "r"(a2), "r"(a3), "r"(b0), "r"(b1));
}
__device__ __forceinline__ void cpa16(uint32_t saddr, const void* gaddr) {
    asm volatile("cp.async.cg.shared.global [%0], [%1], 16;" :: "r"(saddr), "l"(gaddr));
}

// BM=128, BN=128, BK=16; 128 threads (4 warps 2x2), warp tile 64x64.
__global__ __launch_bounds__(128, 2)
void k_gemm_tf32(const float* __restrict__ A, const float* __restrict__ W,
                 const float* __restrict__ bias, float* __restrict__ C) {
    __shared__ __align__(16) float As[2][128][20];
    __shared__ __align__(16) float Bs[2][128][20];
    int tid = threadIdx.x;
    int warp = tid >> 5, lane = tid & 31;
    int wm = warp & 1, wnp = warp >> 1;          // 2 x 2 warp grid
    int lq = lane >> 2, lr = lane & 3;
    int m0 = blockIdx.y * 128, n0 = blockIdx.x * 128;

    float acc[4][8][4];
#pragma unroll
    for (int i = 0; i < 4; i++)
#pragma unroll
        for (int j = 0; j < 8; j++)
#pragma unroll
            for (int c = 0; c < 4; c++) acc[i][j][c] = 0.f;

    const int NK = HH / 16;   // 32 k-steps
#pragma unroll
    for (int i = 0; i < 4; i++) {
        int idx = i*128 + tid, row = idx >> 2, kc = idx & 3;
        cpa16((uint32_t)__cvta_generic_to_shared(&As[0][row][kc*4]),
              A + (long)(m0+row)*HH + kc*4);
        cpa16((uint32_t)__cvta_generic_to_shared(&Bs[0][row][kc*4]),
              W + (long)(n0+row)*HH + kc*4);
    }
    asm volatile("cp.async.commit_group;");

    int buf = 0;
    for (int ks = 0; ks < NK; ks++) {
        asm volatile("cp.async.wait_group 0;");
        __syncthreads();
        if (ks + 1 < NK) {
#pragma unroll
            for (int i = 0; i < 4; i++) {
                int idx = i*128 + tid, row = idx >> 2, kc = idx & 3;
                cpa16((uint32_t)__cvta_generic_to_shared(&As[buf^1][row][kc*4]),
                      A + (long)(m0+row)*HH + (ks+1)*16 + kc*4);
                cpa16((uint32_t)__cvta_generic_to_shared(&Bs[buf^1][row][kc*4]),
                      W + (long)(n0+row)*HH + (ks+1)*16 + kc*4);
            }
            asm volatile("cp.async.commit_group;");
        }
#pragma unroll
        for (int kk = 0; kk < 16; kk += 8) {
            uint32_t af[4][4], bf[8][2];
#pragma unroll
            for (int ms = 0; ms < 4; ms++) {
                int rb = wm*64 + ms*16;
                af[ms][0] = f2tf(As[buf][rb + lq    ][kk + lr    ]);
                af[ms][1] = f2tf(As[buf][rb + lq + 8][kk + lr    ]);
                af[ms][2] = f2tf(As[buf][rb + lq    ][kk + lr + 4]);
                af[ms][3] = f2tf(As[buf][rb + lq + 8][kk + lr + 4]);
            }
#pragma unroll
            for (int ns = 0; ns < 8; ns++) {
                int nb = wnp*64 + ns*8;
                bf[ns][0] = f2tf(Bs[buf][nb + lq][kk + lr    ]);
                bf[ns][1] = f2tf(Bs[buf][nb + lq][kk + lr + 4]);
            }
#pragma unroll
            for (int ms = 0; ms < 4; ms++)
#pragma unroll
                for (int ns = 0; ns < 8; ns++)
                    mma_tf32(acc[ms][ns][0], acc[ms][ns][1], acc[ms][ns][2], acc[ms][ns][3],
                             af[ms][0], af[ms][1], af[ms][2], af[ms][3],
                             bf[ns][0], bf[ns][1]);
        }
        buf ^= 1;
    }
    // epilogue
#pragma unroll
    for (int ms = 0; ms < 4; ms++) {
        int row = m0 + wm*64 + ms*16 + lq;
#pragma unroll
        for (int ns = 0; ns < 8; ns++) {
            int col = n0 + wnp*64 + ns*8 + lr*2;
            float b0 = bias[col], b1 = bias[col+1];
            float2 v0 = make_float2(acc[ms][ns][0] + b0, acc[ms][ns][1] + b1);
            float2 v1 = make_float2(acc[ms][ns][2] + b0, acc[ms][ns][3] + b1);
            *(float2*)(C + (long)row*VV + col)     = v0;
            *(float2*)(C + (long)(row+8)*VV + col) = v1;
        }
    }
}

// projected attention vectors u = W_part^T v and scalar b·v
__global__ void k_uvec(const float* __restrict__ attnW, const float* __restrict__ attnv,
                       const float* __restrict__ attnb, const float* __restrict__ attrW,
                       const float* __restrict__ attrv, const float* __restrict__ attrb) {
    int i = blockIdx.x * blockDim.x + threadIdx.x;
    if (i < HH) {
        float s = 0.f; for (int h = 0; h < HH; h++) s += attnW[(long)h*(2*HH) + i]*attnv[h];
        g_u1[i] = s;
    } else if (i < 2*HH) {
        int k = i - HH;
        float s = 0.f; for (int h = 0; h < HH; h++) s += attnW[(long)h*(2*HH) + HH + k]*attnv[h];
        g_u1e[k] = s;
    } else if (i < 3*HH) {
        int k = i - 2*HH;
        float s = 0.f; for (int h = 0; h < HH; h++) s += attrW[(long)h*(HH+KK) + k]*attrv[h];
        g_u3[k] = s;
    } else if (i < 3*HH + KK) {
        int k = i - 3*HH;
        float s = 0.f; for (int h = 0; h < HH; h++) s += attrW[(long)h*(HH+KK) + HH + k]*attrv[h];
        g_u3e[k] = s;
    } else if (i == 3*HH + KK) {
        float s = 0.f; for (int h = 0; h < HH; h++) s += attnb[h]*attnv[h]; g_bv[0] = s;
    } else if (i == 3*HH + KK + 1) {
        float s = 0.f; for (int h = 0; h < HH; h++) s += attrb[h]*attrv[h]; g_bv[1] = s;
    }
}

// all scalar attention dot products (warp per output)
__global__ void k_ac(const float* __restrict__ enc1, const float* __restrict__ enc2,
                     const float* __restrict__ enc3) {
    int gw = (blockIdx.x * blockDim.x + threadIdx.x) >> 5;
    int lane = threadIdx.x & 31;
    const int E_A1 = M2, E_A3 = 2*M2, E_C1 = E_A3 + TT*BB, E_C2 = E_C1 + SS*BB, E_C3 = E_C2 + AA*BB;
    if (gw >= E_C3) return;
    const float* x; const float* u; float* dst; int len = HH; float add = 0.f;
    if (gw < E_A1)      { x = g_rnn + (long)gw*HH;          u = g_u1;  dst = g_a1 + gw;          add = g_bv[0]; }
    else if (gw < E_A3) { int m = gw - E_A1;  x = g_rnn + (long)m*HH;  u = g_u3;  dst = g_a3 + m; add = g_bv[1]; }
    else if (gw < E_C1) { int m = gw - E_A3;  x = enc1 + (long)m*HH;   u = g_u1e; dst = g_c1 + m; }
    else if (gw < E_C2) { int m = gw - E_C1;  x = enc2 + (long)m*HH;   u = g_u1e; dst = g_c2 + m; }
    else                { int m = gw - E_C2;  x = enc3 + (long)m*KK;   u = g_u3e; dst = g_c3 + m; len = KK; }
    float s = 0.f;
    for (int k = lane; k < len; k += 32) s += x[k]*u[k];
#pragma unroll
    for (int o = 16; o > 0; o >>= 1) s += __shfl_xor_sync(0xffffffffu, s, o);
    if (lane == 0) *dst = s + add;
}

__global__ void k_softmax1(float* __restrict__ aw1) {
    int bn = blockIdx.x;
    int b = bn / NN, n = bn - b*NN;
    int t = threadIdx.x;
    float e  = tanhf(g_a1[n*BB + b] + g_c1[t*BB + b]);
    float ex = expf(e);
    __shared__ float red[8];
    __shared__ float stot;
    float s = ex;
#pragma unroll
    for (int o = 16; o > 0; o >>= 1) s += __shfl_xor_sync(0xffffffffu, s, o);
    if ((t & 31) == 0) red[t >> 5] = s;
    __syncthreads();
    if (t == 0) { float tt = 0.f; for (int i = 0; i < 8; i++) tt += red[i]; stot = tt; }
    __syncthreads();
    aw1[(long)bn*TT + t] = ex / stot;
}

__global__ void k_softmax2(float* __restrict__ aw2) {
    int gw = (blockIdx.x * blockDim.x + threadIdx.x) >> 5;
    if (gw >= BB*NN) return;
    int b = gw / NN, n = gw - b*NN;
    int s = threadIdx.x & 31;
    float e  = tanhf(g_a1[n*BB + b] + g_c2[s*BB + b]);
    float ex = expf(e);
    float tot = ex;
#pragma unroll
    for (int o = 16; o > 0; o >>= 1) tot += __shfl_xor_sync(0xffffffffu, tot, o);
    aw2[(long)gw*SS + s] = ex / tot;
}

__global__ void k_softmax3(float* __restrict__ aw3) {
    int bn = blockIdx.x * blockDim.x + threadIdx.x;
    if (bn >= BB*NN) return;
    int b = bn / NN, n = bn - b*NN;
    float ex[AA]; float tot = 0.f;
#pragma unroll
    for (int a = 0; a < AA; a++) {
        ex[a] = expf(tanhf(g_a3[n*BB + b] + g_c3[a*BB + b]));
        tot += ex[a];
    }
#pragma unroll
    for (int a = 0; a < AA; a++) aw3[(long)bn*AA + a] = ex[a] / tot;
}

__global__ void k_ctx(const float* __restrict__ aw, const float* __restrict__ enc,
                      float* __restrict__ dst, int L, int D) {
    int i = blockIdx.x * blockDim.x + threadIdx.x;
    if (i >= M2*D) return;
    int m = i / D, h = i - m*D;
    int n = m / BB, b = m - n*BB;
    const float* awp = aw + ((long)b*NN + n)*L;
    float s = 0.f;
    for (int t = 0; t < L; t++) s += awp[t]*enc[((long)t*BB + b)*D + h];
    dst[i] = s;
}

__global__ void k_concat() {
    int i = blockIdx.x * blockDim.x + threadIdx.x;
    if (i >= M2*CIN) return;
    int m = i / CIN, k = i - m*CIN;
    float v;
    if (k < HH)        v = g_rnn [m*HH + k];
    else if (k < 2*HH) v = g_ctx1[m*HH + k - HH];
    else if (k < 3*HH) v = g_ctx2[m*HH + k - 2*HH];
    else               v = g_ctx3[m*KK + k - 3*HH];
    g_cin[i] = v;
}

__global__ void k_e4(const float* __restrict__ enc4, const float* __restrict__ projW,
                     const float* __restrict__ projb) {
    int i = blockIdx.x * blockDim.x + threadIdx.x;
    if (i >= BB*AN) return;
    int b = i / AN, j = i - b*AN;
    float s = projb[j];
    for (int k = 0; k < AN; k++) s += enc4[(0*BB + b)*AN + k]*projW[j*2*AN + k];
    for (int k = 0; k < AN; k++) s += enc4[(1*BB + b)*AN + k]*projW[j*2*AN + AN + k];
    g_e4[i] = s;
}

__global__ void k_gin() {
    int i = blockIdx.x * blockDim.x + threadIdx.x;
    if (i >= M2*GIN) return;
    int m = i / GIN, k = i - m*GIN;
    int b = m % BB;
    float v;
    if (k < HH)        v = g_emb[m*HH + k];
    else if (k < 2*HH) v = g_rnn[m*HH + k - HH];
    else               v = g_e4[b*AN + k - 2*HH];
    g_gin[i] = v;
}

__global__ void k_gate(const float* __restrict__ gateW, const float* __restrict__ gateb,
                       float* __restrict__ gateout) {
    int gw = (blockIdx.x * blockDim.x + threadIdx.x) >> 5;
    int lane = threadIdx.x & 31;
    if (gw >= M2*AN) return;
    int m = gw / AN, j = gw - m*AN;
    const float* x = g_gin + (long)m*GIN;
    const float* w = gateW + (long)j*GIN;
    float s = 0.f;
    for (int k = lane; k < GIN; k += 32) s += x[k]*w[k];
#pragma unroll
    for (int o = 16; o > 0; o >>= 1) s += __shfl_xor_sync(0xffffffffu, s, o);
    if (lane == 0) gateout[(long)m*AN + j] = tanhf(s + gateb[j]);
}

__global__ void k_chain(const int* __restrict__ ids) {
    int j = blockIdx.x * blockDim.x + threadIdx.x;
    if (j >= NASP) return;
    int v = ids[j];
    int fst = 1;
    for (int j2 = 0; j2 < j; j2++) if (ids[j2] == v) { fst = 0; break; }
    int nxt = -1;
    for (int j2 = j + 1; j2 < NASP; j2++) if (ids[j2] == v) { nxt = j2; break; }
    g_first[j] = fst;
    g_next[j]  = nxt;
}

__global__ void k_scatter(const float* __restrict__ gate, const int* __restrict__ ids,
                          float* __restrict__ out0) {
    long i = (long)blockIdx.x * blockDim.x + threadIdx.x;
    if (i >= (long)M2*NASP) return;
    int m = (int)(i / NASP);
    int j = (int)(i - (long)m*NASP);
    if (!g_first[j]) return;
    float s = 0.f;
    int jj = j;
    while (jj >= 0) { s += gate[(long)m*AN + (jj % AN)]; jj = g_next[jj]; }
    out0[(long)m*VV + ids[j]] += s;
}

__global__ void k_hidden(float* __restrict__ dst) {
    int i = blockIdx.x * blockDim.x + threadIdx.x;
    if (i < BB*HH) dst[i] = g_rnn[(long)(NN-1)*BB*HH + i];
}

// ---------------- launcher ----------------
extern "C" void kernel_launch(void* const* d_in, const int* in_sizes, int n_in,
                              void* d_out, int out_size) {
    const int*   seq   = (const int*)  d_in[0];
    const float* lasth = (const float*)d_in[1];
    const float* enc1  = (const float*)d_in[2];
    const float* enc2  = (const float*)d_in[3];
    const float* enc3  = (const float*)d_in[4];
    const float* enc4  = (const float*)d_in[5];
    const int*   asp   = (const int*)  d_in[6];
    const float* emb   = (const float*)d_in[7];
    const float* Wih   = (const float*)d_in[8];
    const float* Whh   = (const float*)d_in[9];
    const float* bih   = (const float*)d_in[10];
    const float* bhh   = (const float*)d_in[11];
    const float* attnW = (const float*)d_in[12];
    const float* attnb = (const float*)d_in[13];
    const float* attnv = (const float*)d_in[14];
    const float* attrW = (const float*)d_in[15];
    const float* attrb = (const float*)d_in[16];
    const float* attrv = (const float*)d_in[17];
    const float* concW = (const float*)d_in[18];
    const float* concb = (const float*)d_in[19];
    const float* outW  = (const float*)d_in[20];
    const float* outb  = (const float*)d_in[21];
    const float* gateW = (const float*)d_in[22];
    const float* gateb = (const float*)d_in[23];
    const float* projW = (const float*)d_in[24];
    const float* projb = (const float*)d_in[25];
    float* out = (float*)d_out;

    const long O_HID  = (long)M2*VV;
    const long O_AW1  = O_HID + (long)BB*HH;
    const long O_AW2  = O_AW1 + (long)BB*NN*TT;
    const long O_AW3  = O_AW2 + (long)BB*NN*SS;
    const long O_GATE = O_AW3 + (long)BB*NN*AA;

    float *p_emb, *p_gi, *p_cin, *p_cout, *p_ctx1, *p_ctx2, *p_ctx3;
    cudaGetSymbolAddress((void**)&p_emb,  g_emb);
    cudaGetSymbolAddress((void**)&p_gi,   g_gi);
    cudaGetSymbolAddress((void**)&p_cin,  g_cin);
    cudaGetSymbolAddress((void**)&p_cout, g_cout);
    cudaGetSymbolAddress((void**)&p_ctx1, g_ctx1);
    cudaGetSymbolAddress((void**)&p_ctx2, g_ctx2);
    cudaGetSymbolAddress((void**)&p_ctx3, g_ctx3);

    // 1) embedding
    k_embed<<<(M2*HH + 255)/256, 256>>>(seq, emb);

    // 2) gi = embedded @ Wih^T + bih
    k_gemm_nt<<<dim3((3*HH)/64, M2/64), 256>>>(p_emb, Wih, bih, p_gi, M2, 3*HH, HH, 0);

    // 3) persistent GRU (all 64 steps, one launch)
    k_gru_all<<<GRU_BLOCKS, 256>>>(lasth, Whh, bhh);

    // 4) projected attention vectors + scalar dots
    k_uvec<<<(3*HH + KK + 2 + 255)/256, 256>>>(attnW, attnv, attnb, attrW, attrv, attrb);
    {
        int warps = 2*M2 + TT*BB + SS*BB + AA*BB;
        k_ac<<<(warps*32 + 255)/256, 256>>>(enc1, enc2, enc3);
    }

    // 5) softmaxes -> aw outputs
    k_softmax1<<<BB*NN, TT>>>(out + O_AW1);
    k_softmax2<<<(BB*NN*32 + 255)/256, 256>>>(out + O_AW2);
    k_softmax3<<<(BB*NN + 255)/256, 256>>>(out + O_AW3);

    // 6) contexts (device scratch via resolved symbol addresses!)
    k_ctx<<<(M2*HH + 255)/256, 256>>>(out + O_AW1, enc1, p_ctx1, TT, HH);
    k_ctx<<<(M2*HH + 255)/256, 256>>>(out + O_AW2, enc2, p_ctx2, SS, HH);
    k_ctx<<<(M2*KK + 255)/256, 256>>>(out + O_AW3, enc3, p_ctx3, AA, KK);

    // 7) concat -> tanh GEMM -> big output GEMM (tf32 tensor cores)
    k_concat<<<(M2*CIN + 255)/256, 256>>>();
    k_gemm_nt<<<dim3(HH/64, M2/64), 256>>>(p_cin, concW, concb, p_cout, M2, HH, CIN, 1);
    k_gemm_tf32<<<dim3(VV/128, M2/128), 128>>>(p_cout, outW, outb, out);

    // 8) gate path
    k_e4<<<(BB*AN + 255)/256, 256>>>(enc4, projW, projb);
    k_gin<<<(M2*GIN + 255)/256, 256>>>();
    k_gate<<<(M2*AN*32 + 255)/256, 256>>>(gateW, gateb, out + O_GATE);

    // 9) deterministic scatter-add
    k_chain<<<(NASP + 255)/256, 256>>>(asp);
    k_scatter<<<(int)(((long)M2*NASP + 255)/256), 256>>>(out + O_GATE, asp, out);

    // 10) hidden = final h
    k_hidden<<<(BB*HH + 255)/256, 256>>>(out + O_HID);
}

// round 5
// speedup vs baseline: 2.4456x; 1.0695x over previous
#include <cuda_runtime.h>
#include <cuda_bf16.h>
#include <math.h>
#include <stdint.h>

#define NN 64
#define BB 32
#define HH 512
#define KK 128
#define VV 32000
#define TT 256
#define SS 32
#define AA 5
#define AN 20
#define M2 (NN*BB)          // 2048 rows
#define CIN (3*HH+KK)       // 1664
#define GIN (2*HH+AN)       // 1044
#define NASP 2000
#define GRU_BLOCKS 128

// ---------------- scratch (static device globals; no runtime alloc) ----------------
__device__ __align__(16) float g_emb[M2*HH];
__device__ __align__(16) float g_gi[M2*3*HH];
__device__ __align__(16) float g_hA[HH*BB];
__device__ __align__(16) float g_hB[HH*BB];
__device__ __align__(16) float g_rnn[M2*HH];
__device__ float g_u1[HH], g_u1e[HH], g_u3[HH], g_u3e[KK], g_bv[2];
__device__ float g_a1[M2], g_a3[M2];
__device__ float g_c1[TT*BB], g_c2[SS*BB], g_c3[AA*BB];
__device__ __align__(16) float g_ctx1[M2*HH];
__device__ __align__(16) float g_ctx2[M2*HH];
__device__ __align__(16) float g_ctx3[M2*KK];
__device__ __align__(16) float g_cout[M2*HH];
__device__ float g_e4[BB*AN];
__device__ int g_first[NASP], g_next[NASP];
__device__ unsigned g_barcnt = 0;
__device__ unsigned g_bargen = 0;

// ---------------- small helpers ----------------
__device__ __forceinline__ void grid_barrier(unsigned nb) {
    __threadfence();
    __syncthreads();
    if (threadIdx.x == 0) {
        unsigned gen = *(volatile unsigned*)&g_bargen;
        if (atomicAdd(&g_barcnt, 1u) == nb - 1u) {
            *(volatile unsigned*)&g_barcnt = 0u;
            __threadfence();
            atomicAdd(&g_bargen, 1u);
        } else {
            while (*(volatile unsigned*)&g_bargen == gen) { __nanosleep(40); }
        }
    }
    __syncthreads();
}

// ---------------- kernels ----------------

__global__ void k_embed(const int* __restrict__ seq, const float* __restrict__ emb) {
    int i = blockIdx.x * blockDim.x + threadIdx.x;           // N*B*H
    if (i < M2*HH) {
        int m = i / HH, h = i - m*HH;
        g_emb[i] = emb[(long)seq[m]*HH + h];
    }
}

// fp32 SIMT GEMM: C[M,Nc] = A[M,K] * W[Nc,K]^T (+bias) (opt tanh).
__global__ void k_gemm_nt(const float* __restrict__ A, const float* __restrict__ W,
                          const float* __restrict__ bias, float* __restrict__ C,
                          int M, int Nc, int Kd, int act) {
    __shared__ float As[16][65];
    __shared__ float Ws[16][65];
    int tid = threadIdx.x;
    int tx = tid & 15, ty = tid >> 4;
    int m0 = blockIdx.y * 64, n0 = blockIdx.x * 64;
    float acc[4][4] = {};
    int r  = tid >> 2;
    int kc = (tid & 3) * 4;
    for (int k0 = 0; k0 < Kd; k0 += 16) {
        float4 av = *(const float4*)(A + (long)(m0 + r)*Kd + k0 + kc);
        As[kc+0][r] = av.x; As[kc+1][r] = av.y; As[kc+2][r] = av.z; As[kc+3][r] = av.w;
        float4 wv = *(const float4*)(W + (long)(n0 + r)*Kd + k0 + kc);
        Ws[kc+0][r] = wv.x; Ws[kc+1][r] = wv.y; Ws[kc+2][r] = wv.z; Ws[kc+3][r] = wv.w;
        __syncthreads();
#pragma unroll
        for (int kk = 0; kk < 16; kk++) {
            float a[4], w[4];
#pragma unroll
            for (int i = 0; i < 4; i++) { a[i] = As[kk][ty*4+i]; w[i] = Ws[kk][tx*4+i]; }
#pragma unroll
            for (int i = 0; i < 4; i++)
#pragma unroll
                for (int j = 0; j < 4; j++) acc[i][j] += a[i]*w[j];
        }
        __syncthreads();
    }
#pragma unroll
    for (int i = 0; i < 4; i++) {
        int m = m0 + ty*4 + i;
#pragma unroll
        for (int j = 0; j < 4; j++) {
            int n = n0 + tx*4 + j;
            float v = acc[i][j] + (bias ? bias[n] : 0.f);
            if (act) v = tanhf(v);
            C[(long)m*Nc + n] = v;
        }
    }
}

// ---------------- persistent GRU: all 64 steps, grid-barrier per step ----------------
__global__ __launch_bounds__(256, 1)
void k_gru_all(const float* __restrict__ lasth, const float* __restrict__ Whh,
               const float* __restrict__ bhh) {
    int tid = threadIdx.x, bk = blockIdx.x;
    int jl = (tid >> 5) & 3, b = tid & 31, kh = tid >> 7;
    int jg = bk*4 + jl;
    __shared__ __align__(16) float sw[3][4][HH];
    __shared__ float sb[3][4];
    __shared__ float part[3][128];

    for (int r = 0; r < 12; r++) {
        int g = r / 4, j = r % 4;
        int row = g*HH + bk*4 + j;
        for (int k = tid; k < HH; k += 256) sw[g][j][k] = Whh[(long)row*HH + k];
    }
    if (tid < 12) sb[tid/4][tid%4] = bhh[(tid/4)*HH + bk*4 + (tid%4)];

    if (tid < 128) {
        int idx = bk*128 + tid;           // 128*128 = 16384 = HH*BB
        int k = idx >> 5, bb = idx & 31;
        __stcg(&g_hA[idx], lasth[bb*HH + k]);
    }
    grid_barrier(GRU_BLOCKS);

    float* hp = g_hA;
    float* hc = g_hB;
    const float* wr = sw[0][jl];
    const float* wz = sw[1][jl];
    const float* wn = sw[2][jl];
    int k0 = kh * 256;

    for (int n = 0; n < NN; n++) {
        float sr = 0.f, sz = 0.f, sn = 0.f;
#pragma unroll 4
        for (int k = k0; k < k0 + 256; k += 4) {
            float4 r4 = *(const float4*)(wr + k);
            float4 z4 = *(const float4*)(wz + k);
            float4 n4 = *(const float4*)(wn + k);
            float h0 = __ldcg(hp + (k+0)*BB + b);
            float h1 = __ldcg(hp + (k+1)*BB + b);
            float h2 = __ldcg(hp + (k+2)*BB + b);
            float h3 = __ldcg(hp + (k+3)*BB + b);
            sr += r4.x*h0 + r4.y*h1 + r4.z*h2 + r4.w*h3;
            sz += z4.x*h0 + z4.y*h1 + z4.z*h2 + z4.w*h3;
            sn += n4.x*h0 + n4.y*h1 + n4.z*h2 + n4.w*h3;
        }
        if (kh == 1) {
            part[0][jl*32+b] = sr; part[1][jl*32+b] = sz; part[2][jl*32+b] = sn;
        }
        __syncthreads();
        if (kh == 0) {
            sr += part[0][jl*32+b]; sz += part[1][jl*32+b]; sn += part[2][jl*32+b];
            float hold = __ldcg(hp + jg*BB + b);
            const float* gi = g_gi + ((long)(n*BB + b))*(3*HH);
            float rr = 1.f/(1.f + expf(-(gi[jg]        + sr + sb[0][jl])));
            float zz = 1.f/(1.f + expf(-(gi[HH + jg]   + sz + sb[1][jl])));
            float nn = tanhf(gi[2*HH + jg] + rr*(sn + sb[2][jl]));
            float hn = (1.f - zz)*nn + zz*hold;
            __stcg(hc + jg*BB + b, hn);
            g_rnn[((long)(n*BB + b))*HH + jg] = hn;
        }
        grid_barrier(GRU_BLOCKS);
        float* t = hp; hp = hc; hc = t;
    }
}

// ---------------- tf32 tensor-core GEMM ----------------
__device__ __forceinline__ uint32_t f2tf(float x) {
    uint32_t u; asm("cvt.rna.tf32.f32 %0, %1;" : "=r"(u) : "f"(x)); return u;
}
__device__ __forceinline__ void mma_tf32(float& c0, float& c1, float& c2, float& c3,
                                         uint32_t a0, uint32_t a1, uint32_t a2, uint32_t a3,
                                         uint32_t b0, uint32_t b1) {
    asm volatile("mma.sync.aligned.m16n8k8.row.col.f32.tf32.tf32.f32 "
                 "{%0,%1,%2,%3},{%4,%5,%6,%7},{%8,%9},{%0,%1,%2,%3};"
                 : "+f"(c0), "+f"(c1), "+f"(c2), "+f"(c3)
                 : "r"(a0), "r"(a1), "r"(a2), "r"(a3), "r"(b0), "r"(b1));
}
__device__ __forceinline__ void cpa16(uint32_t saddr, const void* gaddr) {
    asm volatile("cp.async.cg.shared.global [%0], [%1], 16;" :: "r"(saddr), "l"(gaddr));
}

// A-row source for the fused concat GEMM: [rnn | ctx1 | ctx2 | ctx3]
__device__ __forceinline__ const float* concat_src(int m, int k) {
    if (k < HH)        return g_rnn  + (long)m*HH + k;
    if (k < 2*HH)      return g_ctx1 + (long)m*HH + (k - HH);
    if (k < 3*HH)      return g_ctx2 + (long)m*HH + (k - 2*HH);
    return g_ctx3 + (long)m*KK + (k - 3*HH);
}

// BM=128, BN=128, BK=16; 128 threads (4 warps 2x2), warp tile 64x64.
// ASRC=0: plain A (ldA=Kd). ASRC=1: gather concat rows (A unused).
template<int ASRC>
__global__ __launch_bounds__(128, 2)
void k_gemm_tf32(const float* __restrict__ A, const float* __restrict__ W,
                 const float* __restrict__ bias, float* __restrict__ C,
                 int Kd, int ldC, int act) {
    __shared__ __align__(16) float As[2][128][20];
    __shared__ __align__(16) float Bs[2][128][20];
    int tid = threadIdx.x;
    int warp = tid >> 5, lane = tid & 31;
    int wm = warp & 1, wnp = warp >> 1;          // 2 x 2 warp grid
    int lq = lane >> 2, lr = lane & 3;
    int m0 = blockIdx.y * 128, n0 = blockIdx.x * 128;

    float acc[4][8][4];
#pragma unroll
    for (int i = 0; i < 4; i++)
#pragma unroll
        for (int j = 0; j < 8; j++)
#pragma unroll
            for (int c = 0; c < 4; c++) acc[i][j][c] = 0.f;

    const int NK = Kd / 16;
#pragma unroll
    for (int i = 0; i < 4; i++) {
        int idx = i*128 + tid, row = idx >> 2, kc = idx & 3;
        const float* asrc = ASRC ? concat_src(m0+row, kc*4)
                                 : A + (long)(m0+row)*Kd + kc*4;
        cpa16((uint32_t)__cvta_generic_to_shared(&As[0][row][kc*4]), asrc);
        cpa16((uint32_t)__cvta_generic_to_shared(&Bs[0][row][kc*4]),
              W + (long)(n0+row)*Kd + kc*4);
    }
    asm volatile("cp.async.commit_group;");

    int buf = 0;
    for (int ks = 0; ks < NK; ks++) {
        asm volatile("cp.async.wait_group 0;");
        __syncthreads();
        if (ks + 1 < NK) {
#pragma unroll
            for (int i = 0; i < 4; i++) {
                int idx = i*128 + tid, row = idx >> 2, kc = idx & 3;
                int kpos = (ks+1)*16 + kc*4;
                const float* asrc = ASRC ? concat_src(m0+row, kpos)
                                         : A + (long)(m0+row)*Kd + kpos;
                cpa16((uint32_t)__cvta_generic_to_shared(&As[buf^1][row][kc*4]), asrc);
                cpa16((uint32_t)__cvta_generic_to_shared(&Bs[buf^1][row][kc*4]),
                      W + (long)(n0+row)*Kd + kpos);
            }
            asm volatile("cp.async.commit_group;");
        }
#pragma unroll
        for (int kk = 0; kk < 16; kk += 8) {
            uint32_t af[4][4], bf[8][2];
#pragma unroll
            for (int ms = 0; ms < 4; ms++) {
                int rb = wm*64 + ms*16;
                af[ms][0] = f2tf(As[buf][rb + lq    ][kk + lr    ]);
                af[ms][1] = f2tf(As[buf][rb + lq + 8][kk + lr    ]);
                af[ms][2] = f2tf(As[buf][rb + lq    ][kk + lr + 4]);
                af[ms][3] = f2tf(As[buf][rb + lq + 8][kk + lr + 4]);
            }
#pragma unroll
            for (int ns = 0; ns < 8; ns++) {
                int nb = wnp*64 + ns*8;
                bf[ns][0] = f2tf(Bs[buf][nb + lq][kk + lr    ]);
                bf[ns][1] = f2tf(Bs[buf][nb + lq][kk + lr + 4]);
            }
#pragma unroll
            for (int ms = 0; ms < 4; ms++)
#pragma unroll
                for (int ns = 0; ns < 8; ns++)
                    mma_tf32(acc[ms][ns][0], acc[ms][ns][1], acc[ms][ns][2], acc[ms][ns][3],
                             af[ms][0], af[ms][1], af[ms][2], af[ms][3],
                             bf[ns][0], bf[ns][1]);
        }
        buf ^= 1;
    }
#pragma unroll
    for (int ms = 0; ms < 4; ms++) {
        int row = m0 + wm*64 + ms*16 + lq;
#pragma unroll
        for (int ns = 0; ns < 8; ns++) {
            int col = n0 + wnp*64 + ns*8 + lr*2;
            float b0 = bias[col], b1 = bias[col+1];
            float v00 = acc[ms][ns][0] + b0, v01 = acc[ms][ns][1] + b1;
            float v10 = acc[ms][ns][2] + b0, v11 = acc[ms][ns][3] + b1;
            if (act) { v00 = tanhf(v00); v01 = tanhf(v01); v10 = tanhf(v10); v11 = tanhf(v11); }
            *(float2*)(C + (long)row*ldC + col)     = make_float2(v00, v01);
            *(float2*)(C + (long)(row+8)*ldC + col) = make_float2(v10, v11);
        }
    }
}

// ---------------- projected attention vectors (coalesced column tiles) ----------------
// blocks 0..25: 64 columns each over [attnW 1024 cols | attrW 640 cols]; block 26: b·v dots
__global__ void k_uvec2(const float* __restrict__ attnW, const float* __restrict__ attnv,
                        const float* __restrict__ attnb, const float* __restrict__ attrW,
                        const float* __restrict__ attrv, const float* __restrict__ attrb) {
    __shared__ float red[4][64];
    int blk = blockIdx.x;
    int tid = threadIdx.x;
    if (blk < 26) {
        int tx = tid & 63, hy = tid >> 6;
        int col = blk*64 + tx;
        const float* W; const float* v; float* dst; int ld; int c;
        if (col < 2*HH) {
            W = attnW; v = attnv; ld = 2*HH; c = col;
            dst = (col < HH) ? &g_u1[col] : &g_u1e[col - HH];
        } else {
            int cc = col - 2*HH;
            W = attrW; v = attrv; ld = HH + KK; c = cc;
            dst = (cc < HH) ? &g_u3[cc] : &g_u3e[cc - HH];
        }
        float acc = 0.f;
        for (int h = hy; h < HH; h += 4) acc += W[(long)h*ld + c] * v[h];
        red[hy][tx] = acc;
        __syncthreads();
        if (hy == 0) *dst = red[0][tx] + red[1][tx] + red[2][tx] + red[3][tx];
    } else {
        int w = tid >> 5, lane = tid & 31;
        if (w < 2) {
            const float* bp = w ? attrb : attnb;
            const float* vp = w ? attrv : attnv;
            float s = 0.f;
            for (int h = lane; h < HH; h += 32) s += bp[h]*vp[h];
#pragma unroll
            for (int o = 16; o > 0; o >>= 1) s += __shfl_xor_sync(0xffffffffu, s, o);
            if (lane == 0) g_bv[w] = s;
        }
    }
}

// all scalar attention dot products (warp per output)
__global__ void k_ac(const float* __restrict__ enc1, const float* __restrict__ enc2,
                     const float* __restrict__ enc3) {
    int gw = (blockIdx.x * blockDim.x + threadIdx.x) >> 5;
    int lane = threadIdx.x & 31;
    const int E_A1 = M2, E_A3 = 2*M2, E_C1 = E_A3 + TT*BB, E_C2 = E_C1 + SS*BB, E_C3 = E_C2 + AA*BB;
    if (gw >= E_C3) return;
    const float* x; const float* u; float* dst; int len = HH; float add = 0.f;
    if (gw < E_A1)      { x = g_rnn + (long)gw*HH;          u = g_u1;  dst = g_a1 + gw;          add = g_bv[0]; }
    else if (gw < E_A3) { int m = gw - E_A1;  x = g_rnn + (long)m*HH;  u = g_u3;  dst = g_a3 + m; add = g_bv[1]; }
    else if (gw < E_C1) { int m = gw - E_A3;  x = enc1 + (long)m*HH;   u = g_u1e; dst = g_c1 + m; }
    else if (gw < E_C2) { int m = gw - E_C1;  x = enc2 + (long)m*HH;   u = g_u1e; dst = g_c2 + m; }
    else                { int m = gw - E_C2;  x = enc3 + (long)m*KK;   u = g_u3e; dst = g_c3 + m; len = KK; }
    float s = 0.f;
    for (int k = lane; k < len; k += 32) s += x[k]*u[k];
#pragma unroll
    for (int o = 16; o > 0; o >>= 1) s += __shfl_xor_sync(0xffffffffu, s, o);
    if (lane == 0) *dst = s + add;
}

__global__ void k_softmax1(float* __restrict__ aw1) {
    int bn = blockIdx.x;
    int b = bn / NN, n = bn - b*NN;
    int t = threadIdx.x;
    float e  = tanhf(g_a1[n*BB + b] + g_c1[t*BB + b]);
    float ex = expf(e);
    __shared__ float red[8];
    __shared__ float stot;
    float s = ex;
#pragma unroll
    for (int o = 16; o > 0; o >>= 1) s += __shfl_xor_sync(0xffffffffu, s, o);
    if ((t & 31) == 0) red[t >> 5] = s;
    __syncthreads();
    if (t == 0) { float tt = 0.f; for (int i = 0; i < 8; i++) tt += red[i]; stot = tt; }
    __syncthreads();
    aw1[(long)bn*TT + t] = ex / stot;
}

__global__ void k_softmax2(float* __restrict__ aw2) {
    int gw = (blockIdx.x * blockDim.x + threadIdx.x) >> 5;
    if (gw >= BB*NN) return;
    int b = gw / NN, n = gw - b*NN;
    int s = threadIdx.x & 31;
    float e  = tanhf(g_a1[n*BB + b] + g_c2[s*BB + b]);
    float ex = expf(e);
    float tot = ex;
#pragma unroll
    for (int o = 16; o > 0; o >>= 1) tot += __shfl_xor_sync(0xffffffffu, tot, o);
    aw2[(long)gw*SS + s] = ex / tot;
}

__global__ void k_softmax3(float* __restrict__ aw3) {
    int bn = blockIdx.x * blockDim.x + threadIdx.x;
    if (bn >= BB*NN) return;
    int b = bn / NN, n = bn - b*NN;
    float ex[AA]; float tot = 0.f;
#pragma unroll
    for (int a = 0; a < AA; a++) {
        ex[a] = expf(tanhf(g_a3[n*BB + b] + g_c3[a*BB + b]));
        tot += ex[a];
    }
#pragma unroll
    for (int a = 0; a < AA; a++) aw3[(long)bn*AA + a] = ex[a] / tot;
}

// tiled ctx: dst[n,b,h] = sum_t aw[b,n,t] * enc[t,b,h].  L % 32 == 0, D % 64 == 0.
// grid (BB, D/64), 256 threads; block computes [64 n x 64 h] for one b.
__global__ void k_ctx_t(const float* __restrict__ aw, const float* __restrict__ enc,
                        float* __restrict__ dst, int L, int D) {
    int b  = blockIdx.x;
    int h0 = blockIdx.y * 64;
    int tid = threadIdx.x;
    __shared__ float AWs[64][33];
    __shared__ float Es[32][68];
    int tx = tid & 15, ty = tid >> 4;
    float acc[4][4] = {};
    for (int t0 = 0; t0 < L; t0 += 32) {
        {
            int row = tid >> 2, c0 = (tid & 3) * 8;
            const float* ap = aw + ((long)b*NN + row)*L + t0 + c0;
            float4 v0 = *(const float4*)ap;
            float4 v1 = *(const float4*)(ap + 4);
            AWs[row][c0+0]=v0.x; AWs[row][c0+1]=v0.y; AWs[row][c0+2]=v0.z; AWs[row][c0+3]=v0.w;
            AWs[row][c0+4]=v1.x; AWs[row][c0+5]=v1.y; AWs[row][c0+6]=v1.z; AWs[row][c0+7]=v1.w;
        }
        {
            int row = tid >> 3, c0 = (tid & 7) * 8;
            const float* ep = enc + (((long)(t0+row))*BB + b)*D + h0 + c0;
            float4 v0 = *(const float4*)ep;
            float4 v1 = *(const float4*)(ep + 4);
            Es[row][c0+0]=v0.x; Es[row][c0+1]=v0.y; Es[row][c0+2]=v0.z; Es[row][c0+3]=v0.w;
            Es[row][c0+4]=v1.x; Es[row][c0+5]=v1.y; Es[row][c0+6]=v1.z; Es[row][c0+7]=v1.w;
        }
        __syncthreads();
#pragma unroll
        for (int tt = 0; tt < 32; tt++) {
            float a[4], e[4];
#pragma unroll
            for (int i = 0; i < 4; i++) { a[i] = AWs[ty*4+i][tt]; e[i] = Es[tt][tx*4+i]; }
#pragma unroll
            for (int i = 0; i < 4; i++)
#pragma unroll
                for (int j = 0; j < 4; j++) acc[i][j] += a[i]*e[j];
        }
        __syncthreads();
    }
#pragma unroll
    for (int i = 0; i < 4; i++) {
        int n = ty*4 + i;
#pragma unroll
        for (int j = 0; j < 4; j++)
            dst[(((long)n)*BB + b)*D + h0 + tx*4 + j] = acc[i][j];
    }
}

// naive ctx (kept for L=5, D=128)
__global__ void k_ctx(const float* __restrict__ aw, const float* __restrict__ enc,
                      float* __restrict__ dst, int L, int D) {
    int i = blockIdx.x * blockDim.x + threadIdx.x;
    if (i >= M2*KK) return;
    int m = i / D, h = i - m*D;
    int n = m / BB, b = m - n*BB;
    const float* awp = aw + ((long)b*NN + n)*L;
    float s = 0.f;
    for (int t = 0; t < L; t++) s += awp[t]*enc[((long)t*BB + b)*D + h];
    dst[i] = s;
}

__global__ void k_e4(const float* __restrict__ enc4, const float* __restrict__ projW,
                     const float* __restrict__ projb) {
    int i = blockIdx.x * blockDim.x + threadIdx.x;
    if (i >= BB*AN) return;
    int b = i / AN, j = i - b*AN;
    float s = projb[j];
    for (int k = 0; k < AN; k++) s += enc4[(0*BB + b)*AN + k]*projW[j*2*AN + k];
    for (int k = 0; k < AN; k++) s += enc4[(1*BB + b)*AN + k]*projW[j*2*AN + AN + k];
    g_e4[i] = s;
}

// fused gin+gate: block per 4 m-rows; x staged in smem from [emb|rnn|e4]
__global__ void k_gate2(const float* __restrict__ gateW, const float* __restrict__ gateb,
                        float* __restrict__ gateout) {
    int m0 = blockIdx.x * 4;
    int tid = threadIdx.x;
    __shared__ float xs[4][GIN + 12];
#pragma unroll
    for (int r = 0; r < 4; r++) {
        int m = m0 + r, b = m & 31;
        for (int k = tid; k < GIN; k += 256) {
            float v;
            if (k < HH)        v = g_emb[(long)m*HH + k];
            else if (k < 2*HH) v = g_rnn[(long)m*HH + k - HH];
            else               v = g_e4[b*AN + k - 2*HH];
            xs[r][k] = v;
        }
    }
    __syncthreads();
    int w = tid >> 5, lane = tid & 31;
    for (int o = w; o < 4*AN; o += 8) {
        int r = o & 3, j = o >> 2;
        const float* wj = gateW + (long)j*GIN;
        float s = 0.f;
        for (int k = lane; k < GIN; k += 32) s += xs[r][k]*wj[k];
#pragma unroll
        for (int of = 16; of > 0; of >>= 1) s += __shfl_xor_sync(0xffffffffu, s, of);
        if (lane == 0) gateout[(long)(m0+r)*AN + j] = tanhf(s + gateb[j]);
    }
}

__global__ void k_chain(const int* __restrict__ ids) {
    int j = blockIdx.x * blockDim.x + threadIdx.x;
    if (j >= NASP) return;
    int v = ids[j];
    int fst = 1;
    for (int j2 = 0; j2 < j; j2++) if (ids[j2] == v) { fst = 0; break; }
    int nxt = -1;
    for (int j2 = j + 1; j2 < NASP; j2++) if (ids[j2] == v) { nxt = j2; break; }
    g_first[j] = fst;
    g_next[j]  = nxt;
}

__global__ void k_scatter(const float* __restrict__ gate, const int* __restrict__ ids,
                          float* __restrict__ out0) {
    long i = (long)blockIdx.x * blockDim.x + threadIdx.x;
    if (i >= (long)M2*NASP) return;
    int m = (int)(i / NASP);
    int j = (int)(i - (long)m*NASP);
    if (!g_first[j]) return;
    float s = 0.f;
    int jj = j;
    while (jj >= 0) { s += gate[(long)m*AN + (jj % AN)]; jj = g_next[jj]; }
    out0[(long)m*VV + ids[j]] += s;
}

__global__ void k_hidden(float* __restrict__ dst) {
    int i = blockIdx.x * blockDim.x + threadIdx.x;
    if (i < BB*HH) dst[i] = g_rnn[(long)(NN-1)*BB*HH + i];
}

// ---------------- launcher ----------------
extern "C" void kernel_launch(void* const* d_in, const int* in_sizes, int n_in,
                              void* d_out, int out_size) {
    const int*   seq   = (const int*)  d_in[0];
    const float* lasth = (const float*)d_in[1];
    const float* enc1  = (const float*)d_in[2];
    const float* enc2  = (const float*)d_in[3];
    const float* enc3  = (const float*)d_in[4];
    const float* enc4  = (const float*)d_in[5];
    const int*   asp   = (const int*)  d_in[6];
    const float* emb   = (const float*)d_in[7];
    const float* Wih   = (const float*)d_in[8];
    const float* Whh   = (const float*)d_in[9];
    const float* bih   = (const float*)d_in[10];
    const float* bhh   = (const float*)d_in[11];
    const float* attnW = (const float*)d_in[12];
    const float* attnb = (const float*)d_in[13];
    const float* attnv = (const float*)d_in[14];
    const float* attrW = (const float*)d_in[15];
    const float* attrb = (const float*)d_in[16];
    const float* attrv = (const float*)d_in[17];
    const float* concW = (const float*)d_in[18];
    const float* concb = (const float*)d_in[19];
    const float* outW  = (const float*)d_in[20];
    const float* outb  = (const float*)d_in[21];
    const float* gateW = (const float*)d_in[22];
    const float* gateb = (const float*)d_in[23];
    const float* projW = (const float*)d_in[24];
    const float* projb = (const float*)d_in[25];
    float* out = (float*)d_out;

    const long O_HID  = (long)M2*VV;
    const long O_AW1  = O_HID + (long)BB*HH;
    const long O_AW2  = O_AW1 + (long)BB*NN*TT;
    const long O_AW3  = O_AW2 + (long)BB*NN*SS;
    const long O_GATE = O_AW3 + (long)BB*NN*AA;

    float *p_emb, *p_gi, *p_cout, *p_ctx1, *p_ctx2, *p_ctx3;
    cudaGetSymbolAddress((void**)&p_emb,  g_emb);
    cudaGetSymbolAddress((void**)&p_gi,   g_gi);
    cudaGetSymbolAddress((void**)&p_cout, g_cout);
    cudaGetSymbolAddress((void**)&p_ctx1, g_ctx1);
    cudaGetSymbolAddress((void**)&p_ctx2, g_ctx2);
    cudaGetSymbolAddress((void**)&p_ctx3, g_ctx3);

    // 1) embedding
    k_embed<<<(M2*HH + 255)/256, 256>>>(seq, emb);

    // 2) gi = embedded @ Wih^T + bih (fp32 — protects GRU recurrence precision)
    k_gemm_nt<<<dim3((3*HH)/64, M2/64), 256>>>(p_emb, Wih, bih, p_gi, M2, 3*HH, HH, 0);

    // 3) persistent GRU (all 64 steps, one launch)
    k_gru_all<<<GRU_BLOCKS, 256>>>(lasth, Whh, bhh);

    // 4) projected attention vectors + scalar dots
    k_uvec2<<<27, 256>>>(attnW, attnv, attnb, attrW, attrv, attrb);
    {
        int warps = 2*M2 + TT*BB + SS*BB + AA*BB;
        k_ac<<<(warps*32 + 255)/256, 256>>>(enc1, enc2, enc3);
    }

    // 5) softmaxes -> aw outputs
    k_softmax1<<<BB*NN, TT>>>(out + O_AW1);
    k_softmax2<<<(BB*NN*32 + 255)/256, 256>>>(out + O_AW2);
    k_softmax3<<<(BB*NN + 255)/256, 256>>>(out + O_AW3);

    // 6) contexts (tiled for T=256 / S=32; naive for A=5)
    k_ctx_t<<<dim3(BB, HH/64), 256>>>(out + O_AW1, enc1, p_ctx1, TT, HH);
    k_ctx_t<<<dim3(BB, HH/64), 256>>>(out + O_AW2, enc2, p_ctx2, SS, HH);
    k_ctx  <<<(M2*KK + 255)/256, 256>>>(out + O_AW3, enc3, p_ctx3, AA, KK);

    // 7) fused concat-gather tf32 GEMM (tanh) -> big tf32 output GEMM
    k_gemm_tf32<1><<<dim3(HH/128, M2/128), 128>>>(nullptr, concW, concb, p_cout, CIN, HH, 1);
    k_gemm_tf32<0><<<dim3(VV/128, M2/128), 128>>>(p_cout, outW, outb, out, HH, VV, 0);

    // 8) gate path (fused gin+gate)
    k_e4<<<(BB*AN + 255)/256, 256>>>(enc4, projW, projb);
    k_gate2<<<M2/4, 256>>>(gateW, gateb, out + O_GATE);

    // 9) deterministic scatter-add
    k_chain<<<(NASP + 255)/256, 256>>>(asp);
    k_scatter<<<(int)(((long)M2*NASP + 255)/256), 256>>>(out + O_GATE, asp, out);

    // 10) hidden = final h
    k_hidden<<<(BB*HH + 255)/256, 256>>>(out + O_HID);
}

// round 6
// speedup vs baseline: 2.7131x; 1.1094x over previous
#include <cuda_runtime.h>
#include <cuda_bf16.h>
#include <math.h>
#include <stdint.h>

#define NN 64
#define BB 32
#define HH 512
#define KK 128
#define VV 32000
#define TT 256
#define SS 32
#define AA 5
#define AN 20
#define M2 (NN*BB)          // 2048 rows
#define CIN (3*HH+KK)       // 1664
#define GIN (2*HH+AN)       // 1044
#define NASP 2000
#define GRU_BLOCKS 128
#define UCOLS (2*HH + HH + KK)   // 1664 projected columns

// ---------------- scratch (static device globals; no runtime alloc) ----------------
__device__ __align__(16) float g_emb[M2*HH];
__device__ __align__(16) float g_gi[M2*3*HH];
__device__ __align__(16) float g_hA[HH*BB];
__device__ __align__(16) float g_hB[HH*BB];
__device__ __align__(16) float g_rnn[M2*HH];
__device__ float g_u1[HH], g_u1e[HH], g_u3[HH], g_u3e[KK], g_bv[2];
__device__ __align__(16) float g_upart[8][UCOLS];
__device__ float g_a1[M2], g_a3[M2];
__device__ float g_c1[TT*BB], g_c2[SS*BB], g_c3[AA*BB];
__device__ __align__(16) float g_ctx1[M2*HH];
__device__ __align__(16) float g_ctx2[M2*HH];
__device__ __align__(16) float g_ctx3[M2*KK];
__device__ __align__(16) float g_cout[M2*HH];
__device__ float g_e4[BB*AN];
__device__ int g_first[NASP], g_next[NASP];
__device__ unsigned g_barcnt = 0;
__device__ unsigned g_bargen = 0;

// ---------------- grid barrier (release/acquire, no membar.gl) ----------------
__device__ __forceinline__ void grid_barrier(unsigned nb) {
    __syncthreads();
    if (threadIdx.x == 0) {
        unsigned gen;
        asm volatile("ld.relaxed.gpu.global.u32 %0, [%1];" : "=r"(gen) : "l"(&g_bargen));
        unsigned prev;
        asm volatile("atom.release.gpu.global.add.u32 %0, [%1], 1;" : "=r"(prev) : "l"(&g_barcnt));
        if (prev == nb - 1u) {
            asm volatile("st.relaxed.gpu.global.u32 [%0], %1;" :: "l"(&g_barcnt), "r"(0u));
            unsigned d;
            asm volatile("atom.release.gpu.global.add.u32 %0, [%1], 1;" : "=r"(d) : "l"(&g_bargen));
        } else {
            unsigned cur;
            do {
                __nanosleep(20);
                asm volatile("ld.acquire.gpu.global.u32 %0, [%1];" : "=r"(cur) : "l"(&g_bargen));
            } while (cur == gen);
        }
    }
    __syncthreads();
}

// ---------------- kernels ----------------

__global__ void k_embed(const int* __restrict__ seq, const float* __restrict__ emb) {
    int i = blockIdx.x * blockDim.x + threadIdx.x;           // N*B*H
    if (i < M2*HH) {
        int m = i / HH, h = i - m*HH;
        g_emb[i] = emb[(long)seq[m]*HH + h];
    }
}

// ---------------- persistent GRU ----------------
__global__ __launch_bounds__(256, 1)
void k_gru_all(const float* __restrict__ lasth, const float* __restrict__ Whh,
               const float* __restrict__ bhh, float* __restrict__ hid) {
    int tid = threadIdx.x, bk = blockIdx.x;
    int jl = (tid >> 5) & 3, b = tid & 31, kh = tid >> 7;
    int jg = bk*4 + jl;
    __shared__ __align__(16) float sw[3][4][HH];
    __shared__ float sb[3][4];
    __shared__ float part[3][128];

    for (int r = 0; r < 12; r++) {
        int g = r / 4, j = r % 4;
        int row = g*HH + bk*4 + j;
        for (int k = tid; k < HH; k += 256) sw[g][j][k] = Whh[(long)row*HH + k];
    }
    if (tid < 12) sb[tid/4][tid%4] = bhh[(tid/4)*HH + bk*4 + (tid%4)];

    if (tid < 128) {
        int idx = bk*128 + tid;           // 128*128 = 16384 = HH*BB
        int k = idx >> 5, bb = idx & 31;
        __stcg(&g_hA[idx], lasth[bb*HH + k]);
    }
    grid_barrier(GRU_BLOCKS);

    float* hp = g_hA;
    float* hc = g_hB;
    const float* wr = sw[0][jl];
    const float* wz = sw[1][jl];
    const float* wn = sw[2][jl];
    int k0 = kh * 256;

    for (int n = 0; n < NN; n++) {
        float sr = 0.f, sz = 0.f, sn = 0.f;
#pragma unroll 4
        for (int k = k0; k < k0 + 256; k += 4) {
            float4 r4 = *(const float4*)(wr + k);
            float4 z4 = *(const float4*)(wz + k);
            float4 n4 = *(const float4*)(wn + k);
            float h0 = __ldcg(hp + (k+0)*BB + b);
            float h1 = __ldcg(hp + (k+1)*BB + b);
            float h2 = __ldcg(hp + (k+2)*BB + b);
            float h3 = __ldcg(hp + (k+3)*BB + b);
            sr += r4.x*h0 + r4.y*h1 + r4.z*h2 + r4.w*h3;
            sz += z4.x*h0 + z4.y*h1 + z4.z*h2 + z4.w*h3;
            sn += n4.x*h0 + n4.y*h1 + n4.z*h2 + n4.w*h3;
        }
        if (kh == 1) {
            part[0][jl*32+b] = sr; part[1][jl*32+b] = sz; part[2][jl*32+b] = sn;
        }
        __syncthreads();
        if (kh == 0) {
            sr += part[0][jl*32+b]; sz += part[1][jl*32+b]; sn += part[2][jl*32+b];
            float hold = __ldcg(hp + jg*BB + b);
            const float* gi = g_gi + ((long)(n*BB + b))*(3*HH);
            float rr = 1.f/(1.f + expf(-(gi[jg]        + sr + sb[0][jl])));
            float zz = 1.f/(1.f + expf(-(gi[HH + jg]   + sz + sb[1][jl])));
            float nn = tanhf(gi[2*HH + jg] + rr*(sn + sb[2][jl]));
            float hn = (1.f - zz)*nn + zz*hold;
            __stcg(hc + jg*BB + b, hn);
            g_rnn[((long)(n*BB + b))*HH + jg] = hn;
            if (n == NN-1) hid[b*HH + jg] = hn;
        }
        grid_barrier(GRU_BLOCKS);
        float* t = hp; hp = hc; hc = t;
    }
}

// ---------------- tf32 tensor-core GEMM primitives ----------------
__device__ __forceinline__ uint32_t f2tf(float x) {
    uint32_t u; asm("cvt.rna.tf32.f32 %0, %1;" : "=r"(u) : "f"(x)); return u;
}
__device__ __forceinline__ void split_tf32(float x, uint32_t& hi, uint32_t& lo) {
    hi = f2tf(x);
    float r = x - __uint_as_float(hi);
    lo = f2tf(r);
}
__device__ __forceinline__ void mma_tf32(float& c0, float& c1, float& c2, float& c3,
                                         uint32_t a0, uint32_t a1, uint32_t a2, uint32_t a3,
                                         uint32_t b0, uint32_t b1) {
    asm volatile("mma.sync.aligned.m16n8k8.row.col.f32.tf32.tf32.f32 "
                 "{%0,%1,%2,%3},{%4,%5,%6,%7},{%8,%9},{%0,%1,%2,%3};"
                 : "+f"(c0), "+f"(c1), "+f"(c2), "+f"(c3)
                 : "r"(a0), "r"(a1), "r"(a2), "r"(a3), "r"(b0), "r"(b1));
}
__device__ __forceinline__ void cpa16(uint32_t saddr, const void* gaddr) {
    asm volatile("cp.async.cg.shared.global [%0], [%1], 16;" :: "r"(saddr), "l"(gaddr));
}

// A-row source for the fused concat GEMM: [rnn | ctx1 | ctx2 | ctx3]
__device__ __forceinline__ const float* concat_src(int m, int k) {
    if (k < HH)        return g_rnn  + (long)m*HH + k;
    if (k < 2*HH)      return g_ctx1 + (long)m*HH + (k - HH);
    if (k < 3*HH)      return g_ctx2 + (long)m*HH + (k - 2*HH);
    return g_ctx3 + (long)m*KK + (k - 3*HH);
}

// BM=128, BN=128, BK=16; 128 threads (4 warps 2x2), warp tile 64x64.
// ASRC: 0 plain A, 1 concat gather. SWAP: 1 => blockIdx.x is the m-tile (L2 reuse of W).
template<int ASRC, int SWAP>
__global__ __launch_bounds__(128, 2)
void k_gemm_tf32(const float* __restrict__ A, const float* __restrict__ W,
                 const float* __restrict__ bias, float* __restrict__ C,
                 int Kd, int ldC, int act) {
    __shared__ __align__(16) float As[2][128][20];
    __shared__ __align__(16) float Bs[2][128][20];
    int tid = threadIdx.x;
    int warp = tid >> 5, lane = tid & 31;
    int wm = warp & 1, wnp = warp >> 1;
    int lq = lane >> 2, lr = lane & 3;
    int m0 = (SWAP ? blockIdx.x : blockIdx.y) * 128;
    int n0 = (SWAP ? blockIdx.y : blockIdx.x) * 128;

    float acc[4][8][4];
#pragma unroll
    for (int i = 0; i < 4; i++)
#pragma unroll
        for (int j = 0; j < 8; j++)
#pragma unroll
            for (int c = 0; c < 4; c++) acc[i][j][c] = 0.f;

    const int NK = Kd / 16;
#pragma unroll
    for (int i = 0; i < 4; i++) {
        int idx = i*128 + tid, row = idx >> 2, kc = idx & 3;
        const float* asrc = ASRC ? concat_src(m0+row, kc*4)
                                 : A + (long)(m0+row)*Kd + kc*4;
        cpa16((uint32_t)__cvta_generic_to_shared(&As[0][row][kc*4]), asrc);
        cpa16((uint32_t)__cvta_generic_to_shared(&Bs[0][row][kc*4]),
              W + (long)(n0+row)*Kd + kc*4);
    }
    asm volatile("cp.async.commit_group;");

    int buf = 0;
    for (int ks = 0; ks < NK; ks++) {
        asm volatile("cp.async.wait_group 0;");
        __syncthreads();
        if (ks + 1 < NK) {
#pragma unroll
            for (int i = 0; i < 4; i++) {
                int idx = i*128 + tid, row = idx >> 2, kc = idx & 3;
                int kpos = (ks+1)*16 + kc*4;
                const float* asrc = ASRC ? concat_src(m0+row, kpos)
                                         : A + (long)(m0+row)*Kd + kpos;
                cpa16((uint32_t)__cvta_generic_to_shared(&As[buf^1][row][kc*4]), asrc);
                cpa16((uint32_t)__cvta_generic_to_shared(&Bs[buf^1][row][kc*4]),
                      W + (long)(n0+row)*Kd + kpos);
            }
            asm volatile("cp.async.commit_group;");
        }
#pragma unroll
        for (int kk = 0; kk < 16; kk += 8) {
            uint32_t af[4][4], bf[8][2];
#pragma unroll
            for (int ms = 0; ms < 4; ms++) {
                int rb = wm*64 + ms*16;
                af[ms][0] = f2tf(As[buf][rb + lq    ][kk + lr    ]);
                af[ms][1] = f2tf(As[buf][rb + lq + 8][kk + lr    ]);
                af[ms][2] = f2tf(As[buf][rb + lq    ][kk + lr + 4]);
                af[ms][3] = f2tf(As[buf][rb + lq + 8][kk + lr + 4]);
            }
#pragma unroll
            for (int ns = 0; ns < 8; ns++) {
                int nb = wnp*64 + ns*8;
                bf[ns][0] = f2tf(Bs[buf][nb + lq][kk + lr    ]);
                bf[ns][1] = f2tf(Bs[buf][nb + lq][kk + lr + 4]);
            }
#pragma unroll
            for (int ms = 0; ms < 4; ms++)
#pragma unroll
                for (int ns = 0; ns < 8; ns++)
                    mma_tf32(acc[ms][ns][0], acc[ms][ns][1], acc[ms][ns][2], acc[ms][ns][3],
                             af[ms][0], af[ms][1], af[ms][2], af[ms][3],
                             bf[ns][0], bf[ns][1]);
        }
        buf ^= 1;
    }
#pragma unroll
    for (int ms = 0; ms < 4; ms++) {
        int row = m0 + wm*64 + ms*16 + lq;
#pragma unroll
        for (int ns = 0; ns < 8; ns++) {
            int col = n0 + wnp*64 + ns*8 + lr*2;
            float b0 = bias[col], b1 = bias[col+1];
            float v00 = acc[ms][ns][0] + b0, v01 = acc[ms][ns][1] + b1;
            float v10 = acc[ms][ns][2] + b0, v11 = acc[ms][ns][3] + b1;
            if (act) { v00 = tanhf(v00); v01 = tanhf(v01); v10 = tanhf(v10); v11 = tanhf(v11); }
            *(float2*)(C + (long)row*ldC + col)     = make_float2(v00, v01);
            *(float2*)(C + (long)(row+8)*ldC + col) = make_float2(v10, v11);
        }
    }
}

// split-precision tf32 GEMM (fp32-accurate): BM=128, BN=128, 256 thr, warp tile 64x32.
__global__ __launch_bounds__(256)
void k_gemm_tf32s(const float* __restrict__ A, const float* __restrict__ W,
                  const float* __restrict__ bias, float* __restrict__ C,
                  int Kd, int ldC) {
    __shared__ __align__(16) float As[2][128][20];
    __shared__ __align__(16) float Bs[2][128][20];
    int tid = threadIdx.x;
    int warp = tid >> 5, lane = tid & 31;
    int wm = warp & 1, wn = warp >> 1;           // 2 x 4 warps
    int lq = lane >> 2, lr = lane & 3;
    int m0 = blockIdx.y * 128, n0 = blockIdx.x * 128;

    float acc[4][4][4];
#pragma unroll
    for (int i = 0; i < 4; i++)
#pragma unroll
        for (int j = 0; j < 4; j++)
#pragma unroll
            for (int c = 0; c < 4; c++) acc[i][j][c] = 0.f;

    const int NK = Kd / 16;
#pragma unroll
    for (int i = 0; i < 2; i++) {
        int idx = i*256 + tid, row = idx >> 2, kc = idx & 3;
        cpa16((uint32_t)__cvta_generic_to_shared(&As[0][row][kc*4]),
              A + (long)(m0+row)*Kd + kc*4);
        cpa16((uint32_t)__cvta_generic_to_shared(&Bs[0][row][kc*4]),
              W + (long)(n0+row)*Kd + kc*4);
    }
    asm volatile("cp.async.commit_group;");

    int buf = 0;
    for (int ks = 0; ks < NK; ks++) {
        asm volatile("cp.async.wait_group 0;");
        __syncthreads();
        if (ks + 1 < NK) {
#pragma unroll
            for (int i = 0; i < 2; i++) {
                int idx = i*256 + tid, row = idx >> 2, kc = idx & 3;
                int kpos = (ks+1)*16 + kc*4;
                cpa16((uint32_t)__cvta_generic_to_shared(&As[buf^1][row][kc*4]),
                      A + (long)(m0+row)*Kd + kpos);
                cpa16((uint32_t)__cvta_generic_to_shared(&Bs[buf^1][row][kc*4]),
                      W + (long)(n0+row)*Kd + kpos);
            }
            asm volatile("cp.async.commit_group;");
        }
#pragma unroll
        for (int kk = 0; kk < 16; kk += 8) {
            uint32_t ah[4][4], al[4][4], bh[4][2], bl[4][2];
#pragma unroll
            for (int ms = 0; ms < 4; ms++) {
                int rb = wm*64 + ms*16;
                split_tf32(As[buf][rb + lq    ][kk + lr    ], ah[ms][0], al[ms][0]);
                split_tf32(As[buf][rb + lq + 8][kk + lr    ], ah[ms][1], al[ms][1]);
                split_tf32(As[buf][rb + lq    ][kk + lr + 4], ah[ms][2], al[ms][2]);
                split_tf32(As[buf][rb + lq + 8][kk + lr + 4], ah[ms][3], al[ms][3]);
            }
#pragma unroll
            for (int ns = 0; ns < 4; ns++) {
                int nb = wn*32 + ns*8;
                split_tf32(Bs[buf][nb + lq][kk + lr    ], bh[ns][0], bl[ns][0]);
                split_tf32(Bs[buf][nb + lq][kk + lr + 4], bh[ns][1], bl[ns][1]);
            }
#pragma unroll
            for (int ms = 0; ms < 4; ms++)
#pragma unroll
                for (int ns = 0; ns < 4; ns++) {
                    mma_tf32(acc[ms][ns][0], acc[ms][ns][1], acc[ms][ns][2], acc[ms][ns][3],
                             ah[ms][0], ah[ms][1], ah[ms][2], ah[ms][3], bh[ns][0], bh[ns][1]);
                    mma_tf32(acc[ms][ns][0], acc[ms][ns][1], acc[ms][ns][2], acc[ms][ns][3],
                             ah[ms][0], ah[ms][1], ah[ms][2], ah[ms][3], bl[ns][0], bl[ns][1]);
                    mma_tf32(acc[ms][ns][0], acc[ms][ns][1], acc[ms][ns][2], acc[ms][ns][3],
                             al[ms][0], al[ms][1], al[ms][2], al[ms][3], bh[ns][0], bh[ns][1]);
                }
        }
        buf ^= 1;
    }
#pragma unroll
    for (int ms = 0; ms < 4; ms++) {
        int row = m0 + wm*64 + ms*16 + lq;
#pragma unroll
        for (int ns = 0; ns < 4; ns++) {
            int col = n0 + wn*32 + ns*8 + lr*2;
            float b0 = bias[col], b1 = bias[col+1];
            *(float2*)(C + (long)row*ldC + col)     = make_float2(acc[ms][ns][0] + b0, acc[ms][ns][1] + b1);
            *(float2*)(C + (long)(row+8)*ldC + col) = make_float2(acc[ms][ns][2] + b0, acc[ms][ns][3] + b1);
        }
    }
}

// ---------------- uvec: stage 1 (209 blocks of partials) + stage 2 (reduce) ----------------
__global__ void k_uvec_p(const float* __restrict__ attnW, const float* __restrict__ attnv,
                         const float* __restrict__ attnb, const float* __restrict__ attrW,
                         const float* __restrict__ attrv, const float* __restrict__ attrb) {
    __shared__ float red[4][64];
    int blk = blockIdx.x;
    int tid = threadIdx.x;
    if (blk < 208) {
        int hb = blk / 26, cb = blk - hb*26;
        int tx = tid & 63, hy = tid >> 6;
        int col = cb*64 + tx;
        const float* W; const float* v; int ld; int c;
        if (col < 2*HH) { W = attnW; v = attnv; ld = 2*HH;    c = col; }
        else            { W = attrW; v = attrv; ld = HH + KK; c = col - 2*HH; }
        int h0 = hb*64;
        float acc = 0.f;
        for (int t = 0; t < 16; t++) {
            int h = h0 + hy + t*4;
            acc += W[(long)h*ld + c] * v[h];
        }
        red[hy][tx] = acc;
        __syncthreads();
        if (hy == 0) g_upart[hb][col] = red[0][tx] + red[1][tx] + red[2][tx] + red[3][tx];
    } else {
        int w = tid >> 5, lane = tid & 31;
        if (w < 2) {
            const float* bp = w ? attrb : attnb;
            const float* vp = w ? attrv : attnv;
            float s = 0.f;
            for (int h = lane; h < HH; h += 32) s += bp[h]*vp[h];
#pragma unroll
            for (int o = 16; o > 0; o >>= 1) s += __shfl_xor_sync(0xffffffffu, s, o);
            if (lane == 0) g_bv[w] = s;
        }
    }
}

__global__ void k_uvec_r() {
    int i = blockIdx.x * blockDim.x + threadIdx.x;
    if (i >= UCOLS) return;
    float s = 0.f;
#pragma unroll
    for (int hb = 0; hb < 8; hb++) s += g_upart[hb][i];
    if (i < HH)            g_u1[i] = s;
    else if (i < 2*HH)     g_u1e[i - HH] = s;
    else if (i < 3*HH)     g_u3[i - 2*HH] = s;
    else                   g_u3e[i - 3*HH] = s;
}

// all scalar attention dot products (warp per output; a1+a3 fused)
__global__ void k_ac(const float* __restrict__ enc1, const float* __restrict__ enc2,
                     const float* __restrict__ enc3) {
    int gw = (blockIdx.x * blockDim.x + threadIdx.x) >> 5;
    int lane = threadIdx.x & 31;
    const int E_A = M2, E_C1 = E_A + TT*BB, E_C2 = E_C1 + SS*BB, E_C3 = E_C2 + AA*BB;
    if (gw >= E_C3) return;
    if (gw < E_A) {
        const float* x = g_rnn + (long)gw*HH;
        float s1 = 0.f, s3 = 0.f;
        for (int k = lane; k < HH; k += 32) {
            float xv = x[k];
            s1 += xv*g_u1[k];
            s3 += xv*g_u3[k];
        }
#pragma unroll
        for (int o = 16; o > 0; o >>= 1) {
            s1 += __shfl_xor_sync(0xffffffffu, s1, o);
            s3 += __shfl_xor_sync(0xffffffffu, s3, o);
        }
        if (lane == 0) { g_a1[gw] = s1 + g_bv[0]; g_a3[gw] = s3 + g_bv[1]; }
        return;
    }
    const float* x; const float* u; float* dst; int len = HH;
    if (gw < E_C1)      { int m = gw - E_A;   x = enc1 + (long)m*HH; u = g_u1e; dst = g_c1 + m; }
    else if (gw < E_C2) { int m = gw - E_C1;  x = enc2 + (long)m*HH; u = g_u1e; dst = g_c2 + m; }
    else                { int m = gw - E_C2;  x = enc3 + (long)m*KK; u = g_u3e; dst = g_c3 + m; len = KK; }
    float s = 0.f;
    for (int k = lane; k < len; k += 32) s += x[k]*u[k];
#pragma unroll
    for (int o = 16; o > 0; o >>= 1) s += __shfl_xor_sync(0xffffffffu, s, o);
    if (lane == 0) *dst = s;
}

__global__ void k_softmax1(float* __restrict__ aw1) {
    int bn = blockIdx.x;
    int b = bn / NN, n = bn - b*NN;
    int t = threadIdx.x;
    float e  = tanhf(g_a1[n*BB + b] + g_c1[t*BB + b]);
    float ex = expf(e);
    __shared__ float red[8];
    __shared__ float stot;
    float s = ex;
#pragma unroll
    for (int o = 16; o > 0; o >>= 1) s += __shfl_xor_sync(0xffffffffu, s, o);
    if ((t & 31) == 0) red[t >> 5] = s;
    __syncthreads();
    if (t == 0) { float tt = 0.f; for (int i = 0; i < 8; i++) tt += red[i]; stot = tt; }
    __syncthreads();
    aw1[(long)bn*TT + t] = ex / stot;
}

__global__ void k_softmax2(float* __restrict__ aw2) {
    int gw = (blockIdx.x * blockDim.x + threadIdx.x) >> 5;
    if (gw >= BB*NN) return;
    int b = gw / NN, n = gw - b*NN;
    int s = threadIdx.x & 31;
    float e  = tanhf(g_a1[n*BB + b] + g_c2[s*BB + b]);
    float ex = expf(e);
    float tot = ex;
#pragma unroll
    for (int o = 16; o > 0; o >>= 1) tot += __shfl_xor_sync(0xffffffffu, tot, o);
    aw2[(long)gw*SS + s] = ex / tot;
}

__global__ void k_softmax3(float* __restrict__ aw3) {
    int bn = blockIdx.x * blockDim.x + threadIdx.x;
    if (bn >= BB*NN) return;
    int b = bn / NN, n = bn - b*NN;
    float ex[AA]; float tot = 0.f;
#pragma unroll
    for (int a = 0; a < AA; a++) {
        ex[a] = expf(tanhf(g_a3[n*BB + b] + g_c3[a*BB + b]));
        tot += ex[a];
    }
#pragma unroll
    for (int a = 0; a < AA; a++) aw3[(long)bn*AA + a] = ex[a] / tot;
}

// tiled ctx: dst[n,b,h] = sum_t aw[b,n,t] * enc[t,b,h].
__global__ void k_ctx_t(const float* __restrict__ aw, const float* __restrict__ enc,
                        float* __restrict__ dst, int L, int D) {
    int b  = blockIdx.x;
    int h0 = blockIdx.y * 64;
    int tid = threadIdx.x;
    __shared__ float AWs[64][33];
    __shared__ float Es[32][68];
    int tx = tid & 15, ty = tid >> 4;
    float acc[4][4] = {};
    for (int t0 = 0; t0 < L; t0 += 32) {
        {
            int row = tid >> 2, c0 = (tid & 3) * 8;
            const float* ap = aw + ((long)b*NN + row)*L + t0 + c0;
            float4 v0 = *(const float4*)ap;
            float4 v1 = *(const float4*)(ap + 4);
            AWs[row][c0+0]=v0.x; AWs[row][c0+1]=v0.y; AWs[row][c0+2]=v0.z; AWs[row][c0+3]=v0.w;
            AWs[row][c0+4]=v1.x; AWs[row][c0+5]=v1.y; AWs[row][c0+6]=v1.z; AWs[row][c0+7]=v1.w;
        }
        {
            int row = tid >> 3, c0 = (tid & 7) * 8;
            const float* ep = enc + (((long)(t0+row))*BB + b)*D + h0 + c0;
            float4 v0 = *(const float4*)ep;
            float4 v1 = *(const float4*)(ep + 4);
            Es[row][c0+0]=v0.x; Es[row][c0+1]=v0.y; Es[row][c0+2]=v0.z; Es[row][c0+3]=v0.w;
            Es[row][c0+4]=v1.x; Es[row][c0+5]=v1.y; Es[row][c0+6]=v1.z; Es[row][c0+7]=v1.w;
        }
        __syncthreads();
#pragma unroll
        for (int tt = 0; tt < 32; tt++) {
            float a[4], e[4];
#pragma unroll
            for (int i = 0; i < 4; i++) { a[i] = AWs[ty*4+i][tt]; e[i] = Es[tt][tx*4+i]; }
#pragma unroll
            for (int i = 0; i < 4; i++)
#pragma unroll
                for (int j = 0; j < 4; j++) acc[i][j] += a[i]*e[j];
        }
        __syncthreads();
    }
#pragma unroll
    for (int i = 0; i < 4; i++) {
        int n = ty*4 + i;
#pragma unroll
        for (int j = 0; j < 4; j++)
            dst[(((long)n)*BB + b)*D + h0 + tx*4 + j] = acc[i][j];
    }
}

// naive ctx (L=5, D=128)
__global__ void k_ctx(const float* __restrict__ aw, const float* __restrict__ enc,
                      float* __restrict__ dst, int L, int D) {
    int i = blockIdx.x * blockDim.x + threadIdx.x;
    if (i >= M2*KK) return;
    int m = i / D, h = i - m*D;
    int n = m / BB, b = m - n*BB;
    const float* awp = aw + ((long)b*NN + n)*L;
    float s = 0.f;
    for (int t = 0; t < L; t++) s += awp[t]*enc[((long)t*BB + b)*D + h];
    dst[i] = s;
}

__global__ void k_e4(const float* __restrict__ enc4, const float* __restrict__ projW,
                     const float* __restrict__ projb) {
    int i = blockIdx.x * blockDim.x + threadIdx.x;
    if (i >= BB*AN) return;
    int b = i / AN, j = i - b*AN;
    float s = projb[j];
    for (int k = 0; k < AN; k++) s += enc4[(0*BB + b)*AN + k]*projW[j*2*AN + k];
    for (int k = 0; k < AN; k++) s += enc4[(1*BB + b)*AN + k]*projW[j*2*AN + AN + k];
    g_e4[i] = s;
}

// fused gin+gate
__global__ void k_gate2(const float* __restrict__ gateW, const float* __restrict__ gateb,
                        float* __restrict__ gateout) {
    int m0 = blockIdx.x * 4;
    int tid = threadIdx.x;
    __shared__ float xs[4][GIN + 12];
#pragma unroll
    for (int r = 0; r < 4; r++) {
        int m = m0 + r, b = m & 31;
        for (int k = tid; k < GIN; k += 256) {
            float v;
            if (k < HH)        v = g_emb[(long)m*HH + k];
            else if (k < 2*HH) v = g_rnn[(long)m*HH + k - HH];
            else               v = g_e4[b*AN + k - 2*HH];
            xs[r][k] = v;
        }
    }
    __syncthreads();
    int w = tid >> 5, lane = tid & 31;
    for (int o = w; o < 4*AN; o += 8) {
        int r = o & 3, j = o >> 2;
        const float* wj = gateW + (long)j*GIN;
        float s = 0.f;
        for (int k = lane; k < GIN; k += 32) s += xs[r][k]*wj[k];
#pragma unroll
        for (int of = 16; of > 0; of >>= 1) s += __shfl_xor_sync(0xffffffffu, s, of);
        if (lane == 0) gateout[(long)(m0+r)*AN + j] = tanhf(s + gateb[j]);
    }
}

// duplicate chain, smem lockstep scan
__global__ void k_chain(const int* __restrict__ ids) {
    __shared__ int sid[NASP];
    int tid = threadIdx.x;
    int j = blockIdx.x * 256 + tid;
    for (int k = tid; k < NASP; k += 256) sid[k] = ids[k];
    __syncthreads();
    if (j >= NASP) return;
    int v = sid[j];
    int fst = 1, nxt = -1;
    for (int j2 = 0; j2 < NASP; j2++) {
        int w = sid[j2];
        if (w == v) {
            if (j2 < j) fst = 0;
            else if (j2 > j && nxt < 0) nxt = j2;
        }
    }
    g_first[j] = fst;
    g_next[j]  = nxt;
}

__global__ void k_scatter(const float* __restrict__ gate, const int* __restrict__ ids,
                          float* __restrict__ out0) {
    long i = (long)blockIdx.x * blockDim.x + threadIdx.x;
    if (i >= (long)M2*NASP) return;
    int m = (int)(i / NASP);
    int j = (int)(i - (long)m*NASP);
    if (!g_first[j]) return;
    float s = 0.f;
    int jj = j;
    while (jj >= 0) { s += gate[(long)m*AN + (jj % AN)]; jj = g_next[jj]; }
    out0[(long)m*VV + ids[j]] += s;
}

// ---------------- launcher ----------------
extern "C" void kernel_launch(void* const* d_in, const int* in_sizes, int n_in,
                              void* d_out, int out_size) {
    const int*   seq   = (const int*)  d_in[0];
    const float* lasth = (const float*)d_in[1];
    const float* enc1  = (const float*)d_in[2];
    const float* enc2  = (const float*)d_in[3];
    const float* enc3  = (const float*)d_in[4];
    const float* enc4  = (const float*)d_in[5];
    const int*   asp   = (const int*)  d_in[6];
    const float* emb   = (const float*)d_in[7];
    const float* Wih   = (const float*)d_in[8];
    const float* bih   = (const float*)d_in[10];
    const float* Whh   = (const float*)d_in[9];
    const float* bhh   = (const float*)d_in[11];
    const float* attnW = (const float*)d_in[12];
    const float* attnb = (const float*)d_in[13];
    const float* attnv = (const float*)d_in[14];
    const float* attrW = (const float*)d_in[15];
    const float* attrb = (const float*)d_in[16];
    const float* attrv = (const float*)d_in[17];
    const float* concW = (const float*)d_in[18];
    const float* concb = (const float*)d_in[19];
    const float* outW  = (const float*)d_in[20];
    const float* outb  = (const float*)d_in[21];
    const float* gateW = (const float*)d_in[22];
    const float* gateb = (const float*)d_in[23];
    const float* projW = (const float*)d_in[24];
    const float* projb = (const float*)d_in[25];
    float* out = (float*)d_out;

    const long O_HID  = (long)M2*VV;
    const long O_AW1  = O_HID + (long)BB*HH;
    const long O_AW2  = O_AW1 + (long)BB*NN*TT;
    const long O_AW3  = O_AW2 + (long)BB*NN*SS;
    const long O_GATE = O_AW3 + (long)BB*NN*AA;

    float *p_emb, *p_gi, *p_cout, *p_ctx1, *p_ctx2, *p_ctx3;
    cudaGetSymbolAddress((void**)&p_emb,  g_emb);
    cudaGetSymbolAddress((void**)&p_gi,   g_gi);
    cudaGetSymbolAddress((void**)&p_cout, g_cout);
    cudaGetSymbolAddress((void**)&p_ctx1, g_ctx1);
    cudaGetSymbolAddress((void**)&p_ctx2, g_ctx2);
    cudaGetSymbolAddress((void**)&p_ctx3, g_ctx3);

    // 1) embedding
    k_embed<<<(M2*HH + 255)/256, 256>>>(seq, emb);

    // 2) gi = embedded @ Wih^T + bih (split-tf32: fp32-accurate, tensor speed)
    k_gemm_tf32s<<<dim3((3*HH)/128, M2/128), 256>>>(p_emb, Wih, bih, p_gi, HH, 3*HH);

    // 3) persistent GRU (all 64 steps + fused hidden output)
    k_gru_all<<<GRU_BLOCKS, 256>>>(lasth, Whh, bhh, out + O_HID);

    // 4) projected attention vectors (2-stage) + scalar dots
    k_uvec_p<<<209, 256>>>(attnW, attnv, attnb, attrW, attrv, attrb);
    k_uvec_r<<<(UCOLS + 255)/256, 256>>>();
    {
        int warps = M2 + TT*BB + SS*BB + AA*BB;
        k_ac<<<(warps*32 + 255)/256, 256>>>(enc1, enc2, enc3);
    }

    // 5) softmaxes -> aw outputs
    k_softmax1<<<BB*NN, TT>>>(out + O_AW1);
    k_softmax2<<<(BB*NN*32 + 255)/256, 256>>>(out + O_AW2);
    k_softmax3<<<(BB*NN + 255)/256, 256>>>(out + O_AW3);

    // 6) contexts
    k_ctx_t<<<dim3(BB, HH/64), 256>>>(out + O_AW1, enc1, p_ctx1, TT, HH);
    k_ctx_t<<<dim3(BB, HH/64), 256>>>(out + O_AW2, enc2, p_ctx2, SS, HH);
    k_ctx  <<<(M2*KK + 255)/256, 256>>>(out + O_AW3, enc3, p_ctx3, AA, KK);

    // 7) fused concat-gather tf32 GEMM (tanh) -> big tf32 output GEMM (m-tile-fastest grid)
    k_gemm_tf32<1,0><<<dim3(HH/128, M2/128), 128>>>(nullptr, concW, concb, p_cout, CIN, HH, 1);
    k_gemm_tf32<0,1><<<dim3(M2/128, VV/128), 128>>>(p_cout, outW, outb, out, HH, VV, 0);

    // 8) gate path
    k_e4<<<(BB*AN + 255)/256, 256>>>(enc4, projW, projb);
    k_gate2<<<M2/4, 256>>>(gateW, gateb, out + O_GATE);

    // 9) deterministic scatter-add
    k_chain<<<(NASP + 255)/256, 256>>>(asp);
    k_scatter<<<(int)(((long)M2*NASP + 255)/256), 256>>>(out + O_GATE, asp, out);
}

// round 8
// speedup vs baseline: 3.1346x; 1.1554x over previous
#include <cuda_runtime.h>
#include <cuda_bf16.h>
#include <math.h>
#include <stdint.h>

#define NN 64
#define BB 32
#define HH 512
#define KK 128
#define VV 32000
#define TT 256
#define SS 32
#define AA 5
#define AN 20
#define M2 (NN*BB)          // 2048 rows
#define CIN (3*HH+KK)       // 1664
#define GIN (2*HH+AN)       // 1044
#define NASP 2000
#define GRU_BLOCKS 128
#define UCOLS (2*HH + HH + KK)   // 1664 projected columns

// ---------------- scratch (static device globals; no runtime alloc) ----------------
__device__ __align__(16) float g_emb[M2*HH];
__device__ __align__(16) float g_gi[M2*3*HH];
__device__ __align__(16) float g_hA[HH*BB];
__device__ __align__(16) float g_hB[HH*BB];
__device__ __align__(16) float g_rnn[M2*HH];
__device__ __align__(16) float g_u1[HH];
__device__ __align__(16) float g_u1e[HH];
__device__ __align__(16) float g_u3[HH];
__device__ __align__(16) float g_u3e[KK];
__device__ float g_bv[2];
__device__ __align__(16) float g_upart[16][UCOLS];
__device__ float g_a1[M2], g_a3[M2];
__device__ float g_c1[TT*BB], g_c2[SS*BB], g_c3[AA*BB];
__device__ __align__(16) float g_ctx1[M2*HH];
__device__ __align__(16) float g_ctx2[M2*HH];
__device__ __align__(16) float g_ctx3[M2*KK];
__device__ __align__(16) float g_cout[M2*HH];
__device__ __align__(16) uint32_t g_wt[VV*HH];      // 65.5 MB pre-rounded, fragment-packed W
__device__ __align__(16) uint32_t g_at[M2*HH];      // 4 MB fragment-packed A
__device__ float g_e4[BB*AN];
__device__ int g_first[NASP], g_next[NASP];
__device__ unsigned g_barcnt = 0;
__device__ unsigned g_bargen = 0;

// ---------------- grid barrier (release/acquire) ----------------
__device__ __forceinline__ void grid_barrier(unsigned nb) {
    __syncthreads();
    if (threadIdx.x == 0) {
        unsigned gen;
        asm volatile("ld.relaxed.gpu.global.u32 %0, [%1];" : "=r"(gen) : "l"(&g_bargen));
        unsigned prev;
        asm volatile("atom.release.gpu.global.add.u32 %0, [%1], 1;" : "=r"(prev) : "l"(&g_barcnt));
        if (prev == nb - 1u) {
            asm volatile("st.relaxed.gpu.global.u32 [%0], %1;" :: "l"(&g_barcnt), "r"(0u));
            unsigned d;
            asm volatile("atom.release.gpu.global.add.u32 %0, [%1], 1;" : "=r"(d) : "l"(&g_bargen));
        } else {
            unsigned cur;
            do {
                __nanosleep(20);
                asm volatile("ld.acquire.gpu.global.u32 %0, [%1];" : "=r"(cur) : "l"(&g_bargen));
            } while (cur == gen);
        }
    }
    __syncthreads();
}

// ---------------- helpers ----------------
__device__ __forceinline__ uint32_t smem_u32(const void* p) {
    uint32_t a;
    asm("{ .reg .u64 t; cvta.to.shared.u64 t, %1; cvt.u32.u64 %0, t; }" : "=r"(a) : "l"(p));
    return a;
}
__device__ __forceinline__ uint32_t f2tf(float x) {
    uint32_t u; asm("cvt.rna.tf32.f32 %0, %1;" : "=r"(u) : "f"(x)); return u;
}
__device__ __forceinline__ void split_tf32(float x, uint32_t& hi, uint32_t& lo) {
    hi = f2tf(x);
    float r = x - __uint_as_float(hi);
    lo = f2tf(r);
}
__device__ __forceinline__ void mma_tf32(float& c0, float& c1, float& c2, float& c3,
                                         uint32_t a0, uint32_t a1, uint32_t a2, uint32_t a3,
                                         uint32_t b0, uint32_t b1) {
    asm volatile("mma.sync.aligned.m16n8k8.row.col.f32.tf32.tf32.f32 "
                 "{%0,%1,%2,%3},{%4,%5,%6,%7},{%8,%9},{%0,%1,%2,%3};"
                 : "+f"(c0), "+f"(c1), "+f"(c2), "+f"(c3)
                 : "r"(a0), "r"(a1), "r"(a2), "r"(a3), "r"(b0), "r"(b1));
}
__device__ __forceinline__ void cpa16(uint32_t saddr, const void* gaddr) {
    asm volatile("cp.async.cg.shared.global [%0], [%1], 16;" :: "r"(saddr), "l"(gaddr));
}

// ---------------- kernels ----------------

__global__ void k_embed(const int* __restrict__ seq, const float* __restrict__ emb) {
    int i = blockIdx.x * blockDim.x + threadIdx.x;
    if (i < M2*HH) {
        int m = i / HH, h = i - m*HH;
        g_emb[i] = emb[(long)seq[m]*HH + h];
    }
}

// ---- fragment packing for the big GEMM ----
// layout: [blk128][k8 s][fragpair fp 0..7][lane 0..31] -> uint4
// B (W) pack: v = { B[f=2fp,lq][k], B[f=2fp,lq][k+4], B[f=2fp+1,lq][k], B[f=2fp+1,lq][k+4] }, n = blk*128 + f*8 + lq
__global__ void k_pack_w(const float* __restrict__ W) {
    long i = (long)blockIdx.x * 256 + threadIdx.x;
    if (i >= (long)(VV/128)*64*8*32) return;
    int lane = (int)(i & 31), fp = (int)((i >> 5) & 7), s = (int)((i >> 8) & 63);
    long nb = i >> 14;
    int lq = lane >> 2, lr = lane & 3;
    int k = s*8 + lr;
    long ne = nb*128 + fp*16 + lq;
    uint4 v;
    v.x = f2tf(W[ne*HH + k]);
    v.y = f2tf(W[ne*HH + k + 4]);
    v.z = f2tf(W[(ne+8)*HH + k]);
    v.w = f2tf(W[(ne+8)*HH + k + 4]);
    ((uint4*)g_wt)[i] = v;
}

// A pack: v = { A[mf*16+lq][k], A[mf*16+lq+8][k], A[mf*16+lq][k+4], A[mf*16+lq+8][k+4] }
__global__ void k_pack_a(const float* __restrict__ A) {
    long i = (long)blockIdx.x * 256 + threadIdx.x;
    if (i >= (long)(M2/128)*64*8*32) return;
    int lane = (int)(i & 31), mf = (int)((i >> 5) & 7), s = (int)((i >> 8) & 63);
    long mb = i >> 14;
    int lq = lane >> 2, lr = lane & 3;
    int k = s*8 + lr;
    long me = mb*128 + mf*16 + lq;
    uint4 v;
    v.x = f2tf(A[me*HH + k]);
    v.y = f2tf(A[(me+8)*HH + k]);
    v.z = f2tf(A[me*HH + k + 4]);
    v.w = f2tf(A[(me+8)*HH + k + 4]);
    ((uint4*)g_at)[i] = v;
}

// ---------------- packed tf32 GEMM: C[M2,VV] = A[M2,HH] * W[VV,HH]^T + bias ----------------
// grid (M2/128, VV/128): x = m-tile (fast -> W L2 reuse). 128 threads, 2 blocks/SM.
__global__ __launch_bounds__(128, 2)
void k_gemm_tf32p(const uint4* __restrict__ At, const uint4* __restrict__ Wt,
                  const float* __restrict__ bias, float* __restrict__ C) {
    __shared__ __align__(16) uint4 As[2][512];
    __shared__ __align__(16) uint4 Bs[2][512];
    int tid = threadIdx.x;
    int warp = tid >> 5, lane = tid & 31;
    int wm = warp & 1, wnp = warp >> 1;
    int lq = lane >> 2, lr = lane & 3;
    int m0 = blockIdx.x * 128, n0 = blockIdx.y * 128;
    const uint4* Ab = At + (long)blockIdx.x * 16384;
    const uint4* Bb = Wt + (long)blockIdx.y * 16384;

    float acc[4][8][4];
#pragma unroll
    for (int i = 0; i < 4; i++)
#pragma unroll
        for (int j = 0; j < 8; j++)
#pragma unroll
            for (int c = 0; c < 4; c++) acc[i][j][c] = 0.f;

    // prologue: stage k-tile 0 (two k8 blocks = 512 uint4 each for A and B)
#pragma unroll
    for (int i = 0; i < 4; i++) {
        cpa16(smem_u32(&As[0][i*128 + tid]), Ab + i*128 + tid);
        cpa16(smem_u32(&Bs[0][i*128 + tid]), Bb + i*128 + tid);
    }
    asm volatile("cp.async.commit_group;");

    int buf = 0;
    const int NK = HH / 16;    // 32 k16 tiles
    for (int c = 0; c < NK; c++) {
        asm volatile("cp.async.wait_group 0;" ::: "memory");
        __syncthreads();
        if (c + 1 < NK) {
            const uint4* an = Ab + (c+1)*512;
            const uint4* bn = Bb + (c+1)*512;
#pragma unroll
            for (int i = 0; i < 4; i++) {
                cpa16(smem_u32(&As[buf^1][i*128 + tid]), an + i*128 + tid);
                cpa16(smem_u32(&Bs[buf^1][i*128 + tid]), bn + i*128 + tid);
            }
            asm volatile("cp.async.commit_group;");
        }
#pragma unroll
        for (int kk = 0; kk < 2; kk++) {
            uint4 av[4], bv[4];
#pragma unroll
            for (int ms = 0; ms < 4; ms++)
                av[ms] = As[buf][kk*256 + (wm*4 + ms)*32 + lane];
#pragma unroll
            for (int p = 0; p < 4; p++)
                bv[p] = Bs[buf][kk*256 + (wnp*4 + p)*32 + lane];
#pragma unroll
            for (int ms = 0; ms < 4; ms++)
#pragma unroll
                for (int p = 0; p < 4; p++) {
                    mma_tf32(acc[ms][2*p][0], acc[ms][2*p][1], acc[ms][2*p][2], acc[ms][2*p][3],
                             av[ms].x, av[ms].y, av[ms].z, av[ms].w, bv[p].x, bv[p].y);
                    mma_tf32(acc[ms][2*p+1][0], acc[ms][2*p+1][1], acc[ms][2*p+1][2], acc[ms][2*p+1][3],
                             av[ms].x, av[ms].y, av[ms].z, av[ms].w, bv[p].z, bv[p].w);
                }
        }
        buf ^= 1;
    }
#pragma unroll
    for (int ms = 0; ms < 4; ms++) {
        int row = m0 + wm*64 + ms*16 + lq;
#pragma unroll
        for (int ns = 0; ns < 8; ns++) {
            int col = n0 + wnp*64 + ns*8 + lr*2;
            float b0 = bias[col], b1 = bias[col+1];
            *(float2*)(C + (long)row*VV + col)     = make_float2(acc[ms][ns][0] + b0, acc[ms][ns][1] + b1);
            *(float2*)(C + (long)(row+8)*VV + col) = make_float2(acc[ms][ns][2] + b0, acc[ms][ns][3] + b1);
        }
    }
}

// ---------------- persistent GRU ----------------
__global__ __launch_bounds__(256, 1)
void k_gru_all(const float* __restrict__ lasth, const float* __restrict__ Whh,
               const float* __restrict__ bhh, float* __restrict__ hid) {
    int tid = threadIdx.x, bk = blockIdx.x;
    int jl = (tid >> 5) & 3, b = tid & 31, kh = tid >> 7;
    int jg = bk*4 + jl;
    __shared__ __align__(16) float sw[3][4][HH];
    __shared__ float sb[3][4];
    __shared__ float part[3][128];

    for (int r = 0; r < 12; r++) {
        int g = r / 4, j = r % 4;
        int rowi = g*HH + bk*4 + j;
        for (int k = tid; k < HH; k += 256) sw[g][j][k] = Whh[(long)rowi*HH + k];
    }
    if (tid < 12) sb[tid/4][tid%4] = bhh[(tid/4)*HH + bk*4 + (tid%4)];

    if (tid < 128) {
        int idx = bk*128 + tid;
        int k = idx >> 5, bb = idx & 31;
        __stcg(&g_hA[idx], lasth[bb*HH + k]);
    }
    grid_barrier(GRU_BLOCKS);

    float* hp = g_hA;
    float* hc = g_hB;
    const float* wr = sw[0][jl];
    const float* wz = sw[1][jl];
    const float* wn = sw[2][jl];
    int k0 = kh * 256;

    for (int n = 0; n < NN; n++) {
        float sr = 0.f, sz = 0.f, sn = 0.f;
#pragma unroll 4
        for (int k = k0; k < k0 + 256; k += 4) {
            float4 r4 = *(const float4*)(wr + k);
            float4 z4 = *(const float4*)(wz + k);
            float4 n4 = *(const float4*)(wn + k);
            float h0 = __ldcg(hp + (k+0)*BB + b);
            float h1 = __ldcg(hp + (k+1)*BB + b);
            float h2 = __ldcg(hp + (k+2)*BB + b);
            float h3 = __ldcg(hp + (k+3)*BB + b);
            sr += r4.x*h0 + r4.y*h1 + r4.z*h2 + r4.w*h3;
            sz += z4.x*h0 + z4.y*h1 + z4.z*h2 + z4.w*h3;
            sn += n4.x*h0 + n4.y*h1 + n4.z*h2 + n4.w*h3;
        }
        if (kh == 1) {
            part[0][jl*32+b] = sr; part[1][jl*32+b] = sz; part[2][jl*32+b] = sn;
        }
        __syncthreads();
        if (kh == 0) {
            sr += part[0][jl*32+b]; sz += part[1][jl*32+b]; sn += part[2][jl*32+b];
            float hold = __ldcg(hp + jg*BB + b);
            const float* gi = g_gi + ((long)(n*BB + b))*(3*HH);
            float rr = 1.f/(1.f + expf(-(gi[jg]        + sr + sb[0][jl])));
            float zz = 1.f/(1.f + expf(-(gi[HH + jg]   + sz + sb[1][jl])));
            float nn = tanhf(gi[2*HH + jg] + rr*(sn + sb[2][jl]));
            float hn = (1.f - zz)*nn + zz*hold;
            __stcg(hc + jg*BB + b, hn);
            g_rnn[((long)(n*BB + b))*HH + jg] = hn;
            if (n == NN-1) hid[b*HH + jg] = hn;
        }
        grid_barrier(GRU_BLOCKS);
        float* t = hp; hp = hc; hc = t;
    }
}

// ---------------- tf32 mma GEMM (concat path, cvt at use) ----------------
__device__ __forceinline__ const float* concat_src(int m, int k) {
    if (k < HH)        return g_rnn  + (long)m*HH + k;
    if (k < 2*HH)      return g_ctx1 + (long)m*HH + (k - HH);
    if (k < 3*HH)      return g_ctx2 + (long)m*HH + (k - 2*HH);
    return g_ctx3 + (long)m*KK + (k - 3*HH);
}

template<int ASRC>
__global__ __launch_bounds__(128, 2)
void k_gemm_tf32(const float* __restrict__ A, const float* __restrict__ W,
                 const float* __restrict__ bias, float* __restrict__ C,
                 int Kd, int ldC, int act) {
    __shared__ __align__(16) float As[2][128][20];
    __shared__ __align__(16) float Bs[2][128][20];
    int tid = threadIdx.x;
    int warp = tid >> 5, lane = tid & 31;
    int wm = warp & 1, wnp = warp >> 1;
    int lq = lane >> 2, lr = lane & 3;
    int m0 = blockIdx.y * 128, n0 = blockIdx.x * 128;

    float acc[4][8][4];
#pragma unroll
    for (int i = 0; i < 4; i++)
#pragma unroll
        for (int j = 0; j < 8; j++)
#pragma unroll
            for (int c = 0; c < 4; c++) acc[i][j][c] = 0.f;

    const int NK = Kd / 16;
#pragma unroll
    for (int i = 0; i < 4; i++) {
        int idx = i*128 + tid, row = idx >> 2, kc = idx & 3;
        const float* asrc = ASRC ? concat_src(m0+row, kc*4)
                                 : A + (long)(m0+row)*Kd + kc*4;
        cpa16(smem_u32(&As[0][row][kc*4]), asrc);
        cpa16(smem_u32(&Bs[0][row][kc*4]), W + (long)(n0+row)*Kd + kc*4);
    }
    asm volatile("cp.async.commit_group;");

    int buf = 0;
    for (int ks = 0; ks < NK; ks++) {
        asm volatile("cp.async.wait_group 0;");
        __syncthreads();
        if (ks + 1 < NK) {
#pragma unroll
            for (int i = 0; i < 4; i++) {
                int idx = i*128 + tid, row = idx >> 2, kc = idx & 3;
                int kpos = (ks+1)*16 + kc*4;
                const float* asrc = ASRC ? concat_src(m0+row, kpos)
                                         : A + (long)(m0+row)*Kd + kpos;
                cpa16(smem_u32(&As[buf^1][row][kc*4]), asrc);
                cpa16(smem_u32(&Bs[buf^1][row][kc*4]), W + (long)(n0+row)*Kd + kpos);
            }
            asm volatile("cp.async.commit_group;");
        }
#pragma unroll
        for (int kk = 0; kk < 16; kk += 8) {
            uint32_t af[4][4], bf[8][2];
#pragma unroll
            for (int ms = 0; ms < 4; ms++) {
                int rb = wm*64 + ms*16;
                af[ms][0] = f2tf(As[buf][rb + lq    ][kk + lr    ]);
                af[ms][1] = f2tf(As[buf][rb + lq + 8][kk + lr    ]);
                af[ms][2] = f2tf(As[buf][rb + lq    ][kk + lr + 4]);
                af[ms][3] = f2tf(As[buf][rb + lq + 8][kk + lr + 4]);
            }
#pragma unroll
            for (int ns = 0; ns < 8; ns++) {
                int nb = wnp*64 + ns*8;
                bf[ns][0] = f2tf(Bs[buf][nb + lq][kk + lr    ]);
                bf[ns][1] = f2tf(Bs[buf][nb + lq][kk + lr + 4]);
            }
#pragma unroll
            for (int ms = 0; ms < 4; ms++)
#pragma unroll
                for (int ns = 0; ns < 8; ns++)
                    mma_tf32(acc[ms][ns][0], acc[ms][ns][1], acc[ms][ns][2], acc[ms][ns][3],
                             af[ms][0], af[ms][1], af[ms][2], af[ms][3],
                             bf[ns][0], bf[ns][1]);
        }
        buf ^= 1;
    }
#pragma unroll
    for (int ms = 0; ms < 4; ms++) {
        int row = m0 + wm*64 + ms*16 + lq;
#pragma unroll
        for (int ns = 0; ns < 8; ns++) {
            int col = n0 + wnp*64 + ns*8 + lr*2;
            float b0 = bias[col], b1 = bias[col+1];
            float v00 = acc[ms][ns][0] + b0, v01 = acc[ms][ns][1] + b1;
            float v10 = acc[ms][ns][2] + b0, v11 = acc[ms][ns][3] + b1;
            if (act) { v00 = tanhf(v00); v01 = tanhf(v01); v10 = tanhf(v10); v11 = tanhf(v11); }
            *(float2*)(C + (long)row*ldC + col)     = make_float2(v00, v01);
            *(float2*)(C + (long)(row+8)*ldC + col) = make_float2(v10, v11);
        }
    }
}

// split-precision tf32 GEMM (fp32-accurate) for gi
__global__ __launch_bounds__(256)
void k_gemm_tf32s(const float* __restrict__ A, const float* __restrict__ W,
                  const float* __restrict__ bias, float* __restrict__ C,
                  int Kd, int ldC) {
    __shared__ __align__(16) float As[2][128][20];
    __shared__ __align__(16) float Bs[2][128][20];
    int tid = threadIdx.x;
    int warp = tid >> 5, lane = tid & 31;
    int wm = warp & 1, wn = warp >> 1;
    int lq = lane >> 2, lr = lane & 3;
    int m0 = blockIdx.y * 128, n0 = blockIdx.x * 128;

    float acc[4][4][4];
#pragma unroll
    for (int i = 0; i < 4; i++)
#pragma unroll
        for (int j = 0; j < 4; j++)
#pragma unroll
            for (int c = 0; c < 4; c++) acc[i][j][c] = 0.f;

    const int NK = Kd / 16;
#pragma unroll
    for (int i = 0; i < 2; i++) {
        int idx = i*256 + tid, row = idx >> 2, kc = idx & 3;
        cpa16(smem_u32(&As[0][row][kc*4]), A + (long)(m0+row)*Kd + kc*4);
        cpa16(smem_u32(&Bs[0][row][kc*4]), W + (long)(n0+row)*Kd + kc*4);
    }
    asm volatile("cp.async.commit_group;");

    int buf = 0;
    for (int ks = 0; ks < NK; ks++) {
        asm volatile("cp.async.wait_group 0;");
        __syncthreads();
        if (ks + 1 < NK) {
#pragma unroll
            for (int i = 0; i < 2; i++) {
                int idx = i*256 + tid, row = idx >> 2, kc = idx & 3;
                int kpos = (ks+1)*16 + kc*4;
                cpa16(smem_u32(&As[buf^1][row][kc*4]), A + (long)(m0+row)*Kd + kpos);
                cpa16(smem_u32(&Bs[buf^1][row][kc*4]), W + (long)(n0+row)*Kd + kpos);
            }
            asm volatile("cp.async.commit_group;");
        }
#pragma unroll
        for (int kk = 0; kk < 16; kk += 8) {
            uint32_t ah[4][4], al[4][4], bh[4][2], bl[4][2];
#pragma unroll
            for (int ms = 0; ms < 4; ms++) {
                int rb = wm*64 + ms*16;
                split_tf32(As[buf][rb + lq    ][kk + lr    ], ah[ms][0], al[ms][0]);
                split_tf32(As[buf][rb + lq + 8][kk + lr    ], ah[ms][1], al[ms][1]);
                split_tf32(As[buf][rb + lq    ][kk + lr + 4], ah[ms][2], al[ms][2]);
                split_tf32(As[buf][rb + lq + 8][kk + lr + 4], ah[ms][3], al[ms][3]);
            }
#pragma unroll
            for (int ns = 0; ns < 4; ns++) {
                int nb = wn*32 + ns*8;
                split_tf32(Bs[buf][nb + lq][kk + lr    ], bh[ns][0], bl[ns][0]);
                split_tf32(Bs[buf][nb + lq][kk + lr + 4], bh[ns][1], bl[ns][1]);
            }
#pragma unroll
            for (int ms = 0; ms < 4; ms++)
#pragma unroll
                for (int ns = 0; ns < 4; ns++) {
                    mma_tf32(acc[ms][ns][0], acc[ms][ns][1], acc[ms][ns][2], acc[ms][ns][3],
                             ah[ms][0], ah[ms][1], ah[ms][2], ah[ms][3], bh[ns][0], bh[ns][1]);
                    mma_tf32(acc[ms][ns][0], acc[ms][ns][1], acc[ms][ns][2], acc[ms][ns][3],
                             ah[ms][0], ah[ms][1], ah[ms][2], ah[ms][3], bl[ns][0], bl[ns][1]);
                    mma_tf32(acc[ms][ns][0], acc[ms][ns][1], acc[ms][ns][2], acc[ms][ns][3],
                             al[ms][0], al[ms][1], al[ms][2], al[ms][3], bh[ns][0], bh[ns][1]);
                }
        }
        buf ^= 1;
    }
#pragma unroll
    for (int ms = 0; ms < 4; ms++) {
        int row = m0 + wm*64 + ms*16 + lq;
#pragma unroll
        for (int ns = 0; ns < 4; ns++) {
            int col = n0 + wn*32 + ns*8 + lr*2;
            float b0 = bias[col], b1 = bias[col+1];
            *(float2*)(C + (long)row*ldC + col)     = make_float2(acc[ms][ns][0] + b0, acc[ms][ns][1] + b1);
            *(float2*)(C + (long)(row+8)*ldC + col) = make_float2(acc[ms][ns][2] + b0, acc[ms][ns][3] + b1);
        }
    }
}

// ---------------- uvec: stage 1 + stage 2 ----------------
__global__ void k_uvec_p(const float* __restrict__ attnW, const float* __restrict__ attnv,
                         const float* __restrict__ attnb, const float* __restrict__ attrW,
                         const float* __restrict__ attrv, const float* __restrict__ attrb) {
    __shared__ float red[4][64];
    int blk = blockIdx.x;
    int tid = threadIdx.x;
    if (blk < 416) {
        int hb = blk / 26, cb = blk - hb*26;
        int tx = tid & 63, hy = tid >> 6;
        int col = cb*64 + tx;
        const float* W; const float* v; int ld; int c;
        if (col < 2*HH) { W = attnW; v = attnv; ld = 2*HH;    c = col; }
        else            { W = attrW; v = attrv; ld = HH + KK; c = col - 2*HH; }
        int h0 = hb*32;
        float acc = 0.f;
#pragma unroll
        for (int t = 0; t < 8; t++) {
            int h = h0 + hy + t*4;
            acc += W[(long)h*ld + c] * v[h];
        }
        red[hy][tx] = acc;
        __syncthreads();
        if (hy == 0) g_upart[hb][col] = red[0][tx] + red[1][tx] + red[2][tx] + red[3][tx];
    } else {
        int w = tid >> 5, lane = tid & 31;
        if (w < 2) {
            const float* bp = w ? attrb : attnb;
            const float* vp = w ? attrv : attnv;
            float s = 0.f;
            for (int h = lane; h < HH; h += 32) s += bp[h]*vp[h];
#pragma unroll
            for (int o = 16; o > 0; o >>= 1) s += __shfl_xor_sync(0xffffffffu, s, o);
            if (lane == 0) g_bv[w] = s;
        }
    }
}

__global__ void k_uvec_r() {
    int i = blockIdx.x * blockDim.x + threadIdx.x;
    if (i >= UCOLS) return;
    float s = 0.f;
#pragma unroll
    for (int hb = 0; hb < 16; hb++) s += g_upart[hb][i];
    if (i < HH)            g_u1[i] = s;
    else if (i < 2*HH)     g_u1e[i - HH] = s;
    else if (i < 3*HH)     g_u3[i - 2*HH] = s;
    else                   g_u3e[i - 3*HH] = s;
}

// all scalar attention dot products
__global__ void k_ac(const float* __restrict__ enc1, const float* __restrict__ enc2,
                     const float* __restrict__ enc3) {
    int gw = (blockIdx.x * blockDim.x + threadIdx.x) >> 5;
    int lane = threadIdx.x & 31;
    const int E_A = M2, E_C1 = E_A + TT*BB, E_C2 = E_C1 + SS*BB, E_C3 = E_C2 + AA*BB;
    if (gw >= E_C3) return;
    if (gw < E_A) {
        const float4* x = (const float4*)(g_rnn + (long)gw*HH);
        const float4* u1 = (const float4*)g_u1;
        const float4* u3 = (const float4*)g_u3;
        float s1 = 0.f, s3 = 0.f;
#pragma unroll
        for (int k = lane; k < HH/4; k += 32) {
            float4 xv = x[k], a = u1[k], b = u3[k];
            s1 += xv.x*a.x + xv.y*a.y + xv.z*a.z + xv.w*a.w;
            s3 += xv.x*b.x + xv.y*b.y + xv.z*b.z + xv.w*b.w;
        }
#pragma unroll
        for (int o = 16; o > 0; o >>= 1) {
            s1 += __shfl_xor_sync(0xffffffffu, s1, o);
            s3 += __shfl_xor_sync(0xffffffffu, s3, o);
        }
        if (lane == 0) { g_a1[gw] = s1 + g_bv[0]; g_a3[gw] = s3 + g_bv[1]; }
        return;
    }
    const float* x; const float* u; float* dst; int len = HH;
    if (gw < E_C1)      { int m = gw - E_A;   x = enc1 + (long)m*HH; u = g_u1e; dst = g_c1 + m; }
    else if (gw < E_C2) { int m = gw - E_C1;  x = enc2 + (long)m*HH; u = g_u1e; dst = g_c2 + m; }
    else                { int m = gw - E_C2;  x = enc3 + (long)m*KK; u = g_u3e; dst = g_c3 + m; len = KK; }
    const float4* x4 = (const float4*)x;
    const float4* u4 = (const float4*)u;
    float s = 0.f;
    for (int k = lane; k < len/4; k += 32) {
        float4 xv = x4[k], uv = u4[k];
        s += xv.x*uv.x + xv.y*uv.y + xv.z*uv.z + xv.w*uv.w;
    }
#pragma unroll
    for (int o = 16; o > 0; o >>= 1) s += __shfl_xor_sync(0xffffffffu, s, o);
    if (lane == 0) *dst = s;
}

__global__ void k_softmax1(float* __restrict__ aw1) {
    int bn = blockIdx.x;
    int b = bn / NN, n = bn - b*NN;
    int t = threadIdx.x;
    float e  = tanhf(g_a1[n*BB + b] + g_c1[t*BB + b]);
    float ex = expf(e);
    __shared__ float red[8];
    __shared__ float stot;
    float s = ex;
#pragma unroll
    for (int o = 16; o > 0; o >>= 1) s += __shfl_xor_sync(0xffffffffu, s, o);
    if ((t & 31) == 0) red[t >> 5] = s;
    __syncthreads();
    if (t == 0) { float tt = 0.f; for (int i = 0; i < 8; i++) tt += red[i]; stot = tt; }
    __syncthreads();
    aw1[(long)bn*TT + t] = ex / stot;
}

__global__ void k_softmax2(float* __restrict__ aw2) {
    int gw = (blockIdx.x * blockDim.x + threadIdx.x) >> 5;
    if (gw >= BB*NN) return;
    int b = gw / NN, n = gw - b*NN;
    int s = threadIdx.x & 31;
    float e  = tanhf(g_a1[n*BB + b] + g_c2[s*BB + b]);
    float ex = expf(e);
    float tot = ex;
#pragma unroll
    for (int o = 16; o > 0; o >>= 1) tot += __shfl_xor_sync(0xffffffffu, tot, o);
    aw2[(long)gw*SS + s] = ex / tot;
}

__global__ void k_softmax3(float* __restrict__ aw3) {
    int bn = blockIdx.x * blockDim.x + threadIdx.x;
    if (bn >= BB*NN) return;
    int b = bn / NN, n = bn - b*NN;
    float ex[AA]; float tot = 0.f;
#pragma unroll
    for (int a = 0; a < AA; a++) {
        ex[a] = expf(tanhf(g_a3[n*BB + b] + g_c3[a*BB + b]));
        tot += ex[a];
    }
#pragma unroll
    for (int a = 0; a < AA; a++) aw3[(long)bn*AA + a] = ex[a] / tot;
}

// tiled ctx
__global__ void k_ctx_t(const float* __restrict__ aw, const float* __restrict__ enc,
                        float* __restrict__ dst, int L, int D) {
    int b  = blockIdx.x;
    int h0 = blockIdx.y * 64;
    int tid = threadIdx.x;
    __shared__ float AWs[64][33];
    __shared__ float Es[32][68];
    int tx = tid & 15, ty = tid >> 4;
    float acc[4][4] = {};
    for (int t0 = 0; t0 < L; t0 += 32) {
        {
            int row = tid >> 2, c0 = (tid & 3) * 8;
            const float* ap = aw + ((long)b*NN + row)*L + t0 + c0;
            float4 v0 = *(const float4*)ap;
            float4 v1 = *(const float4*)(ap + 4);
            AWs[row][c0+0]=v0.x; AWs[row][c0+1]=v0.y; AWs[row][c0+2]=v0.z; AWs[row][c0+3]=v0.w;
            AWs[row][c0+4]=v1.x; AWs[row][c0+5]=v1.y; AWs[row][c0+6]=v1.z; AWs[row][c0+7]=v1.w;
        }
        {
            int row = tid >> 3, c0 = (tid & 7) * 8;
            const float* ep = enc + (((long)(t0+row))*BB + b)*D + h0 + c0;
            float4 v0 = *(const float4*)ep;
            float4 v1 = *(const float4*)(ep + 4);
            Es[row][c0+0]=v0.x; Es[row][c0+1]=v0.y; Es[row][c0+2]=v0.z; Es[row][c0+3]=v0.w;
            Es[row][c0+4]=v1.x; Es[row][c0+5]=v1.y; Es[row][c0+6]=v1.z; Es[row][c0+7]=v1.w;
        }
        __syncthreads();
#pragma unroll
        for (int tt = 0; tt < 32; tt++) {
            float a[4], e[4];
#pragma unroll
            for (int i = 0; i < 4; i++) { a[i] = AWs[ty*4+i][tt]; e[i] = Es[tt][tx*4+i]; }
#pragma unroll
            for (int i = 0; i < 4; i++)
#pragma unroll
                for (int j = 0; j < 4; j++) acc[i][j] += a[i]*e[j];
        }
        __syncthreads();
    }
#pragma unroll
    for (int i = 0; i < 4; i++) {
        int n = ty*4 + i;
#pragma unroll
        for (int j = 0; j < 4; j++)
            dst[(((long)n)*BB + b)*D + h0 + tx*4 + j] = acc[i][j];
    }
}

// naive ctx (L=5, D=128)
__global__ void k_ctx(const float* __restrict__ aw, const float* __restrict__ enc,
                      float* __restrict__ dst, int L, int D) {
    int i = blockIdx.x * blockDim.x + threadIdx.x;
    if (i >= M2*KK) return;
    int m = i / D, h = i - m*D;
    int n = m / BB, b = m - n*BB;
    const float* awp = aw + ((long)b*NN + n)*L;
    float s = 0.f;
    for (int t = 0; t < L; t++) s += awp[t]*enc[((long)t*BB + b)*D + h];
    dst[i] = s;
}

__global__ void k_e4(const float* __restrict__ enc4, const float* __restrict__ projW,
                     const float* __restrict__ projb) {
    int i = blockIdx.x * blockDim.x + threadIdx.x;
    if (i >= BB*AN) return;
    int b = i / AN, j = i - b*AN;
    float s = projb[j];
    for (int k = 0; k < AN; k++) s += enc4[(0*BB + b)*AN + k]*projW[j*2*AN + k];
    for (int k = 0; k < AN; k++) s += enc4[(1*BB + b)*AN + k]*projW[j*2*AN + AN + k];
    g_e4[i] = s;
}

__global__ void k_gate2(const float* __restrict__ gateW, const float* __restrict__ gateb,
                        float* __restrict__ gateout) {
    int m0 = blockIdx.x * 4;
    int tid = threadIdx.x;
    __shared__ float xs[4][GIN + 12];
#pragma unroll
    for (int r = 0; r < 4; r++) {
        int m = m0 + r, b = m & 31;
        for (int k = tid; k < GIN; k += 256) {
            float v;
            if (k < HH)        v = g_emb[(long)m*HH + k];
            else if (k < 2*HH) v = g_rnn[(long)m*HH + k - HH];
            else               v = g_e4[b*AN + k - 2*HH];
            xs[r][k] = v;
        }
    }
    __syncthreads();
    int w = tid >> 5, lane = tid & 31;
    for (int o = w; o < 4*AN; o += 8) {
        int r = o & 3, j = o >> 2;
        const float* wj = gateW + (long)j*GIN;
        float s = 0.f;
        for (int k = lane; k < GIN; k += 32) s += xs[r][k]*wj[k];
#pragma unroll
        for (int of = 16; of > 0; of >>= 1) s += __shfl_xor_sync(0xffffffffu, s, of);
        if (lane == 0) gateout[(long)(m0+r)*AN + j] = tanhf(s + gateb[j]);
    }
}

__global__ void k_chain(const int* __restrict__ ids) {
    __shared__ int sid[NASP];
    int tid = threadIdx.x;
    int j = blockIdx.x * 256 + tid;
    for (int k = tid; k < NASP; k += 256) sid[k] = ids[k];
    __syncthreads();
    if (j >= NASP) return;
    int v = sid[j];
    int fst = 1, nxt = -1;
    for (int j2 = 0; j2 < NASP; j2++) {
        int w = sid[j2];
        if (w == v) {
            if (j2 < j) fst = 0;
            else if (j2 > j && nxt < 0) nxt = j2;
        }
    }
    g_first[j] = fst;
    g_next[j]  = nxt;
}

__global__ void k_scatter(const float* __restrict__ gate, const int* __restrict__ ids,
                          float* __restrict__ out0) {
    long i = (long)blockIdx.x * blockDim.x + threadIdx.x;
    if (i >= (long)M2*NASP) return;
    int m = (int)(i / NASP);
    int j = (int)(i - (long)m*NASP);
    if (!g_first[j]) return;
    float s = 0.f;
    int jj = j;
    while (jj >= 0) { s += gate[(long)m*AN + (jj % AN)]; jj = g_next[jj]; }
    out0[(long)m*VV + ids[j]] += s;
}

// ---------------- launcher ----------------
extern "C" void kernel_launch(void* const* d_in, const int* in_sizes, int n_in,
                              void* d_out, int out_size) {
    const int*   seq   = (const int*)  d_in[0];
    const float* lasth = (const float*)d_in[1];
    const float* enc1  = (const float*)d_in[2];
    const float* enc2  = (const float*)d_in[3];
    const float* enc3  = (const float*)d_in[4];
    const float* enc4  = (const float*)d_in[5];
    const int*   asp   = (const int*)  d_in[6];
    const float* emb   = (const float*)d_in[7];
    const float* Wih   = (const float*)d_in[8];
    const float* Whh   = (const float*)d_in[9];
    const float* bih   = (const float*)d_in[10];
    const float* bhh   = (const float*)d_in[11];
    const float* attnW = (const float*)d_in[12];
    const float* attnb = (const float*)d_in[13];
    const float* attnv = (const float*)d_in[14];
    const float* attrW = (const float*)d_in[15];
    const float* attrb = (const float*)d_in[16];
    const float* attrv = (const float*)d_in[17];
    const float* concW = (const float*)d_in[18];
    const float* concb = (const float*)d_in[19];
    const float* outW  = (const float*)d_in[20];
    const float* outb  = (const float*)d_in[21];
    const float* gateW = (const float*)d_in[22];
    const float* gateb = (const float*)d_in[23];
    const float* projW = (const float*)d_in[24];
    const float* projb = (const float*)d_in[25];
    float* out = (float*)d_out;

    const long O_HID  = (long)M2*VV;
    const long O_AW1  = O_HID + (long)BB*HH;
    const long O_AW2  = O_AW1 + (long)BB*NN*TT;
    const long O_AW3  = O_AW2 + (long)BB*NN*SS;
    const long O_GATE = O_AW3 + (long)BB*NN*AA;

    float *p_emb, *p_gi, *p_cout, *p_ctx1, *p_ctx2, *p_ctx3;
    uint32_t *p_wt, *p_at;
    cudaGetSymbolAddress((void**)&p_emb,  g_emb);
    cudaGetSymbolAddress((void**)&p_gi,   g_gi);
    cudaGetSymbolAddress((void**)&p_cout, g_cout);
    cudaGetSymbolAddress((void**)&p_ctx1, g_ctx1);
    cudaGetSymbolAddress((void**)&p_ctx2, g_ctx2);
    cudaGetSymbolAddress((void**)&p_ctx3, g_ctx3);
    cudaGetSymbolAddress((void**)&p_wt,   g_wt);
    cudaGetSymbolAddress((void**)&p_at,   g_at);

    // 0) W pre-round + fragment pack (depends only on outW)
    k_pack_w<<<(int)(((long)(VV/128)*64*8*32 + 255)/256), 256>>>(outW);

    // 1) embedding
    k_embed<<<(M2*HH + 255)/256, 256>>>(seq, emb);

    // 2) gi = embedded @ Wih^T + bih (split-tf32, fp32-accurate)
    k_gemm_tf32s<<<dim3((3*HH)/128, M2/128), 256>>>(p_emb, Wih, bih, p_gi, HH, 3*HH);

    // 3) persistent GRU
    k_gru_all<<<GRU_BLOCKS, 256>>>(lasth, Whh, bhh, out + O_HID);

    // 4) attention vectors + scalar dots
    k_uvec_p<<<417, 256>>>(attnW, attnv, attnb, attrW, attrv, attrb);
    k_uvec_r<<<(UCOLS + 255)/256, 256>>>();
    {
        int warps = M2 + TT*BB + SS*BB + AA*BB;
        k_ac<<<(warps*32 + 255)/256, 256>>>(enc1, enc2, enc3);
    }

    // 5) softmaxes
    k_softmax1<<<BB*NN, TT>>>(out + O_AW1);
    k_softmax2<<<(BB*NN*32 + 255)/256, 256>>>(out + O_AW2);
    k_softmax3<<<(BB*NN + 255)/256, 256>>>(out + O_AW3);

    // 6) contexts
    k_ctx_t<<<dim3(BB, HH/64), 256>>>(out + O_AW1, enc1, p_ctx1, TT, HH);
    k_ctx_t<<<dim3(BB, HH/64), 256>>>(out + O_AW2, enc2, p_ctx2, SS, HH);
    k_ctx  <<<(M2*KK + 255)/256, 256>>>(out + O_AW3, enc3, p_ctx3, AA, KK);

    // 7) concat GEMM (tf32) -> A pack -> packed tf32 big GEMM
    k_gemm_tf32<1><<<dim3(HH/128, M2/128), 128>>>(nullptr, concW, concb, p_cout, CIN, HH, 1);
    k_pack_a<<<(int)(((long)(M2/128)*64*8*32 + 255)/256), 256>>>(p_cout);
    k_gemm_tf32p<<<dim3(M2/128, VV/128), 128>>>((const uint4*)p_at, (const uint4*)p_wt, outb, out);

    // 8) gate path
    k_e4<<<(BB*AN + 255)/256, 256>>>(enc4, projW, projb);
    k_gate2<<<M2/4, 256>>>(gateW, gateb, out + O_GATE);

    // 9) deterministic scatter-add
    k_chain<<<(NASP + 255)/256, 256>>>(asp);
    k_scatter<<<(int)(((long)M2*NASP + 255)/256), 256>>>(out + O_GATE, asp, out);
}

// round 9
// speedup vs baseline: 3.4913x; 1.1138x over previous
#include <cuda_runtime.h>
#include <cuda_bf16.h>
#include <math.h>
#include <stdint.h>

#define NN 64
#define BB 32
#define HH 512
#define KK 128
#define VV 32000
#define TT 256
#define SS 32
#define AA 5
#define AN 20
#define M2 (NN*BB)          // 2048 rows
#define CIN (3*HH+KK)       // 1664
#define GIN (2*HH+AN)       // 1044
#define NASP 2000
#define GRU_BLOCKS 128
#define UCOLS (2*HH + HH + KK)   // 1664 projected columns

// ---------------- scratch (static device globals; no runtime alloc) ----------------
__device__ __align__(16) float g_emb[M2*HH];
__device__ __align__(16) float g_gi[M2*3*HH];
__device__ __align__(16) float g_hA[HH*BB];
__device__ __align__(16) float g_hB[HH*BB];
__device__ __align__(16) float g_rnn[M2*HH];
__device__ __align__(16) float g_u1[HH];
__device__ __align__(16) float g_u1e[HH];
__device__ __align__(16) float g_u3[HH];
__device__ __align__(16) float g_u3e[KK];
__device__ float g_bv[2];
__device__ __align__(16) float g_upart[16][UCOLS];
__device__ float g_a1[M2], g_a3[M2];
__device__ float g_c1[TT*BB], g_c2[SS*BB], g_c3[AA*BB];
__device__ __align__(16) float g_ctx1[M2*HH];
__device__ __align__(16) float g_ctx2[M2*HH];
__device__ __align__(16) float g_ctx3[M2*KK];
__device__ __align__(16) float g_cout[M2*HH];
__device__ __align__(16) uint32_t g_wt[VV*HH];      // 65.5 MB pre-rounded, fragment-packed W
__device__ __align__(16) uint32_t g_at[M2*HH];      // 4 MB fragment-packed A
__device__ float g_e4[BB*AN];
__device__ int g_first[NASP], g_next[NASP];
__device__ unsigned g_barcnt = 0;
__device__ unsigned g_bargen = 0;

// ---------------- grid barrier (release/acquire) ----------------
__device__ __forceinline__ void grid_barrier(unsigned nb) {
    __syncthreads();
    if (threadIdx.x == 0) {
        unsigned gen;
        asm volatile("ld.relaxed.gpu.global.u32 %0, [%1];" : "=r"(gen) : "l"(&g_bargen));
        unsigned prev;
        asm volatile("atom.release.gpu.global.add.u32 %0, [%1], 1;" : "=r"(prev) : "l"(&g_barcnt));
        if (prev == nb - 1u) {
            asm volatile("st.relaxed.gpu.global.u32 [%0], %1;" :: "l"(&g_barcnt), "r"(0u));
            unsigned d;
            asm volatile("atom.release.gpu.global.add.u32 %0, [%1], 1;" : "=r"(d) : "l"(&g_bargen));
        } else {
            unsigned cur;
            do {
                __nanosleep(20);
                asm volatile("ld.acquire.gpu.global.u32 %0, [%1];" : "=r"(cur) : "l"(&g_bargen));
            } while (cur == gen);
        }
    }
    __syncthreads();
}

// ---------------- helpers ----------------
__device__ __forceinline__ uint32_t smem_u32(const void* p) {
    uint32_t a;
    asm("{ .reg .u64 t; cvta.to.shared.u64 t, %1; cvt.u32.u64 %0, t; }" : "=r"(a) : "l"(p));
    return a;
}
__device__ __forceinline__ uint32_t f2tf(float x) {
    uint32_t u; asm("cvt.rna.tf32.f32 %0, %1;" : "=r"(u) : "f"(x)); return u;
}
__device__ __forceinline__ void split_tf32(float x, uint32_t& hi, uint32_t& lo) {
    hi = f2tf(x);
    float r = x - __uint_as_float(hi);
    lo = f2tf(r);
}
__device__ __forceinline__ void mma_tf32(float& c0, float& c1, float& c2, float& c3,
                                         uint32_t a0, uint32_t a1, uint32_t a2, uint32_t a3,
                                         uint32_t b0, uint32_t b1) {
    asm volatile("mma.sync.aligned.m16n8k8.row.col.f32.tf32.tf32.f32 "
                 "{%0,%1,%2,%3},{%4,%5,%6,%7},{%8,%9},{%0,%1,%2,%3};"
                 : "+f"(c0), "+f"(c1), "+f"(c2), "+f"(c3)
                 : "r"(a0), "r"(a1), "r"(a2), "r"(a3), "r"(b0), "r"(b1));
}
__device__ __forceinline__ void cpa16(uint32_t saddr, const void* gaddr) {
    asm volatile("cp.async.cg.shared.global [%0], [%1], 16;" :: "r"(saddr), "l"(gaddr));
}

// ---------------- kernels ----------------

__global__ void k_embed(const int* __restrict__ seq, const float* __restrict__ emb) {
    int i = blockIdx.x * blockDim.x + threadIdx.x;
    if (i < M2*HH) {
        int m = i / HH, h = i - m*HH;
        g_emb[i] = emb[(long)seq[m]*HH + h];
    }
}

// ---- fragment packing for the big GEMM ----
__global__ void k_pack_w(const float* __restrict__ W) {
    long i = (long)blockIdx.x * 256 + threadIdx.x;
    if (i >= (long)(VV/128)*64*8*32) return;
    int lane = (int)(i & 31), fp = (int)((i >> 5) & 7), s = (int)((i >> 8) & 63);
    long nb = i >> 14;
    int lq = lane >> 2, lr = lane & 3;
    int k = s*8 + lr;
    long ne = nb*128 + fp*16 + lq;
    uint4 v;
    v.x = f2tf(W[ne*HH + k]);
    v.y = f2tf(W[ne*HH + k + 4]);
    v.z = f2tf(W[(ne+8)*HH + k]);
    v.w = f2tf(W[(ne+8)*HH + k + 4]);
    ((uint4*)g_wt)[i] = v;
}

__global__ void k_pack_a(const float* __restrict__ A) {
    long i = (long)blockIdx.x * 256 + threadIdx.x;
    if (i >= (long)(M2/128)*64*8*32) return;
    int lane = (int)(i & 31), mf = (int)((i >> 5) & 7), s = (int)((i >> 8) & 63);
    long mb = i >> 14;
    int lq = lane >> 2, lr = lane & 3;
    int k = s*8 + lr;
    long me = mb*128 + mf*16 + lq;
    uint4 v;
    v.x = f2tf(A[me*HH + k]);
    v.y = f2tf(A[(me+8)*HH + k]);
    v.z = f2tf(A[me*HH + k + 4]);
    v.w = f2tf(A[(me+8)*HH + k + 4]);
    ((uint4*)g_at)[i] = v;
}

// ---------------- packed tf32 GEMM: C[M2,VV] = A[M2,HH] * W[VV,HH]^T + bias ----------------
__global__ __launch_bounds__(128, 2)
void k_gemm_tf32p(const uint4* __restrict__ At, const uint4* __restrict__ Wt,
                  const float* __restrict__ bias, float* __restrict__ C) {
    __shared__ __align__(16) uint4 As[2][512];
    __shared__ __align__(16) uint4 Bs[2][512];
    int tid = threadIdx.x;
    int warp = tid >> 5, lane = tid & 31;
    int wm = warp & 1, wnp = warp >> 1;
    int lq = lane >> 2, lr = lane & 3;
    int m0 = blockIdx.x * 128, n0 = blockIdx.y * 128;
    const uint4* Ab = At + (long)blockIdx.x * 16384;
    const uint4* Bb = Wt + (long)blockIdx.y * 16384;

    float acc[4][8][4];
#pragma unroll
    for (int i = 0; i < 4; i++)
#pragma unroll
        for (int j = 0; j < 8; j++)
#pragma unroll
            for (int c = 0; c < 4; c++) acc[i][j][c] = 0.f;

#pragma unroll
    for (int i = 0; i < 4; i++) {
        cpa16(smem_u32(&As[0][i*128 + tid]), Ab + i*128 + tid);
        cpa16(smem_u32(&Bs[0][i*128 + tid]), Bb + i*128 + tid);
    }
    asm volatile("cp.async.commit_group;");

    int buf = 0;
    const int NK = HH / 16;    // 32 k16 tiles
    for (int c = 0; c < NK; c++) {
        asm volatile("cp.async.wait_group 0;" ::: "memory");
        __syncthreads();
        if (c + 1 < NK) {
            const uint4* an = Ab + (c+1)*512;
            const uint4* bn = Bb + (c+1)*512;
#pragma unroll
            for (int i = 0; i < 4; i++) {
                cpa16(smem_u32(&As[buf^1][i*128 + tid]), an + i*128 + tid);
                cpa16(smem_u32(&Bs[buf^1][i*128 + tid]), bn + i*128 + tid);
            }
            asm volatile("cp.async.commit_group;");
        }
#pragma unroll
        for (int kk = 0; kk < 2; kk++) {
            uint4 av[4], bv[4];
#pragma unroll
            for (int ms = 0; ms < 4; ms++)
                av[ms] = As[buf][kk*256 + (wm*4 + ms)*32 + lane];
#pragma unroll
            for (int p = 0; p < 4; p++)
                bv[p] = Bs[buf][kk*256 + (wnp*4 + p)*32 + lane];
#pragma unroll
            for (int ms = 0; ms < 4; ms++)
#pragma unroll
                for (int p = 0; p < 4; p++) {
                    mma_tf32(acc[ms][2*p][0], acc[ms][2*p][1], acc[ms][2*p][2], acc[ms][2*p][3],
                             av[ms].x, av[ms].y, av[ms].z, av[ms].w, bv[p].x, bv[p].y);
                    mma_tf32(acc[ms][2*p+1][0], acc[ms][2*p+1][1], acc[ms][2*p+1][2], acc[ms][2*p+1][3],
                             av[ms].x, av[ms].y, av[ms].z, av[ms].w, bv[p].z, bv[p].w);
                }
        }
        buf ^= 1;
    }
#pragma unroll
    for (int ms = 0; ms < 4; ms++) {
        int row = m0 + wm*64 + ms*16 + lq;
#pragma unroll
        for (int ns = 0; ns < 8; ns++) {
            int col = n0 + wnp*64 + ns*8 + lr*2;
            float b0 = bias[col], b1 = bias[col+1];
            *(float2*)(C + (long)row*VV + col)     = make_float2(acc[ms][ns][0] + b0, acc[ms][ns][1] + b1);
            *(float2*)(C + (long)(row+8)*VV + col) = make_float2(acc[ms][ns][2] + b0, acc[ms][ns][3] + b1);
        }
    }
}

// ---------------- persistent GRU (smem-staged h) ----------------
// dyn smem: [0..6144) sw floats, [6144..22528) sh (h matrix 512x32),
//           [22528..22912) part, [22912..22924) sbias
__global__ __launch_bounds__(256, 1)
void k_gru_all(const float* __restrict__ lasth, const float* __restrict__ Whh,
               const float* __restrict__ bhh, float* __restrict__ hid) {
    extern __shared__ __align__(16) float dsm[];
    float* sw   = dsm;                 // [3][4][512]
    float* sh   = dsm + 6144;          // [512*32] = 64KB
    float* part = dsm + 6144 + 16384;  // [3][128]
    float* sbv  = part + 384;          // [3][4]

    int tid = threadIdx.x, bk = blockIdx.x;
    int jl = (tid >> 5) & 3, b = tid & 31, kh = tid >> 7;
    int jg = bk*4 + jl;

    for (int r = 0; r < 12; r++) {
        int g = r / 4, j = r % 4;
        int rowi = g*HH + bk*4 + j;
        for (int k = tid; k < HH; k += 256) sw[(g*4 + j)*HH + k] = Whh[(long)rowi*HH + k];
    }
    if (tid < 12) sbv[tid] = bhh[(tid/4)*HH + bk*4 + (tid%4)];

    if (tid < 128) {
        int idx = bk*128 + tid;
        int k = idx >> 5, bb = idx & 31;
        __stcg(&g_hA[idx], lasth[bb*HH + k]);
    }
    grid_barrier(GRU_BLOCKS);

    float* hp = g_hA;
    float* hc = g_hB;
    const float* wr = sw + (0*4 + jl)*HH;
    const float* wz = sw + (1*4 + jl)*HH;
    const float* wn = sw + (2*4 + jl)*HH;
    int k0 = kh * 256;

    for (int n = 0; n < NN; n++) {
        // stage full h (16K floats) into smem with high-MLP coalesced loads
#pragma unroll
        for (int i = 0; i < 16; i++) {
            int f = tid + i*256;                  // float4 index 0..4095
            float4 v = __ldcg((const float4*)hp + f);
            *(float4*)(sh + 4*f) = v;
        }
        __syncthreads();

        float sr = 0.f, sz = 0.f, sn = 0.f;
#pragma unroll 8
        for (int k = k0; k < k0 + 256; k += 4) {
            float4 r4 = *(const float4*)(wr + k);
            float4 z4 = *(const float4*)(wz + k);
            float4 n4 = *(const float4*)(wn + k);
            float h0 = sh[(k+0)*BB + b];
            float h1 = sh[(k+1)*BB + b];
            float h2 = sh[(k+2)*BB + b];
            float h3 = sh[(k+3)*BB + b];
            sr += r4.x*h0 + r4.y*h1 + r4.z*h2 + r4.w*h3;
            sz += z4.x*h0 + z4.y*h1 + z4.z*h2 + z4.w*h3;
            sn += n4.x*h0 + n4.y*h1 + n4.z*h2 + n4.w*h3;
        }
        if (kh == 1) {
            part[0*128 + jl*32 + b] = sr;
            part[1*128 + jl*32 + b] = sz;
            part[2*128 + jl*32 + b] = sn;
        }
        __syncthreads();
        if (kh == 0) {
            sr += part[0*128 + jl*32 + b];
            sz += part[1*128 + jl*32 + b];
            sn += part[2*128 + jl*32 + b];
            float hold = sh[jg*BB + b];
            const float* gi = g_gi + ((long)(n*BB + b))*(3*HH);
            float rr = 1.f/(1.f + expf(-(gi[jg]        + sr + sbv[0*4 + jl])));
            float zz = 1.f/(1.f + expf(-(gi[HH + jg]   + sz + sbv[1*4 + jl])));
            float nn = tanhf(gi[2*HH + jg] + rr*(sn + sbv[2*4 + jl]));
            float hn = (1.f - zz)*nn + zz*hold;
            __stcg(hc + jg*BB + b, hn);
            g_rnn[((long)(n*BB + b))*HH + jg] = hn;
            if (n == NN-1) hid[b*HH + jg] = hn;
        }
        grid_barrier(GRU_BLOCKS);
        float* t = hp; hp = hc; hc = t;
    }
}

// ---------------- tf32 mma GEMM (concat path, cvt at use) ----------------
__device__ __forceinline__ const float* concat_src(int m, int k) {
    if (k < HH)        return g_rnn  + (long)m*HH + k;
    if (k < 2*HH)      return g_ctx1 + (long)m*HH + (k - HH);
    if (k < 3*HH)      return g_ctx2 + (long)m*HH + (k - 2*HH);
    return g_ctx3 + (long)m*KK + (k - 3*HH);
}

template<int ASRC>
__global__ __launch_bounds__(128, 2)
void k_gemm_tf32(const float* __restrict__ A, const float* __restrict__ W,
                 const float* __restrict__ bias, float* __restrict__ C,
                 int Kd, int ldC, int act) {
    __shared__ __align__(16) float As[2][128][20];
    __shared__ __align__(16) float Bs[2][128][20];
    int tid = threadIdx.x;
    int warp = tid >> 5, lane = tid & 31;
    int wm = warp & 1, wnp = warp >> 1;
    int lq = lane >> 2, lr = lane & 3;
    int m0 = blockIdx.y * 128, n0 = blockIdx.x * 128;

    float acc[4][8][4];
#pragma unroll
    for (int i = 0; i < 4; i++)
#pragma unroll
        for (int j = 0; j < 8; j++)
#pragma unroll
            for (int c = 0; c < 4; c++) acc[i][j][c] = 0.f;

    const int NK = Kd / 16;
#pragma unroll
    for (int i = 0; i < 4; i++) {
        int idx = i*128 + tid, row = idx >> 2, kc = idx & 3;
        const float* asrc = ASRC ? concat_src(m0+row, kc*4)
                                 : A + (long)(m0+row)*Kd + kc*4;
        cpa16(smem_u32(&As[0][row][kc*4]), asrc);
        cpa16(smem_u32(&Bs[0][row][kc*4]), W + (long)(n0+row)*Kd + kc*4);
    }
    asm volatile("cp.async.commit_group;");

    int buf = 0;
    for (int ks = 0; ks < NK; ks++) {
        asm volatile("cp.async.wait_group 0;");
        __syncthreads();
        if (ks + 1 < NK) {
#pragma unroll
            for (int i = 0; i < 4; i++) {
                int idx = i*128 + tid, row = idx >> 2, kc = idx & 3;
                int kpos = (ks+1)*16 + kc*4;
                const float* asrc = ASRC ? concat_src(m0+row, kpos)
                                         : A + (long)(m0+row)*Kd + kpos;
                cpa16(smem_u32(&As[buf^1][row][kc*4]), asrc);
                cpa16(smem_u32(&Bs[buf^1][row][kc*4]), W + (long)(n0+row)*Kd + kpos);
            }
            asm volatile("cp.async.commit_group;");
        }
#pragma unroll
        for (int kk = 0; kk < 16; kk += 8) {
            uint32_t af[4][4], bf[8][2];
#pragma unroll
            for (int ms = 0; ms < 4; ms++) {
                int rb = wm*64 + ms*16;
                af[ms][0] = f2tf(As[buf][rb + lq    ][kk + lr    ]);
                af[ms][1] = f2tf(As[buf][rb + lq + 8][kk + lr    ]);
                af[ms][2] = f2tf(As[buf][rb + lq    ][kk + lr + 4]);
                af[ms][3] = f2tf(As[buf][rb + lq + 8][kk + lr + 4]);
            }
#pragma unroll
            for (int ns = 0; ns < 8; ns++) {
                int nb = wnp*64 + ns*8;
                bf[ns][0] = f2tf(Bs[buf][nb + lq][kk + lr    ]);
                bf[ns][1] = f2tf(Bs[buf][nb + lq][kk + lr + 4]);
            }
#pragma unroll
            for (int ms = 0; ms < 4; ms++)
#pragma unroll
                for (int ns = 0; ns < 8; ns++)
                    mma_tf32(acc[ms][ns][0], acc[ms][ns][1], acc[ms][ns][2], acc[ms][ns][3],
                             af[ms][0], af[ms][1], af[ms][2], af[ms][3],
                             bf[ns][0], bf[ns][1]);
        }
        buf ^= 1;
    }
#pragma unroll
    for (int ms = 0; ms < 4; ms++) {
        int row = m0 + wm*64 + ms*16 + lq;
#pragma unroll
        for (int ns = 0; ns < 8; ns++) {
            int col = n0 + wnp*64 + ns*8 + lr*2;
            float b0 = bias[col], b1 = bias[col+1];
            float v00 = acc[ms][ns][0] + b0, v01 = acc[ms][ns][1] + b1;
            float v10 = acc[ms][ns][2] + b0, v11 = acc[ms][ns][3] + b1;
            if (act) { v00 = tanhf(v00); v01 = tanhf(v01); v10 = tanhf(v10); v11 = tanhf(v11); }
            *(float2*)(C + (long)row*ldC + col)     = make_float2(v00, v01);
            *(float2*)(C + (long)(row+8)*ldC + col) = make_float2(v10, v11);
        }
    }
}

// split-precision tf32 GEMM (fp32-accurate) for gi
__global__ __launch_bounds__(256)
void k_gemm_tf32s(const float* __restrict__ A, const float* __restrict__ W,
                  const float* __restrict__ bias, float* __restrict__ C,
                  int Kd, int ldC) {
    __shared__ __align__(16) float As[2][128][20];
    __shared__ __align__(16) float Bs[2][128][20];
    int tid = threadIdx.x;
    int warp = tid >> 5, lane = tid & 31;
    int wm = warp & 1, wn = warp >> 1;
    int lq = lane >> 2, lr = lane & 3;
    int m0 = blockIdx.y * 128, n0 = blockIdx.x * 128;

    float acc[4][4][4];
#pragma unroll
    for (int i = 0; i < 4; i++)
#pragma unroll
        for (int j = 0; j < 4; j++)
#pragma unroll
            for (int c = 0; c < 4; c++) acc[i][j][c] = 0.f;

    const int NK = Kd / 16;
#pragma unroll
    for (int i = 0; i < 2; i++) {
        int idx = i*256 + tid, row = idx >> 2, kc = idx & 3;
        cpa16(smem_u32(&As[0][row][kc*4]), A + (long)(m0+row)*Kd + kc*4);
        cpa16(smem_u32(&Bs[0][row][kc*4]), W + (long)(n0+row)*Kd + kc*4);
    }
    asm volatile("cp.async.commit_group;");

    int buf = 0;
    for (int ks = 0; ks < NK; ks++) {
        asm volatile("cp.async.wait_group 0;");
        __syncthreads();
        if (ks + 1 < NK) {
#pragma unroll
            for (int i = 0; i < 2; i++) {
                int idx = i*256 + tid, row = idx >> 2, kc = idx & 3;
                int kpos = (ks+1)*16 + kc*4;
                cpa16(smem_u32(&As[buf^1][row][kc*4]), A + (long)(m0+row)*Kd + kpos);
                cpa16(smem_u32(&Bs[buf^1][row][kc*4]), W + (long)(n0+row)*Kd + kpos);
            }
            asm volatile("cp.async.commit_group;");
        }
#pragma unroll
        for (int kk = 0; kk < 16; kk += 8) {
            uint32_t ah[4][4], al[4][4], bh[4][2], bl[4][2];
#pragma unroll
            for (int ms = 0; ms < 4; ms++) {
                int rb = wm*64 + ms*16;
                split_tf32(As[buf][rb + lq    ][kk + lr    ], ah[ms][0], al[ms][0]);
                split_tf32(As[buf][rb + lq + 8][kk + lr    ], ah[ms][1], al[ms][1]);
                split_tf32(As[buf][rb + lq    ][kk + lr + 4], ah[ms][2], al[ms][2]);
                split_tf32(As[buf][rb + lq + 8][kk + lr + 4], ah[ms][3], al[ms][3]);
            }
#pragma unroll
            for (int ns = 0; ns < 4; ns++) {
                int nb = wn*32 + ns*8;
                split_tf32(Bs[buf][nb + lq][kk + lr    ], bh[ns][0], bl[ns][0]);
                split_tf32(Bs[buf][nb + lq][kk + lr + 4], bh[ns][1], bl[ns][1]);
            }
#pragma unroll
            for (int ms = 0; ms < 4; ms++)
#pragma unroll
                for (int ns = 0; ns < 4; ns++) {
                    mma_tf32(acc[ms][ns][0], acc[ms][ns][1], acc[ms][ns][2], acc[ms][ns][3],
                             ah[ms][0], ah[ms][1], ah[ms][2], ah[ms][3], bh[ns][0], bh[ns][1]);
                    mma_tf32(acc[ms][ns][0], acc[ms][ns][1], acc[ms][ns][2], acc[ms][ns][3],
                             ah[ms][0], ah[ms][1], ah[ms][2], ah[ms][3], bl[ns][0], bl[ns][1]);
                    mma_tf32(acc[ms][ns][0], acc[ms][ns][1], acc[ms][ns][2], acc[ms][ns][3],
                             al[ms][0], al[ms][1], al[ms][2], al[ms][3], bh[ns][0], bh[ns][1]);
                }
        }
        buf ^= 1;
    }
#pragma unroll
    for (int ms = 0; ms < 4; ms++) {
        int row = m0 + wm*64 + ms*16 + lq;
#pragma unroll
        for (int ns = 0; ns < 4; ns++) {
            int col = n0 + wn*32 + ns*8 + lr*2;
            float b0 = bias[col], b1 = bias[col+1];
            *(float2*)(C + (long)row*ldC + col)     = make_float2(acc[ms][ns][0] + b0, acc[ms][ns][1] + b1);
            *(float2*)(C + (long)(row+8)*ldC + col) = make_float2(acc[ms][ns][2] + b0, acc[ms][ns][3] + b1);
        }
    }
}

// ---------------- uvec: stage 1 + stage 2 ----------------
__global__ void k_uvec_p(const float* __restrict__ attnW, const float* __restrict__ attnv,
                         const float* __restrict__ attnb, const float* __restrict__ attrW,
                         const float* __restrict__ attrv, const float* __restrict__ attrb) {
    __shared__ float red[4][64];
    int blk = blockIdx.x;
    int tid = threadIdx.x;
    if (blk < 416) {
        int hb = blk / 26, cb = blk - hb*26;
        int tx = tid & 63, hy = tid >> 6;
        int col = cb*64 + tx;
        const float* W; const float* v; int ld; int c;
        if (col < 2*HH) { W = attnW; v = attnv; ld = 2*HH;    c = col; }
        else            { W = attrW; v = attrv; ld = HH + KK; c = col - 2*HH; }
        int h0 = hb*32;
        float acc = 0.f;
#pragma unroll
        for (int t = 0; t < 8; t++) {
            int h = h0 + hy + t*4;
            acc += W[(long)h*ld + c] * v[h];
        }
        red[hy][tx] = acc;
        __syncthreads();
        if (hy == 0) g_upart[hb][col] = red[0][tx] + red[1][tx] + red[2][tx] + red[3][tx];
    } else {
        int w = tid >> 5, lane = tid & 31;
        if (w < 2) {
            const float* bp = w ? attrb : attnb;
            const float* vp = w ? attrv : attnv;
            float s = 0.f;
            for (int h = lane; h < HH; h += 32) s += bp[h]*vp[h];
#pragma unroll
            for (int o = 16; o > 0; o >>= 1) s += __shfl_xor_sync(0xffffffffu, s, o);
            if (lane == 0) g_bv[w] = s;
        }
    }
}

__global__ void k_uvec_r() {
    int i = blockIdx.x * blockDim.x + threadIdx.x;
    if (i >= UCOLS) return;
    float s = 0.f;
#pragma unroll
    for (int hb = 0; hb < 16; hb++) s += g_upart[hb][i];
    if (i < HH)            g_u1[i] = s;
    else if (i < 2*HH)     g_u1e[i - HH] = s;
    else if (i < 3*HH)     g_u3[i - 2*HH] = s;
    else                   g_u3e[i - 3*HH] = s;
}

// all scalar attention dot products
__global__ void k_ac(const float* __restrict__ enc1, const float* __restrict__ enc2,
                     const float* __restrict__ enc3) {
    int gw = (blockIdx.x * blockDim.x + threadIdx.x) >> 5;
    int lane = threadIdx.x & 31;
    const int E_A = M2, E_C1 = E_A + TT*BB, E_C2 = E_C1 + SS*BB, E_C3 = E_C2 + AA*BB;
    if (gw >= E_C3) return;
    if (gw < E_A) {
        const float4* x = (const float4*)(g_rnn + (long)gw*HH);
        const float4* u1 = (const float4*)g_u1;
        const float4* u3 = (const float4*)g_u3;
        float s1 = 0.f, s3 = 0.f;
#pragma unroll
        for (int k = lane; k < HH/4; k += 32) {
            float4 xv = x[k], a = u1[k], b = u3[k];
            s1 += xv.x*a.x + xv.y*a.y + xv.z*a.z + xv.w*a.w;
            s3 += xv.x*b.x + xv.y*b.y + xv.z*b.z + xv.w*b.w;
        }
#pragma unroll
        for (int o = 16; o > 0; o >>= 1) {
            s1 += __shfl_xor_sync(0xffffffffu, s1, o);
            s3 += __shfl_xor_sync(0xffffffffu, s3, o);
        }
        if (lane == 0) { g_a1[gw] = s1 + g_bv[0]; g_a3[gw] = s3 + g_bv[1]; }
        return;
    }
    const float* x; const float* u; float* dst; int len = HH;
    if (gw < E_C1)      { int m = gw - E_A;   x = enc1 + (long)m*HH; u = g_u1e; dst = g_c1 + m; }
    else if (gw < E_C2) { int m = gw - E_C1;  x = enc2 + (long)m*HH; u = g_u1e; dst = g_c2 + m; }
    else                { int m = gw - E_C2;  x = enc3 + (long)m*KK; u = g_u3e; dst = g_c3 + m; len = KK; }
    const float4* x4 = (const float4*)x;
    const float4* u4 = (const float4*)u;
    float s = 0.f;
    for (int k = lane; k < len/4; k += 32) {
        float4 xv = x4[k], uv = u4[k];
        s += xv.x*uv.x + xv.y*uv.y + xv.z*uv.z + xv.w*uv.w;
    }
#pragma unroll
    for (int o = 16; o > 0; o >>= 1) s += __shfl_xor_sync(0xffffffffu, s, o);
    if (lane == 0) *dst = s;
}

__global__ void k_softmax1(float* __restrict__ aw1) {
    int bn = blockIdx.x;
    int b = bn / NN, n = bn - b*NN;
    int t = threadIdx.x;
    float e  = tanhf(g_a1[n*BB + b] + g_c1[t*BB + b]);
    float ex = expf(e);
    __shared__ float red[8];
    __shared__ float stot;
    float s = ex;
#pragma unroll
    for (int o = 16; o > 0; o >>= 1) s += __shfl_xor_sync(0xffffffffu, s, o);
    if ((t & 31) == 0) red[t >> 5] = s;
    __syncthreads();
    if (t == 0) { float tt = 0.f; for (int i = 0; i < 8; i++) tt += red[i]; stot = tt; }
    __syncthreads();
    aw1[(long)bn*TT + t] = ex / stot;
}

__global__ void k_softmax2(float* __restrict__ aw2) {
    int gw = (blockIdx.x * blockDim.x + threadIdx.x) >> 5;
    if (gw >= BB*NN) return;
    int b = gw / NN, n = gw - b*NN;
    int s = threadIdx.x & 31;
    float e  = tanhf(g_a1[n*BB + b] + g_c2[s*BB + b]);
    float ex = expf(e);
    float tot = ex;
#pragma unroll
    for (int o = 16; o > 0; o >>= 1) tot += __shfl_xor_sync(0xffffffffu, tot, o);
    aw2[(long)gw*SS + s] = ex / tot;
}

__global__ void k_softmax3(float* __restrict__ aw3) {
    int bn = blockIdx.x * blockDim.x + threadIdx.x;
    if (bn >= BB*NN) return;
    int b = bn / NN, n = bn - b*NN;
    float ex[AA]; float tot = 0.f;
#pragma unroll
    for (int a = 0; a < AA; a++) {
        ex[a] = expf(tanhf(g_a3[n*BB + b] + g_c3[a*BB + b]));
        tot += ex[a];
    }
#pragma unroll
    for (int a = 0; a < AA; a++) aw3[(long)bn*AA + a] = ex[a] / tot;
}

// tiled ctx
__global__ void k_ctx_t(const float* __restrict__ aw, const float* __restrict__ enc,
                        float* __restrict__ dst, int L, int D) {
    int b  = blockIdx.x;
    int h0 = blockIdx.y * 64;
    int tid = threadIdx.x;
    __shared__ float AWs[64][33];
    __shared__ float Es[32][68];
    int tx = tid & 15, ty = tid >> 4;
    float acc[4][4] = {};
    for (int t0 = 0; t0 < L; t0 += 32) {
        {
            int row = tid >> 2, c0 = (tid & 3) * 8;
            const float* ap = aw + ((long)b*NN + row)*L + t0 + c0;
            float4 v0 = *(const float4*)ap;
            float4 v1 = *(const float4*)(ap + 4);
            AWs[row][c0+0]=v0.x; AWs[row][c0+1]=v0.y; AWs[row][c0+2]=v0.z; AWs[row][c0+3]=v0.w;
            AWs[row][c0+4]=v1.x; AWs[row][c0+5]=v1.y; AWs[row][c0+6]=v1.z; AWs[row][c0+7]=v1.w;
        }
        {
            int row = tid >> 3, c0 = (tid & 7) * 8;
            const float* ep = enc + (((long)(t0+row))*BB + b)*D + h0 + c0;
            float4 v0 = *(const float4*)ep;
            float4 v1 = *(const float4*)(ep + 4);
            Es[row][c0+0]=v0.x; Es[row][c0+1]=v0.y; Es[row][c0+2]=v0.z; Es[row][c0+3]=v0.w;
            Es[row][c0+4]=v1.x; Es[row][c0+5]=v1.y; Es[row][c0+6]=v1.z; Es[row][c0+7]=v1.w;
        }
        __syncthreads();
#pragma unroll
        for (int tt = 0; tt < 32; tt++) {
            float a[4], e[4];
#pragma unroll
            for (int i = 0; i < 4; i++) { a[i] = AWs[ty*4+i][tt]; e[i] = Es[tt][tx*4+i]; }
#pragma unroll
            for (int i = 0; i < 4; i++)
#pragma unroll
                for (int j = 0; j < 4; j++) acc[i][j] += a[i]*e[j];
        }
        __syncthreads();
    }
#pragma unroll
    for (int i = 0; i < 4; i++) {
        int n = ty*4 + i;
#pragma unroll
        for (int j = 0; j < 4; j++)
            dst[(((long)n)*BB + b)*D + h0 + tx*4 + j] = acc[i][j];
    }
}

// naive ctx (L=5, D=128)
__global__ void k_ctx(const float* __restrict__ aw, const float* __restrict__ enc,
                      float* __restrict__ dst, int L, int D) {
    int i = blockIdx.x * blockDim.x + threadIdx.x;
    if (i >= M2*KK) return;
    int m = i / D, h = i - m*D;
    int n = m / BB, b = m - n*BB;
    const float* awp = aw + ((long)b*NN + n)*L;
    float s = 0.f;
    for (int t = 0; t < L; t++) s += awp[t]*enc[((long)t*BB + b)*D + h];
    dst[i] = s;
}

__global__ void k_e4(const float* __restrict__ enc4, const float* __restrict__ projW,
                     const float* __restrict__ projb) {
    int i = blockIdx.x * blockDim.x + threadIdx.x;
    if (i >= BB*AN) return;
    int b = i / AN, j = i - b*AN;
    float s = projb[j];
    for (int k = 0; k < AN; k++) s += enc4[(0*BB + b)*AN + k]*projW[j*2*AN + k];
    for (int k = 0; k < AN; k++) s += enc4[(1*BB + b)*AN + k]*projW[j*2*AN + AN + k];
    g_e4[i] = s;
}

__global__ void k_gate2(const float* __restrict__ gateW, const float* __restrict__ gateb,
                        float* __restrict__ gateout) {
    int m0 = blockIdx.x * 4;
    int tid = threadIdx.x;
    __shared__ float xs[4][GIN + 12];
#pragma unroll
    for (int r = 0; r < 4; r++) {
        int m = m0 + r, b = m & 31;
        for (int k = tid; k < GIN; k += 256) {
            float v;
            if (k < HH)        v = g_emb[(long)m*HH + k];
            else if (k < 2*HH) v = g_rnn[(long)m*HH + k - HH];
            else               v = g_e4[b*AN + k - 2*HH];
            xs[r][k] = v;
        }
    }
    __syncthreads();
    int w = tid >> 5, lane = tid & 31;
    for (int o = w; o < 4*AN; o += 8) {
        int r = o & 3, j = o >> 2;
        const float* wj = gateW + (long)j*GIN;
        float s = 0.f;
        for (int k = lane; k < GIN; k += 32) s += xs[r][k]*wj[k];
#pragma unroll
        for (int of = 16; of > 0; of >>= 1) s += __shfl_xor_sync(0xffffffffu, s, of);
        if (lane == 0) gateout[(long)(m0+r)*AN + j] = tanhf(s + gateb[j]);
    }
}

__global__ void k_chain(const int* __restrict__ ids) {
    __shared__ int sid[NASP];
    int tid = threadIdx.x;
    int j = blockIdx.x * 256 + tid;
    for (int k = tid; k < NASP; k += 256) sid[k] = ids[k];
    __syncthreads();
    if (j >= NASP) return;
    int v = sid[j];
    int fst = 1, nxt = -1;
    for (int j2 = 0; j2 < NASP; j2++) {
        int w = sid[j2];
        if (w == v) {
            if (j2 < j) fst = 0;
            else if (j2 > j && nxt < 0) nxt = j2;
        }
    }
    g_first[j] = fst;
    g_next[j]  = nxt;
}

__global__ void k_scatter(const float* __restrict__ gate, const int* __restrict__ ids,
                          float* __restrict__ out0) {
    long i = (long)blockIdx.x * blockDim.x + threadIdx.x;
    if (i >= (long)M2*NASP) return;
    int m = (int)(i / NASP);
    int j = (int)(i - (long)m*NASP);
    if (!g_first[j]) return;
    float s = 0.f;
    int jj = j;
    while (jj >= 0) { s += gate[(long)m*AN + (jj % AN)]; jj = g_next[jj]; }
    out0[(long)m*VV + ids[j]] += s;
}

// ---------------- launcher ----------------
extern "C" void kernel_launch(void* const* d_in, const int* in_sizes, int n_in,
                              void* d_out, int out_size) {
    const int*   seq   = (const int*)  d_in[0];
    const float* lasth = (const float*)d_in[1];
    const float* enc1  = (const float*)d_in[2];
    const float* enc2  = (const float*)d_in[3];
    const float* enc3  = (const float*)d_in[4];
    const float* enc4  = (const float*)d_in[5];
    const int*   asp   = (const int*)  d_in[6];
    const float* emb   = (const float*)d_in[7];
    const float* Wih   = (const float*)d_in[8];
    const float* Whh   = (const float*)d_in[9];
    const float* bih   = (const float*)d_in[10];
    const float* bhh   = (const float*)d_in[11];
    const float* attnW = (const float*)d_in[12];
    const float* attnb = (const float*)d_in[13];
    const float* attnv = (const float*)d_in[14];
    const float* attrW = (const float*)d_in[15];
    const float* attrb = (const float*)d_in[16];
    const float* attrv = (const float*)d_in[17];
    const float* concW = (const float*)d_in[18];
    const float* concb = (const float*)d_in[19];
    const float* outW  = (const float*)d_in[20];
    const float* outb  = (const float*)d_in[21];
    const float* gateW = (const float*)d_in[22];
    const float* gateb = (const float*)d_in[23];
    const float* projW = (const float*)d_in[24];
    const float* projb = (const float*)d_in[25];
    float* out = (float*)d_out;

    const long O_HID  = (long)M2*VV;
    const long O_AW1  = O_HID + (long)BB*HH;
    const long O_AW2  = O_AW1 + (long)BB*NN*TT;
    const long O_AW3  = O_AW2 + (long)BB*NN*SS;
    const long O_GATE = O_AW3 + (long)BB*NN*AA;

    float *p_emb, *p_gi, *p_cout, *p_ctx1, *p_ctx2, *p_ctx3;
    uint32_t *p_wt, *p_at;
    cudaGetSymbolAddress((void**)&p_emb,  g_emb);
    cudaGetSymbolAddress((void**)&p_gi,   g_gi);
    cudaGetSymbolAddress((void**)&p_cout, g_cout);
    cudaGetSymbolAddress((void**)&p_ctx1, g_ctx1);
    cudaGetSymbolAddress((void**)&p_ctx2, g_ctx2);
    cudaGetSymbolAddress((void**)&p_ctx3, g_ctx3);
    cudaGetSymbolAddress((void**)&p_wt,   g_wt);
    cudaGetSymbolAddress((void**)&p_at,   g_at);

    const int GRU_SMEM = (6144 + 16384 + 384 + 16) * 4;   // ~92KB
    cudaFuncSetAttribute(k_gru_all, cudaFuncAttributeMaxDynamicSharedMemorySize, GRU_SMEM);

    // 0) W pre-round + fragment pack
    k_pack_w<<<(int)(((long)(VV/128)*64*8*32 + 255)/256), 256>>>(outW);

    // 1) embedding
    k_embed<<<(M2*HH + 255)/256, 256>>>(seq, emb);

    // 2) gi = embedded @ Wih^T + bih (split-tf32, fp32-accurate)
    k_gemm_tf32s<<<dim3((3*HH)/128, M2/128), 256>>>(p_emb, Wih, bih, p_gi, HH, 3*HH);

    // 3) persistent GRU (smem-staged h)
    k_gru_all<<<GRU_BLOCKS, 256, GRU_SMEM>>>(lasth, Whh, bhh, out + O_HID);

    // 4) attention vectors + scalar dots
    k_uvec_p<<<417, 256>>>(attnW, attnv, attnb, attrW, attrv, attrb);
    k_uvec_r<<<(UCOLS + 255)/256, 256>>>();
    {
        int warps = M2 + TT*BB + SS*BB + AA*BB;
        k_ac<<<(warps*32 + 255)/256, 256>>>(enc1, enc2, enc3);
    }

    // 5) softmaxes
    k_softmax1<<<BB*NN, TT>>>(out + O_AW1);
    k_softmax2<<<(BB*NN*32 + 255)/256, 256>>>(out + O_AW2);
    k_softmax3<<<(BB*NN + 255)/256, 256>>>(out + O_AW3);

    // 6) contexts
    k_ctx_t<<<dim3(BB, HH/64), 256>>>(out + O_AW1, enc1, p_ctx1, TT, HH);
    k_ctx_t<<<dim3(BB, HH/64), 256>>>(out + O_AW2, enc2, p_ctx2, SS, HH);
    k_ctx  <<<(M2*KK + 255)/256, 256>>>(out + O_AW3, enc3, p_ctx3, AA, KK);

    // 7) concat GEMM (tf32) -> A pack -> packed tf32 big GEMM
    k_gemm_tf32<1><<<dim3(HH/128, M2/128), 128>>>(nullptr, concW, concb, p_cout, CIN, HH, 1);
    k_pack_a<<<(int)(((long)(M2/128)*64*8*32 + 255)/256), 256>>>(p_cout);
    k_gemm_tf32p<<<dim3(M2/128, VV/128), 128>>>((const uint4*)p_at, (const uint4*)p_wt, outb, out);

    // 8) gate path
    k_e4<<<(BB*AN + 255)/256, 256>>>(enc4, projW, projb);
    k_gate2<<<M2/4, 256>>>(gateW, gateb, out + O_GATE);

    // 9) deterministic scatter-add
    k_chain<<<(NASP + 255)/256, 256>>>(asp);
    k_scatter<<<(int)(((long)M2*NASP + 255)/256), 256>>>(out + O_GATE, asp, out);
}

// round 10
// speedup vs baseline: 3.5434x; 1.0149x over previous
#include <cuda_runtime.h>
#include <cuda_bf16.h>
#include <math.h>
#include <stdint.h>

#define NN 64
#define BB 32
#define HH 512
#define KK 128
#define VV 32000
#define TT 256
#define SS 32
#define AA 5
#define AN 20
#define M2 (NN*BB)          // 2048 rows
#define CIN (3*HH+KK)       // 1664
#define GIN (2*HH+AN)       // 1044
#define NASP 2000
#define GRU_BLOCKS 128
#define UCOLS (2*HH + HH + KK)   // 1664 projected columns

// ---------------- scratch (static device globals; no runtime alloc) ----------------
__device__ __align__(16) float g_emb[M2*HH];
__device__ __align__(16) float g_gi[M2*3*HH];
__device__ __align__(16) float g_hA[HH*BB];
__device__ __align__(16) float g_hB[HH*BB];
__device__ __align__(16) float g_rnn[M2*HH];
__device__ __align__(16) float g_u1[HH];
__device__ __align__(16) float g_u1e[HH];
__device__ __align__(16) float g_u3[HH];
__device__ __align__(16) float g_u3e[KK];
__device__ float g_bv[2];
__device__ __align__(16) float g_upart[16][UCOLS];
__device__ float g_a1[M2], g_a3[M2];
__device__ float g_c1[TT*BB], g_c2[SS*BB], g_c3[AA*BB];
__device__ __align__(16) float g_ctx1[M2*HH];
__device__ __align__(16) float g_ctx2[M2*HH];
__device__ __align__(16) float g_ctx3[M2*KK];
__device__ __align__(16) float g_cout[M2*HH];
__device__ __align__(16) uint32_t g_wt[VV*HH];      // 65.5 MB pre-rounded, fragment-packed W
__device__ __align__(16) uint32_t g_at[M2*HH];      // 4 MB fragment-packed A
__device__ float g_e4[BB*AN];
__device__ int g_first[NASP], g_next[NASP];
__device__ unsigned g_barcnt = 0;
__device__ unsigned g_bargen = 0;

// ---------------- grid barrier (release/acquire) ----------------
__device__ __forceinline__ void grid_barrier(unsigned nb) {
    __syncthreads();
    if (threadIdx.x == 0) {
        unsigned gen;
        asm volatile("ld.relaxed.gpu.global.u32 %0, [%1];" : "=r"(gen) : "l"(&g_bargen));
        unsigned prev;
        asm volatile("atom.release.gpu.global.add.u32 %0, [%1], 1;" : "=r"(prev) : "l"(&g_barcnt));
        if (prev == nb - 1u) {
            asm volatile("st.relaxed.gpu.global.u32 [%0], %1;" :: "l"(&g_barcnt), "r"(0u));
            unsigned d;
            asm volatile("atom.release.gpu.global.add.u32 %0, [%1], 1;" : "=r"(d) : "l"(&g_bargen));
        } else {
            unsigned cur;
            do {
                __nanosleep(20);
                asm volatile("ld.acquire.gpu.global.u32 %0, [%1];" : "=r"(cur) : "l"(&g_bargen));
            } while (cur == gen);
        }
    }
    __syncthreads();
}

// ---------------- helpers ----------------
__device__ __forceinline__ uint32_t smem_u32(const void* p) {
    uint32_t a;
    asm("{ .reg .u64 t; cvta.to.shared.u64 t, %1; cvt.u32.u64 %0, t; }" : "=r"(a) : "l"(p));
    return a;
}
__device__ __forceinline__ uint32_t f2tf(float x) {
    uint32_t u; asm("cvt.rna.tf32.f32 %0, %1;" : "=r"(u) : "f"(x)); return u;
}
__device__ __forceinline__ void split_tf32(float x, uint32_t& hi, uint32_t& lo) {
    hi = f2tf(x);
    float r = x - __uint_as_float(hi);
    lo = f2tf(r);
}
__device__ __forceinline__ void mma_tf32(float& c0, float& c1, float& c2, float& c3,
                                         uint32_t a0, uint32_t a1, uint32_t a2, uint32_t a3,
                                         uint32_t b0, uint32_t b1) {
    asm volatile("mma.sync.aligned.m16n8k8.row.col.f32.tf32.tf32.f32 "
                 "{%0,%1,%2,%3},{%4,%5,%6,%7},{%8,%9},{%0,%1,%2,%3};"
                 : "+f"(c0), "+f"(c1), "+f"(c2), "+f"(c3)
                 : "r"(a0), "r"(a1), "r"(a2), "r"(a3), "r"(b0), "r"(b1));
}
__device__ __forceinline__ void cpa16(uint32_t saddr, const void* gaddr) {
    asm volatile("cp.async.cg.shared.global [%0], [%1], 16;" :: "r"(saddr), "l"(gaddr));
}

// ---------------- kernels ----------------

__global__ void k_embed(const int* __restrict__ seq, const float* __restrict__ emb) {
    int i = blockIdx.x * blockDim.x + threadIdx.x;
    if (i < M2*HH) {
        int m = i / HH, h = i - m*HH;
        g_emb[i] = emb[(long)seq[m]*HH + h];
    }
}

// ---- fragment packing for the big GEMM ----
__global__ void k_pack_w(const float* __restrict__ W) {
    long i = (long)blockIdx.x * 256 + threadIdx.x;
    if (i >= (long)(VV/128)*64*8*32) return;
    int lane = (int)(i & 31), fp = (int)((i >> 5) & 7), s = (int)((i >> 8) & 63);
    long nb = i >> 14;
    int lq = lane >> 2, lr = lane & 3;
    int k = s*8 + lr;
    long ne = nb*128 + fp*16 + lq;
    uint4 v;
    v.x = f2tf(W[ne*HH + k]);
    v.y = f2tf(W[ne*HH + k + 4]);
    v.z = f2tf(W[(ne+8)*HH + k]);
    v.w = f2tf(W[(ne+8)*HH + k + 4]);
    ((uint4*)g_wt)[i] = v;
}

__global__ void k_pack_a(const float* __restrict__ A) {
    long i = (long)blockIdx.x * 256 + threadIdx.x;
    if (i >= (long)(M2/128)*64*8*32) return;
    int lane = (int)(i & 31), mf = (int)((i >> 5) & 7), s = (int)((i >> 8) & 63);
    long mb = i >> 14;
    int lq = lane >> 2, lr = lane & 3;
    int k = s*8 + lr;
    long me = mb*128 + mf*16 + lq;
    uint4 v;
    v.x = f2tf(A[me*HH + k]);
    v.y = f2tf(A[(me+8)*HH + k]);
    v.z = f2tf(A[me*HH + k + 4]);
    v.w = f2tf(A[(me+8)*HH + k + 4]);
    ((uint4*)g_at)[i] = v;
}

// ---------------- packed tf32 GEMM: C[M2,VV] = A[M2,HH] * W[VV,HH]^T + bias ----------------
__global__ __launch_bounds__(128, 2)
void k_gemm_tf32p(const uint4* __restrict__ At, const uint4* __restrict__ Wt,
                  const float* __restrict__ bias, float* __restrict__ C) {
    __shared__ __align__(16) uint4 As[2][512];
    __shared__ __align__(16) uint4 Bs[2][512];
    int tid = threadIdx.x;
    int warp = tid >> 5, lane = tid & 31;
    int wm = warp & 1, wnp = warp >> 1;
    int lq = lane >> 2, lr = lane & 3;
    int m0 = blockIdx.x * 128, n0 = blockIdx.y * 128;
    const uint4* Ab = At + (long)blockIdx.x * 16384;
    const uint4* Bb = Wt + (long)blockIdx.y * 16384;

    float acc[4][8][4];
#pragma unroll
    for (int i = 0; i < 4; i++)
#pragma unroll
        for (int j = 0; j < 8; j++)
#pragma unroll
            for (int c = 0; c < 4; c++) acc[i][j][c] = 0.f;

#pragma unroll
    for (int i = 0; i < 4; i++) {
        cpa16(smem_u32(&As[0][i*128 + tid]), Ab + i*128 + tid);
        cpa16(smem_u32(&Bs[0][i*128 + tid]), Bb + i*128 + tid);
    }
    asm volatile("cp.async.commit_group;");

    int buf = 0;
    const int NK = HH / 16;    // 32 k16 tiles
    for (int c = 0; c < NK; c++) {
        asm volatile("cp.async.wait_group 0;" ::: "memory");
        __syncthreads();
        if (c + 1 < NK) {
            const uint4* an = Ab + (c+1)*512;
            const uint4* bn = Bb + (c+1)*512;
#pragma unroll
            for (int i = 0; i < 4; i++) {
                cpa16(smem_u32(&As[buf^1][i*128 + tid]), an + i*128 + tid);
                cpa16(smem_u32(&Bs[buf^1][i*128 + tid]), bn + i*128 + tid);
            }
            asm volatile("cp.async.commit_group;");
        }
#pragma unroll
        for (int kk = 0; kk < 2; kk++) {
            uint4 av[4], bv[4];
#pragma unroll
            for (int ms = 0; ms < 4; ms++)
                av[ms] = As[buf][kk*256 + (wm*4 + ms)*32 + lane];
#pragma unroll
            for (int p = 0; p < 4; p++)
                bv[p] = Bs[buf][kk*256 + (wnp*4 + p)*32 + lane];
#pragma unroll
            for (int ms = 0; ms < 4; ms++)
#pragma unroll
                for (int p = 0; p < 4; p++) {
                    mma_tf32(acc[ms][2*p][0], acc[ms][2*p][1], acc[ms][2*p][2], acc[ms][2*p][3],
                             av[ms].x, av[ms].y, av[ms].z, av[ms].w, bv[p].x, bv[p].y);
                    mma_tf32(acc[ms][2*p+1][0], acc[ms][2*p+1][1], acc[ms][2*p+1][2], acc[ms][2*p+1][3],
                             av[ms].x, av[ms].y, av[ms].z, av[ms].w, bv[p].z, bv[p].w);
                }
        }
        buf ^= 1;
    }
#pragma unroll
    for (int ms = 0; ms < 4; ms++) {
        int row = m0 + wm*64 + ms*16 + lq;
#pragma unroll
        for (int ns = 0; ns < 8; ns++) {
            int col = n0 + wnp*64 + ns*8 + lr*2;
            float b0 = bias[col], b1 = bias[col+1];
            *(float2*)(C + (long)row*VV + col)     = make_float2(acc[ms][ns][0] + b0, acc[ms][ns][1] + b1);
            *(float2*)(C + (long)(row+8)*VV + col) = make_float2(acc[ms][ns][2] + b0, acc[ms][ns][3] + b1);
        }
    }
}

// ---------------- persistent GRU v3: 512 threads, 2 units/warp, 8-way k split ----------------
// thread: b = tid&31, ju = (tid>>5)&1 (unit pair), kq = tid>>6 (0..7, 64 k each)
// dyn smem: sw [3][4][512], sh [512*32], part [3][4][8][32], sbv [12]
__global__ __launch_bounds__(512, 1)
void k_gru_all(const float* __restrict__ lasth, const float* __restrict__ Whh,
               const float* __restrict__ bhh, float* __restrict__ hid) {
    extern __shared__ __align__(16) float dsm[];
    float* sw   = dsm;                    // 6144
    float* sh   = dsm + 6144;             // 16384
    float* part = dsm + 6144 + 16384;     // 3072
    float* sbv  = part + 3072;            // 12

    int tid = threadIdx.x, bk = blockIdx.x;
    int b  = tid & 31;
    int ju = (tid >> 5) & 1;
    int kq = tid >> 6;                    // 0..7

    for (int r = 0; r < 12; r++) {
        int g = r / 4, j = r % 4;
        int rowi = g*HH + bk*4 + j;
        for (int k = tid; k < HH; k += 512) sw[(g*4 + j)*HH + k] = Whh[(long)rowi*HH + k];
    }
    if (tid < 12) sbv[tid] = bhh[(tid/4)*HH + bk*4 + (tid%4)];

    if (tid < 128) {
        int idx = bk*128 + tid;
        int k = idx >> 5, bb = idx & 31;
        __stcg(&g_hA[idx], lasth[bb*HH + k]);
    }
    grid_barrier(GRU_BLOCKS);

    float* hp = g_hA;
    float* hc = g_hB;
    int u0 = ju*2;                        // units u0, u0+1
    const float* wr0 = sw + (0*4 + u0    )*HH;
    const float* wr1 = sw + (0*4 + u0 + 1)*HH;
    const float* wz0 = sw + (1*4 + u0    )*HH;
    const float* wz1 = sw + (1*4 + u0 + 1)*HH;
    const float* wn0 = sw + (2*4 + u0    )*HH;
    const float* wn1 = sw + (2*4 + u0 + 1)*HH;
    int k0 = kq * 64;

    for (int n = 0; n < NN; n++) {
        // stage full h into smem: 512 threads x 8 float4, high MLP
#pragma unroll
        for (int i = 0; i < 8; i++) {
            int f = tid + i*512;
            float4 v = __ldcg((const float4*)hp + f);
            *(float4*)(sh + 4*f) = v;
        }
        __syncthreads();

        float sr0 = 0.f, sz0 = 0.f, sn0 = 0.f;
        float sr1 = 0.f, sz1 = 0.f, sn1 = 0.f;
#pragma unroll 4
        for (int k = k0; k < k0 + 64; k += 4) {
            float h0 = sh[(k+0)*BB + b];
            float h1 = sh[(k+1)*BB + b];
            float h2 = sh[(k+2)*BB + b];
            float h3 = sh[(k+3)*BB + b];
            float4 a;
            a = *(const float4*)(wr0 + k); sr0 += a.x*h0 + a.y*h1 + a.z*h2 + a.w*h3;
            a = *(const float4*)(wz0 + k); sz0 += a.x*h0 + a.y*h1 + a.z*h2 + a.w*h3;
            a = *(const float4*)(wn0 + k); sn0 += a.x*h0 + a.y*h1 + a.z*h2 + a.w*h3;
            a = *(const float4*)(wr1 + k); sr1 += a.x*h0 + a.y*h1 + a.z*h2 + a.w*h3;
            a = *(const float4*)(wz1 + k); sz1 += a.x*h0 + a.y*h1 + a.z*h2 + a.w*h3;
            a = *(const float4*)(wn1 + k); sn1 += a.x*h0 + a.y*h1 + a.z*h2 + a.w*h3;
        }
        // partials: part[((g*4 + unit)*8 + kq)*32 + b]
        part[((0*4 + u0    )*8 + kq)*32 + b] = sr0;
        part[((1*4 + u0    )*8 + kq)*32 + b] = sz0;
        part[((2*4 + u0    )*8 + kq)*32 + b] = sn0;
        part[((0*4 + u0 + 1)*8 + kq)*32 + b] = sr1;
        part[((1*4 + u0 + 1)*8 + kq)*32 + b] = sz1;
        part[((2*4 + u0 + 1)*8 + kq)*32 + b] = sn1;
        __syncthreads();

        if (kq == 0) {
#pragma unroll
            for (int u = 0; u < 2; u++) {
                int jgl = u0 + u;
                int jg  = bk*4 + jgl;
                float sr = 0.f, sz = 0.f, sn = 0.f;
#pragma unroll
                for (int q = 0; q < 8; q++) {
                    sr += part[((0*4 + jgl)*8 + q)*32 + b];
                    sz += part[((1*4 + jgl)*8 + q)*32 + b];
                    sn += part[((2*4 + jgl)*8 + q)*32 + b];
                }
                float hold = sh[jg % 4 == jg % 4 ? (jg - bk*4 + bk*4)*0 + (bk*4 + jgl)*BB + b - bk*4*BB + bk*4*BB : 0]; // placeholder
                hold = sh[(bk*4 + jgl)*BB + b];
                const float* gi = g_gi + ((long)(n*BB + b))*(3*HH);
                float rr = 1.f/(1.f + expf(-(gi[jg]        + sr + sbv[0*4 + jgl])));
                float zz = 1.f/(1.f + expf(-(gi[HH + jg]   + sz + sbv[1*4 + jgl])));
                float nn = tanhf(gi[2*HH + jg] + rr*(sn + sbv[2*4 + jgl]));
                float hn = (1.f - zz)*nn + zz*hold;
                __stcg(hc + jg*BB + b, hn);
                g_rnn[((long)(n*BB + b))*HH + jg] = hn;
                if (n == NN-1) hid[b*HH + jg] = hn;
            }
        }
        grid_barrier(GRU_BLOCKS);
        float* t = hp; hp = hc; hc = t;
    }
}

// ---------------- tf32 mma GEMM (concat path, cvt at use) ----------------
__device__ __forceinline__ const float* concat_src(int m, int k) {
    if (k < HH)        return g_rnn  + (long)m*HH + k;
    if (k < 2*HH)      return g_ctx1 + (long)m*HH + (k - HH);
    if (k < 3*HH)      return g_ctx2 + (long)m*HH + (k - 2*HH);
    return g_ctx3 + (long)m*KK + (k - 3*HH);
}

template<int ASRC>
__global__ __launch_bounds__(128, 2)
void k_gemm_tf32(const float* __restrict__ A, const float* __restrict__ W,
                 const float* __restrict__ bias, float* __restrict__ C,
                 int Kd, int ldC, int act) {
    __shared__ __align__(16) float As[2][128][20];
    __shared__ __align__(16) float Bs[2][128][20];
    int tid = threadIdx.x;
    int warp = tid >> 5, lane = tid & 31;
    int wm = warp & 1, wnp = warp >> 1;
    int lq = lane >> 2, lr = lane & 3;
    int m0 = blockIdx.y * 128, n0 = blockIdx.x * 128;

    float acc[4][8][4];
#pragma unroll
    for (int i = 0; i < 4; i++)
#pragma unroll
        for (int j = 0; j < 8; j++)
#pragma unroll
            for (int c = 0; c < 4; c++) acc[i][j][c] = 0.f;

    const int NK = Kd / 16;
#pragma unroll
    for (int i = 0; i < 4; i++) {
        int idx = i*128 + tid, row = idx >> 2, kc = idx & 3;
        const float* asrc = ASRC ? concat_src(m0+row, kc*4)
                                 : A + (long)(m0+row)*Kd + kc*4;
        cpa16(smem_u32(&As[0][row][kc*4]), asrc);
        cpa16(smem_u32(&Bs[0][row][kc*4]), W + (long)(n0+row)*Kd + kc*4);
    }
    asm volatile("cp.async.commit_group;");

    int buf = 0;
    for (int ks = 0; ks < NK; ks++) {
        asm volatile("cp.async.wait_group 0;");
        __syncthreads();
        if (ks + 1 < NK) {
#pragma unroll
            for (int i = 0; i < 4; i++) {
                int idx = i*128 + tid, row = idx >> 2, kc = idx & 3;
                int kpos = (ks+1)*16 + kc*4;
                const float* asrc = ASRC ? concat_src(m0+row, kpos)
                                         : A + (long)(m0+row)*Kd + kpos;
                cpa16(smem_u32(&As[buf^1][row][kc*4]), asrc);
                cpa16(smem_u32(&Bs[buf^1][row][kc*4]), W + (long)(n0+row)*Kd + kpos);
            }
            asm volatile("cp.async.commit_group;");
        }
#pragma unroll
        for (int kk = 0; kk < 16; kk += 8) {
            uint32_t af[4][4], bf[8][2];
#pragma unroll
            for (int ms = 0; ms < 4; ms++) {
                int rb = wm*64 + ms*16;
                af[ms][0] = f2tf(As[buf][rb + lq    ][kk + lr    ]);
                af[ms][1] = f2tf(As[buf][rb + lq + 8][kk + lr    ]);
                af[ms][2] = f2tf(As[buf][rb + lq    ][kk + lr + 4]);
                af[ms][3] = f2tf(As[buf][rb + lq + 8][kk + lr + 4]);
            }
#pragma unroll
            for (int ns = 0; ns < 8; ns++) {
                int nb = wnp*64 + ns*8;
                bf[ns][0] = f2tf(Bs[buf][nb + lq][kk + lr    ]);
                bf[ns][1] = f2tf(Bs[buf][nb + lq][kk + lr + 4]);
            }
#pragma unroll
            for (int ms = 0; ms < 4; ms++)
#pragma unroll
                for (int ns = 0; ns < 8; ns++)
                    mma_tf32(acc[ms][ns][0], acc[ms][ns][1], acc[ms][ns][2], acc[ms][ns][3],
                             af[ms][0], af[ms][1], af[ms][2], af[ms][3],
                             bf[ns][0], bf[ns][1]);
        }
        buf ^= 1;
    }
#pragma unroll
    for (int ms = 0; ms < 4; ms++) {
        int row = m0 + wm*64 + ms*16 + lq;
#pragma unroll
        for (int ns = 0; ns < 8; ns++) {
            int col = n0 + wnp*64 + ns*8 + lr*2;
            float b0 = bias[col], b1 = bias[col+1];
            float v00 = acc[ms][ns][0] + b0, v01 = acc[ms][ns][1] + b1;
            float v10 = acc[ms][ns][2] + b0, v11 = acc[ms][ns][3] + b1;
            if (act) { v00 = tanhf(v00); v01 = tanhf(v01); v10 = tanhf(v10); v11 = tanhf(v11); }
            *(float2*)(C + (long)row*ldC + col)     = make_float2(v00, v01);
            *(float2*)(C + (long)(row+8)*ldC + col) = make_float2(v10, v11);
        }
    }
}

// split-precision tf32 GEMM (fp32-accurate) for gi
__global__ __launch_bounds__(256)
void k_gemm_tf32s(const float* __restrict__ A, const float* __restrict__ W,
                  const float* __restrict__ bias, float* __restrict__ C,
                  int Kd, int ldC) {
    __shared__ __align__(16) float As[2][128][20];
    __shared__ __align__(16) float Bs[2][128][20];
    int tid = threadIdx.x;
    int warp = tid >> 5, lane = tid & 31;
    int wm = warp & 1, wn = warp >> 1;
    int lq = lane >> 2, lr = lane & 3;
    int m0 = blockIdx.y * 128, n0 = blockIdx.x * 128;

    float acc[4][4][4];
#pragma unroll
    for (int i = 0; i < 4; i++)
#pragma unroll
        for (int j = 0; j < 4; j++)
#pragma unroll
            for (int c = 0; c < 4; c++) acc[i][j][c] = 0.f;

    const int NK = Kd / 16;
#pragma unroll
    for (int i = 0; i < 2; i++) {
        int idx = i*256 + tid, row = idx >> 2, kc = idx & 3;
        cpa16(smem_u32(&As[0][row][kc*4]), A + (long)(m0+row)*Kd + kc*4);
        cpa16(smem_u32(&Bs[0][row][kc*4]), W + (long)(n0+row)*Kd + kc*4);
    }
    asm volatile("cp.async.commit_group;");

    int buf = 0;
    for (int ks = 0; ks < NK; ks++) {
        asm volatile("cp.async.wait_group 0;");
        __syncthreads();
        if (ks + 1 < NK) {
#pragma unroll
            for (int i = 0; i < 2; i++) {
                int idx = i*256 + tid, row = idx >> 2, kc = idx & 3;
                int kpos = (ks+1)*16 + kc*4;
                cpa16(smem_u32(&As[buf^1][row][kc*4]), A + (long)(m0+row)*Kd + kpos);
                cpa16(smem_u32(&Bs[buf^1][row][kc*4]), W + (long)(n0+row)*Kd + kpos);
            }
            asm volatile("cp.async.commit_group;");
        }
#pragma unroll
        for (int kk = 0; kk < 16; kk += 8) {
            uint32_t ah[4][4], al[4][4], bh[4][2], bl[4][2];
#pragma unroll
            for (int ms = 0; ms < 4; ms++) {
                int rb = wm*64 + ms*16;
                split_tf32(As[buf][rb + lq    ][kk + lr    ], ah[ms][0], al[ms][0]);
                split_tf32(As[buf][rb + lq + 8][kk + lr    ], ah[ms][1], al[ms][1]);
                split_tf32(As[buf][rb + lq    ][kk + lr + 4], ah[ms][2], al[ms][2]);
                split_tf32(As[buf][rb + lq + 8][kk + lr + 4], ah[ms][3], al[ms][3]);
            }
#pragma unroll
            for (int ns = 0; ns < 4; ns++) {
                int nb = wn*32 + ns*8;
                split_tf32(Bs[buf][nb + lq][kk + lr    ], bh[ns][0], bl[ns][0]);
                split_tf32(Bs[buf][nb + lq][kk + lr + 4], bh[ns][1], bl[ns][1]);
            }
#pragma unroll
            for (int ms = 0; ms < 4; ms++)
#pragma unroll
                for (int ns = 0; ns < 4; ns++) {
                    mma_tf32(acc[ms][ns][0], acc[ms][ns][1], acc[ms][ns][2], acc[ms][ns][3],
                             ah[ms][0], ah[ms][1], ah[ms][2], ah[ms][3], bh[ns][0], bh[ns][1]);
                    mma_tf32(acc[ms][ns][0], acc[ms][ns][1], acc[ms][ns][2], acc[ms][ns][3],
                             ah[ms][0], ah[ms][1], ah[ms][2], ah[ms][3], bl[ns][0], bl[ns][1]);
                    mma_tf32(acc[ms][ns][0], acc[ms][ns][1], acc[ms][ns][2], acc[ms][ns][3],
                             al[ms][0], al[ms][1], al[ms][2], al[ms][3], bh[ns][0], bh[ns][1]);
                }
        }
        buf ^= 1;
    }
#pragma unroll
    for (int ms = 0; ms < 4; ms++) {
        int row = m0 + wm*64 + ms*16 + lq;
#pragma unroll
        for (int ns = 0; ns < 4; ns++) {
            int col = n0 + wn*32 + ns*8 + lr*2;
            float b0 = bias[col], b1 = bias[col+1];
            *(float2*)(C + (long)row*ldC + col)     = make_float2(acc[ms][ns][0] + b0, acc[ms][ns][1] + b1);
            *(float2*)(C + (long)(row+8)*ldC + col) = make_float2(acc[ms][ns][2] + b0, acc[ms][ns][3] + b1);
        }
    }
}

// ---------------- uvec: stage 1 + stage 2 ----------------
__global__ void k_uvec_p(const float* __restrict__ attnW, const float* __restrict__ attnv,
                         const float* __restrict__ attnb, const float* __restrict__ attrW,
                         const float* __restrict__ attrv, const float* __restrict__ attrb) {
    __shared__ float red[4][64];
    int blk = blockIdx.x;
    int tid = threadIdx.x;
    if (blk < 416) {
        int hb = blk / 26, cb = blk - hb*26;
        int tx = tid & 63, hy = tid >> 6;
        int col = cb*64 + tx;
        const float* W; const float* v; int ld; int c;
        if (col < 2*HH) { W = attnW; v = attnv; ld = 2*HH;    c = col; }
        else            { W = attrW; v = attrv; ld = HH + KK; c = col - 2*HH; }
        int h0 = hb*32;
        float acc = 0.f;
#pragma unroll
        for (int t = 0; t < 8; t++) {
            int h = h0 + hy + t*4;
            acc += W[(long)h*ld + c] * v[h];
        }
        red[hy][tx] = acc;
        __syncthreads();
        if (hy == 0) g_upart[hb][col] = red[0][tx] + red[1][tx] + red[2][tx] + red[3][tx];
    } else {
        int w = tid >> 5, lane = tid & 31;
        if (w < 2) {
            const float* bp = w ? attrb : attnb;
            const float* vp = w ? attrv : attnv;
            float s = 0.f;
            for (int h = lane; h < HH; h += 32) s += bp[h]*vp[h];
#pragma unroll
            for (int o = 16; o > 0; o >>= 1) s += __shfl_xor_sync(0xffffffffu, s, o);
            if (lane == 0) g_bv[w] = s;
        }
    }
}

__global__ void k_uvec_r() {
    int i = blockIdx.x * blockDim.x + threadIdx.x;
    if (i >= UCOLS) return;
    float s = 0.f;
#pragma unroll
    for (int hb = 0; hb < 16; hb++) s += g_upart[hb][i];
    if (i < HH)            g_u1[i] = s;
    else if (i < 2*HH)     g_u1e[i - HH] = s;
    else if (i < 3*HH)     g_u3[i - 2*HH] = s;
    else                   g_u3e[i - 3*HH] = s;
}

// all scalar attention dot products
__global__ void k_ac(const float* __restrict__ enc1, const float* __restrict__ enc2,
                     const float* __restrict__ enc3) {
    int gw = (blockIdx.x * blockDim.x + threadIdx.x) >> 5;
    int lane = threadIdx.x & 31;
    const int E_A = M2, E_C1 = E_A + TT*BB, E_C2 = E_C1 + SS*BB, E_C3 = E_C2 + AA*BB;
    if (gw >= E_C3) return;
    if (gw < E_A) {
        const float4* x = (const float4*)(g_rnn + (long)gw*HH);
        const float4* u1 = (const float4*)g_u1;
        const float4* u3 = (const float4*)g_u3;
        float s1 = 0.f, s3 = 0.f;
#pragma unroll
        for (int k = lane; k < HH/4; k += 32) {
            float4 xv = x[k], a = u1[k], b = u3[k];
            s1 += xv.x*a.x + xv.y*a.y + xv.z*a.z + xv.w*a.w;
            s3 += xv.x*b.x + xv.y*b.y + xv.z*b.z + xv.w*b.w;
        }
#pragma unroll
        for (int o = 16; o > 0; o >>= 1) {
            s1 += __shfl_xor_sync(0xffffffffu, s1, o);
            s3 += __shfl_xor_sync(0xffffffffu, s3, o);
        }
        if (lane == 0) { g_a1[gw] = s1 + g_bv[0]; g_a3[gw] = s3 + g_bv[1]; }
        return;
    }
    const float* x; const float* u; float* dst; int len = HH;
    if (gw < E_C1)      { int m = gw - E_A;   x = enc1 + (long)m*HH; u = g_u1e; dst = g_c1 + m; }
    else if (gw < E_C2) { int m = gw - E_C1;  x = enc2 + (long)m*HH; u = g_u1e; dst = g_c2 + m; }
    else                { int m = gw - E_C2;  x = enc3 + (long)m*KK; u = g_u3e; dst = g_c3 + m; len = KK; }
    const float4* x4 = (const float4*)x;
    const float4* u4 = (const float4*)u;
    float s = 0.f;
    for (int k = lane; k < len/4; k += 32) {
        float4 xv = x4[k], uv = u4[k];
        s += xv.x*uv.x + xv.y*uv.y + xv.z*uv.z + xv.w*uv.w;
    }
#pragma unroll
    for (int o = 16; o > 0; o >>= 1) s += __shfl_xor_sync(0xffffffffu, s, o);
    if (lane == 0) *dst = s;
}

__global__ void k_softmax1(float* __restrict__ aw1) {
    int bn = blockIdx.x;
    int b = bn / NN, n = bn - b*NN;
    int t = threadIdx.x;
    float e  = tanhf(g_a1[n*BB + b] + g_c1[t*BB + b]);
    float ex = expf(e);
    __shared__ float red[8];
    __shared__ float stot;
    float s = ex;
#pragma unroll
    for (int o = 16; o > 0; o >>= 1) s += __shfl_xor_sync(0xffffffffu, s, o);
    if ((t & 31) == 0) red[t >> 5] = s;
    __syncthreads();
    if (t == 0) { float tt = 0.f; for (int i = 0; i < 8; i++) tt += red[i]; stot = tt; }
    __syncthreads();
    aw1[(long)bn*TT + t] = ex / stot;
}

__global__ void k_softmax2(float* __restrict__ aw2) {
    int gw = (blockIdx.x * blockDim.x + threadIdx.x) >> 5;
    if (gw >= BB*NN) return;
    int b = gw / NN, n = gw - b*NN;
    int s = threadIdx.x & 31;
    float e  = tanhf(g_a1[n*BB + b] + g_c2[s*BB + b]);
    float ex = expf(e);
    float tot = ex;
#pragma unroll
    for (int o = 16; o > 0; o >>= 1) tot += __shfl_xor_sync(0xffffffffu, tot, o);
    aw2[(long)gw*SS + s] = ex / tot;
}

__global__ void k_softmax3(float* __restrict__ aw3) {
    int bn = blockIdx.x * blockDim.x + threadIdx.x;
    if (bn >= BB*NN) return;
    int b = bn / NN, n = bn - b*NN;
    float ex[AA]; float tot = 0.f;
#pragma unroll
    for (int a = 0; a < AA; a++) {
        ex[a] = expf(tanhf(g_a3[n*BB + b] + g_c3[a*BB + b]));
        tot += ex[a];
    }
#pragma unroll
    for (int a = 0; a < AA; a++) aw3[(long)bn*AA + a] = ex[a] / tot;
}

// tiled ctx
__global__ void k_ctx_t(const float* __restrict__ aw, const float* __restrict__ enc,
                        float* __restrict__ dst, int L, int D) {
    int b  = blockIdx.x;
    int h0 = blockIdx.y * 64;
    int tid = threadIdx.x;
    __shared__ float AWs[64][33];
    __shared__ float Es[32][68];
    int tx = tid & 15, ty = tid >> 4;
    float acc[4][4] = {};
    for (int t0 = 0; t0 < L; t0 += 32) {
        {
            int row = tid >> 2, c0 = (tid & 3) * 8;
            const float* ap = aw + ((long)b*NN + row)*L + t0 + c0;
            float4 v0 = *(const float4*)ap;
            float4 v1 = *(const float4*)(ap + 4);
            AWs[row][c0+0]=v0.x; AWs[row][c0+1]=v0.y; AWs[row][c0+2]=v0.z; AWs[row][c0+3]=v0.w;
            AWs[row][c0+4]=v1.x; AWs[row][c0+5]=v1.y; AWs[row][c0+6]=v1.z; AWs[row][c0+7]=v1.w;
        }
        {
            int row = tid >> 3, c0 = (tid & 7) * 8;
            const float* ep = enc + (((long)(t0+row))*BB + b)*D + h0 + c0;
            float4 v0 = *(const float4*)ep;
            float4 v1 = *(const float4*)(ep + 4);
            Es[row][c0+0]=v0.x; Es[row][c0+1]=v0.y; Es[row][c0+2]=v0.z; Es[row][c0+3]=v0.w;
            Es[row][c0+4]=v1.x; Es[row][c0+5]=v1.y; Es[row][c0+6]=v1.z; Es[row][c0+7]=v1.w;
        }
        __syncthreads();
#pragma unroll
        for (int tt = 0; tt < 32; tt++) {
            float a[4], e[4];
#pragma unroll
            for (int i = 0; i < 4; i++) { a[i] = AWs[ty*4+i][tt]; e[i] = Es[tt][tx*4+i]; }
#pragma unroll
            for (int i = 0; i < 4; i++)
#pragma unroll
                for (int j = 0; j < 4; j++) acc[i][j] += a[i]*e[j];
        }
        __syncthreads();
    }
#pragma unroll
    for (int i = 0; i < 4; i++) {
        int n = ty*4 + i;
#pragma unroll
        for (int j = 0; j < 4; j++)
            dst[(((long)n)*BB + b)*D + h0 + tx*4 + j] = acc[i][j];
    }
}

// naive ctx (L=5, D=128)
__global__ void k_ctx(const float* __restrict__ aw, const float* __restrict__ enc,
                      float* __restrict__ dst, int L, int D) {
    int i = blockIdx.x * blockDim.x + threadIdx.x;
    if (i >= M2*KK) return;
    int m = i / D, h = i - m*D;
    int n = m / BB, b = m - n*BB;
    const float* awp = aw + ((long)b*NN + n)*L;
    float s = 0.f;
    for (int t = 0; t < L; t++) s += awp[t]*enc[((long)t*BB + b)*D + h];
    dst[i] = s;
}

__global__ void k_e4(const float* __restrict__ enc4, const float* __restrict__ projW,
                     const float* __restrict__ projb) {
    int i = blockIdx.x * blockDim.x + threadIdx.x;
    if (i >= BB*AN) return;
    int b = i / AN, j = i - b*AN;
    float s = projb[j];
    for (int k = 0; k < AN; k++) s += enc4[(0*BB + b)*AN + k]*projW[j*2*AN + k];
    for (int k = 0; k < AN; k++) s += enc4[(1*BB + b)*AN + k]*projW[j*2*AN + AN + k];
    g_e4[i] = s;
}

__global__ void k_gate2(const float* __restrict__ gateW, const float* __restrict__ gateb,
                        float* __restrict__ gateout) {
    int m0 = blockIdx.x * 4;
    int tid = threadIdx.x;
    __shared__ float xs[4][GIN + 12];
#pragma unroll
    for (int r = 0; r < 4; r++) {
        int m = m0 + r, b = m & 31;
        for (int k = tid; k < GIN; k += 256) {
            float v;
            if (k < HH)        v = g_emb[(long)m*HH + k];
            else if (k < 2*HH) v = g_rnn[(long)m*HH + k - HH];
            else               v = g_e4[b*AN + k - 2*HH];
            xs[r][k] = v;
        }
    }
    __syncthreads();
    int w = tid >> 5, lane = tid & 31;
    for (int o = w; o < 4*AN; o += 8) {
        int r = o & 3, j = o >> 2;
        const float* wj = gateW + (long)j*GIN;
        float s = 0.f;
        for (int k = lane; k < GIN; k += 32) s += xs[r][k]*wj[k];
#pragma unroll
        for (int of = 16; of > 0; of >>= 1) s += __shfl_xor_sync(0xffffffffu, s, of);
        if (lane == 0) gateout[(long)(m0+r)*AN + j] = tanhf(s + gateb[j]);
    }
}

__global__ void k_chain(const int* __restrict__ ids) {
    __shared__ int sid[NASP];
    int tid = threadIdx.x;
    int j = blockIdx.x * 256 + tid;
    for (int k = tid; k < NASP; k += 256) sid[k] = ids[k];
    __syncthreads();
    if (j >= NASP) return;
    int v = sid[j];
    int fst = 1, nxt = -1;
    for (int j2 = 0; j2 < NASP; j2++) {
        int w = sid[j2];
        if (w == v) {
            if (j2 < j) fst = 0;
            else if (j2 > j && nxt < 0) nxt = j2;
        }
    }
    g_first[j] = fst;
    g_next[j]  = nxt;
}

__global__ void k_scatter(const float* __restrict__ gate, const int* __restrict__ ids,
                          float* __restrict__ out0) {
    long i = (long)blockIdx.x * blockDim.x + threadIdx.x;
    if (i >= (long)M2*NASP) return;
    int m = (int)(i / NASP);
    int j = (int)(i - (long)m*NASP);
    if (!g_first[j]) return;
    float s = 0.f;
    int jj = j;
    while (jj >= 0) { s += gate[(long)m*AN + (jj % AN)]; jj = g_next[jj]; }
    out0[(long)m*VV + ids[j]] += s;
}

// ---------------- launcher ----------------
extern "C" void kernel_launch(void* const* d_in, const int* in_sizes, int n_in,
                              void* d_out, int out_size) {
    const int*   seq   = (const int*)  d_in[0];
    const float* lasth = (const float*)d_in[1];
    const float* enc1  = (const float*)d_in[2];
    const float* enc2  = (const float*)d_in[3];
    const float* enc3  = (const float*)d_in[4];
    const float* enc4  = (const float*)d_in[5];
    const int*   asp   = (const int*)  d_in[6];
    const float* emb   = (const float*)d_in[7];
    const float* Wih   = (const float*)d_in[8];
    const float* Whh   = (const float*)d_in[9];
    const float* bih   = (const float*)d_in[10];
    const float* bhh   = (const float*)d_in[11];
    const float* attnW = (const float*)d_in[12];
    const float* attnb = (const float*)d_in[13];
    const float* attnv = (const float*)d_in[14];
    const float* attrW = (const float*)d_in[15];
    const float* attrb = (const float*)d_in[16];
    const float* attrv = (const float*)d_in[17];
    const float* concW = (const float*)d_in[18];
    const float* concb = (const float*)d_in[19];
    const float* outW  = (const float*)d_in[20];
    const float* outb  = (const float*)d_in[21];
    const float* gateW = (const float*)d_in[22];
    const float* gateb = (const float*)d_in[23];
    const float* projW = (const float*)d_in[24];
    const float* projb = (const float*)d_in[25];
    float* out = (float*)d_out;

    const long O_HID  = (long)M2*VV;
    const long O_AW1  = O_HID + (long)BB*HH;
    const long O_AW2  = O_AW1 + (long)BB*NN*TT;
    const long O_AW3  = O_AW2 + (long)BB*NN*SS;
    const long O_GATE = O_AW3 + (long)BB*NN*AA;

    float *p_emb, *p_gi, *p_cout, *p_ctx1, *p_ctx2, *p_ctx3;
    uint32_t *p_wt, *p_at;
    cudaGetSymbolAddress((void**)&p_emb,  g_emb);
    cudaGetSymbolAddress((void**)&p_gi,   g_gi);
    cudaGetSymbolAddress((void**)&p_cout, g_cout);
    cudaGetSymbolAddress((void**)&p_ctx1, g_ctx1);
    cudaGetSymbolAddress((void**)&p_ctx2, g_ctx2);
    cudaGetSymbolAddress((void**)&p_ctx3, g_ctx3);
    cudaGetSymbolAddress((void**)&p_wt,   g_wt);
    cudaGetSymbolAddress((void**)&p_at,   g_at);

    const int GRU_SMEM = (6144 + 16384 + 3072 + 16) * 4;   // ~100KB
    cudaFuncSetAttribute(k_gru_all, cudaFuncAttributeMaxDynamicSharedMemorySize, GRU_SMEM);

    // 0) W pre-round + fragment pack
    k_pack_w<<<(int)(((long)(VV/128)*64*8*32 + 255)/256), 256>>>(outW);

    // 1) embedding
    k_embed<<<(M2*HH + 255)/256, 256>>>(seq, emb);

    // 2) gi = embedded @ Wih^T + bih (split-tf32, fp32-accurate)
    k_gemm_tf32s<<<dim3((3*HH)/128, M2/128), 256>>>(p_emb, Wih, bih, p_gi, HH, 3*HH);

    // 3) persistent GRU v3 (512 threads, 2 units/warp, 8-way k split)
    k_gru_all<<<GRU_BLOCKS, 512, GRU_SMEM>>>(lasth, Whh, bhh, out + O_HID);

    // 4) attention vectors + scalar dots
    k_uvec_p<<<417, 256>>>(attnW, attnv, attnb, attrW, attrv, attrb);
    k_uvec_r<<<(UCOLS + 255)/256, 256>>>();
    {
        int warps = M2 + TT*BB + SS*BB + AA*BB;
        k_ac<<<(warps*32 + 255)/256, 256>>>(enc1, enc2, enc3);
    }

    // 5) softmaxes
    k_softmax1<<<BB*NN, TT>>>(out + O_AW1);
    k_softmax2<<<(BB*NN*32 + 255)/256, 256>>>(out + O_AW2);
    k_softmax3<<<(BB*NN + 255)/256, 256>>>(out + O_AW3);

    // 6) contexts
    k_ctx_t<<<dim3(BB, HH/64), 256>>>(out + O_AW1, enc1, p_ctx1, TT, HH);
    k_ctx_t<<<dim3(BB, HH/64), 256>>>(out + O_AW2, enc2, p_ctx2, SS, HH);
    k_ctx  <<<(M2*KK + 255)/256, 256>>>(out + O_AW3, enc3, p_ctx3, AA, KK);

    // 7) concat GEMM (tf32) -> A pack -> packed tf32 big GEMM
    k_gemm_tf32<1><<<dim3(HH/128, M2/128), 128>>>(nullptr, concW, concb, p_cout, CIN, HH, 1);
    k_pack_a<<<(int)(((long)(M2/128)*64*8*32 + 255)/256), 256>>>(p_cout);
    k_gemm_tf32p<<<dim3(M2/128, VV/128), 128>>>((const uint4*)p_at, (const uint4*)p_wt, outb, out);

    // 8) gate path
    k_e4<<<(BB*AN + 255)/256, 256>>>(enc4, projW, projb);
    k_gate2<<<M2/4, 256>>>(gateW, gateb, out + O_GATE);

    // 9) deterministic scatter-add
    k_chain<<<(NASP + 255)/256, 256>>>(asp);
    k_scatter<<<(int)(((long)M2*NASP + 255)/256), 256>>>(out + O_GATE, asp, out);
}

// round 12
// speedup vs baseline: 3.5473x; 1.0011x over previous
#include <cuda_runtime.h>
#include <cuda_bf16.h>
#include <math.h>
#include <stdint.h>

#define NN 64
#define BB 32
#define HH 512
#define KK 128
#define VV 32000
#define TT 256
#define SS 32
#define AA 5
#define AN 20
#define M2 (NN*BB)          // 2048 rows
#define CIN (3*HH+KK)       // 1664
#define GIN (2*HH+AN)       // 1044
#define NASP 2000
#define GRU_BLOCKS 128
#define UCOLS (2*HH + HH + KK)   // 1664 projected columns

// ---------------- scratch (static device globals; no runtime alloc) ----------------
__device__ __align__(16) float g_emb[M2*HH];
__device__ __align__(16) float g_gi[M2*3*HH];
__device__ __align__(16) float g_hA[HH*BB];
__device__ __align__(16) float g_hB[HH*BB];
__device__ __align__(16) float g_rnn[M2*HH];
__device__ __align__(16) float g_u1[HH];
__device__ __align__(16) float g_u1e[HH];
__device__ __align__(16) float g_u3[HH];
__device__ __align__(16) float g_u3e[KK];
__device__ float g_bv[2];
__device__ __align__(16) float g_upart[16][UCOLS];
__device__ float g_a1[M2], g_a3[M2];
__device__ float g_c1[TT*BB], g_c2[SS*BB], g_c3[AA*BB];
__device__ __align__(16) float g_ctx1[M2*HH];
__device__ __align__(16) float g_ctx2[M2*HH];
__device__ __align__(16) float g_ctx3[M2*KK];
__device__ __align__(16) float g_cout[M2*HH];
__device__ __align__(16) uint32_t g_wt[VV*HH];      // 65.5 MB pre-rounded, fragment-packed W
__device__ __align__(16) uint32_t g_at[M2*HH];      // 4 MB fragment-packed A
__device__ float g_e4[BB*AN];
__device__ int g_first[NASP], g_next[NASP];
__device__ __align__(128) unsigned g_flag[GRU_BLOCKS*32] = {0};   // one padded flag per block

// ---------------- contention-free flag barrier (GRU only; monotonic steps) ----------------
__device__ __forceinline__ void gru_barrier(int bk, unsigned step) {
    __syncthreads();
    if (threadIdx.x == 0) {
        asm volatile("st.release.gpu.global.u32 [%0], %1;"
                     :: "l"(&g_flag[bk*32]), "r"(step) : "memory");
    }
    if (threadIdx.x < GRU_BLOCKS) {
        unsigned v;
        do {
            asm volatile("ld.acquire.gpu.global.u32 %0, [%1];"
                         : "=r"(v) : "l"(&g_flag[threadIdx.x*32]) : "memory");
        } while (v < step);
    }
    __syncthreads();
}

// reset flags AFTER the GRU kernel has fully exited (launch boundary = global sync)
__global__ void k_flagreset() {
    if (threadIdx.x < GRU_BLOCKS) g_flag[threadIdx.x*32] = 0u;
}

// ---------------- helpers ----------------
__device__ __forceinline__ uint32_t smem_u32(const void* p) {
    uint32_t a;
    asm("{ .reg .u64 t; cvta.to.shared.u64 t, %1; cvt.u32.u64 %0, t; }" : "=r"(a) : "l"(p));
    return a;
}
__device__ __forceinline__ uint32_t f2tf(float x) {
    uint32_t u; asm("cvt.rna.tf32.f32 %0, %1;" : "=r"(u) : "f"(x)); return u;
}
__device__ __forceinline__ void split_tf32(float x, uint32_t& hi, uint32_t& lo) {
    hi = f2tf(x);
    float r = x - __uint_as_float(hi);
    lo = f2tf(r);
}
__device__ __forceinline__ void mma_tf32(float& c0, float& c1, float& c2, float& c3,
                                         uint32_t a0, uint32_t a1, uint32_t a2, uint32_t a3,
                                         uint32_t b0, uint32_t b1) {
    asm volatile("mma.sync.aligned.m16n8k8.row.col.f32.tf32.tf32.f32 "
                 "{%0,%1,%2,%3},{%4,%5,%6,%7},{%8,%9},{%0,%1,%2,%3};"
                 : "+f"(c0), "+f"(c1), "+f"(c2), "+f"(c3)
                 : "r"(a0), "r"(a1), "r"(a2), "r"(a3), "r"(b0), "r"(b1));
}
__device__ __forceinline__ void cpa16(uint32_t saddr, const void* gaddr) {
    asm volatile("cp.async.cg.shared.global [%0], [%1], 16;" :: "r"(saddr), "l"(gaddr));
}

// ---------------- kernels ----------------

__global__ void k_embed(const int* __restrict__ seq, const float* __restrict__ emb) {
    int i = blockIdx.x * blockDim.x + threadIdx.x;
    if (i < M2*HH) {
        int m = i / HH, h = i - m*HH;
        g_emb[i] = emb[(long)seq[m]*HH + h];
    }
}

// ---- fragment packing for the big GEMM ----
__global__ void k_pack_w(const float* __restrict__ W) {
    long i = (long)blockIdx.x * 256 + threadIdx.x;
    if (i >= (long)(VV/128)*64*8*32) return;
    int lane = (int)(i & 31), fp = (int)((i >> 5) & 7), s = (int)((i >> 8) & 63);
    long nb = i >> 14;
    int lq = lane >> 2, lr = lane & 3;
    int k = s*8 + lr;
    long ne = nb*128 + fp*16 + lq;
    uint4 v;
    v.x = f2tf(W[ne*HH + k]);
    v.y = f2tf(W[ne*HH + k + 4]);
    v.z = f2tf(W[(ne+8)*HH + k]);
    v.w = f2tf(W[(ne+8)*HH + k + 4]);
    ((uint4*)g_wt)[i] = v;
}

__global__ void k_pack_a(const float* __restrict__ A) {
    long i = (long)blockIdx.x * 256 + threadIdx.x;
    if (i >= (long)(M2/128)*64*8*32) return;
    int lane = (int)(i & 31), mf = (int)((i >> 5) & 7), s = (int)((i >> 8) & 63);
    long mb = i >> 14;
    int lq = lane >> 2, lr = lane & 3;
    int k = s*8 + lr;
    long me = mb*128 + mf*16 + lq;
    uint4 v;
    v.x = f2tf(A[me*HH + k]);
    v.y = f2tf(A[(me+8)*HH + k]);
    v.z = f2tf(A[me*HH + k + 4]);
    v.w = f2tf(A[(me+8)*HH + k + 4]);
    ((uint4*)g_at)[i] = v;
}

// ---------------- packed tf32 GEMM: C[M2,VV] = A[M2,HH] * W[VV,HH]^T + bias ----------------
__global__ __launch_bounds__(128, 2)
void k_gemm_tf32p(const uint4* __restrict__ At, const uint4* __restrict__ Wt,
                  const float* __restrict__ bias, float* __restrict__ C) {
    __shared__ __align__(16) uint4 As[2][512];
    __shared__ __align__(16) uint4 Bs[2][512];
    int tid = threadIdx.x;
    int warp = tid >> 5, lane = tid & 31;
    int wm = warp & 1, wnp = warp >> 1;
    int lq = lane >> 2, lr = lane & 3;
    int m0 = blockIdx.x * 128, n0 = blockIdx.y * 128;
    const uint4* Ab = At + (long)blockIdx.x * 16384;
    const uint4* Bb = Wt + (long)blockIdx.y * 16384;

    float acc[4][8][4];
#pragma unroll
    for (int i = 0; i < 4; i++)
#pragma unroll
        for (int j = 0; j < 8; j++)
#pragma unroll
            for (int c = 0; c < 4; c++) acc[i][j][c] = 0.f;

#pragma unroll
    for (int i = 0; i < 4; i++) {
        cpa16(smem_u32(&As[0][i*128 + tid]), Ab + i*128 + tid);
        cpa16(smem_u32(&Bs[0][i*128 + tid]), Bb + i*128 + tid);
    }
    asm volatile("cp.async.commit_group;");

    int buf = 0;
    const int NK = HH / 16;    // 32 k16 tiles
    for (int c = 0; c < NK; c++) {
        asm volatile("cp.async.wait_group 0;" ::: "memory");
        __syncthreads();
        if (c + 1 < NK) {
            const uint4* an = Ab + (c+1)*512;
            const uint4* bn = Bb + (c+1)*512;
#pragma unroll
            for (int i = 0; i < 4; i++) {
                cpa16(smem_u32(&As[buf^1][i*128 + tid]), an + i*128 + tid);
                cpa16(smem_u32(&Bs[buf^1][i*128 + tid]), bn + i*128 + tid);
            }
            asm volatile("cp.async.commit_group;");
        }
#pragma unroll
        for (int kk = 0; kk < 2; kk++) {
            uint4 av[4], bv[4];
#pragma unroll
            for (int ms = 0; ms < 4; ms++)
                av[ms] = As[buf][kk*256 + (wm*4 + ms)*32 + lane];
#pragma unroll
            for (int p = 0; p < 4; p++)
                bv[p] = Bs[buf][kk*256 + (wnp*4 + p)*32 + lane];
#pragma unroll
            for (int ms = 0; ms < 4; ms++)
#pragma unroll
                for (int p = 0; p < 4; p++) {
                    mma_tf32(acc[ms][2*p][0], acc[ms][2*p][1], acc[ms][2*p][2], acc[ms][2*p][3],
                             av[ms].x, av[ms].y, av[ms].z, av[ms].w, bv[p].x, bv[p].y);
                    mma_tf32(acc[ms][2*p+1][0], acc[ms][2*p+1][1], acc[ms][2*p+1][2], acc[ms][2*p+1][3],
                             av[ms].x, av[ms].y, av[ms].z, av[ms].w, bv[p].z, bv[p].w);
                }
        }
        buf ^= 1;
    }
#pragma unroll
    for (int ms = 0; ms < 4; ms++) {
        int row = m0 + wm*64 + ms*16 + lq;
#pragma unroll
        for (int ns = 0; ns < 8; ns++) {
            int col = n0 + wnp*64 + ns*8 + lr*2;
            float b0 = bias[col], b1 = bias[col+1];
            *(float2*)(C + (long)row*VV + col)     = make_float2(acc[ms][ns][0] + b0, acc[ms][ns][1] + b1);
            *(float2*)(C + (long)(row+8)*VV + col) = make_float2(acc[ms][ns][2] + b0, acc[ms][ns][3] + b1);
        }
    }
}

// ---------------- persistent GRU v4: flag barrier, 512 threads ----------------
__global__ __launch_bounds__(512, 1)
void k_gru_all(const float* __restrict__ lasth, const float* __restrict__ Whh,
               const float* __restrict__ bhh, float* __restrict__ hid) {
    extern __shared__ __align__(16) float dsm[];
    float* sw   = dsm;                    // 6144
    float* sh   = dsm + 6144;             // 16384
    float* part = dsm + 6144 + 16384;     // 3072
    float* sbv  = part + 3072;            // 12

    int tid = threadIdx.x, bk = blockIdx.x;
    int b  = tid & 31;
    int ju = (tid >> 5) & 1;
    int kq = tid >> 6;                    // 0..7

    for (int r = 0; r < 12; r++) {
        int g = r / 4, j = r % 4;
        int rowi = g*HH + bk*4 + j;
        for (int k = tid; k < HH; k += 512) sw[(g*4 + j)*HH + k] = Whh[(long)rowi*HH + k];
    }
    if (tid < 12) sbv[tid] = bhh[(tid/4)*HH + bk*4 + (tid%4)];

    if (tid < 128) {
        int idx = bk*128 + tid;
        int k = idx >> 5, bb = idx & 31;
        __stcg(&g_hA[idx], lasth[bb*HH + k]);
    }
    gru_barrier(bk, 1u);

    float* hp = g_hA;
    float* hc = g_hB;
    int u0 = ju*2;                        // units u0, u0+1
    const float* wr0 = sw + (0*4 + u0    )*HH;
    const float* wr1 = sw + (0*4 + u0 + 1)*HH;
    const float* wz0 = sw + (1*4 + u0    )*HH;
    const float* wz1 = sw + (1*4 + u0 + 1)*HH;
    const float* wn0 = sw + (2*4 + u0    )*HH;
    const float* wn1 = sw + (2*4 + u0 + 1)*HH;
    int k0 = kq * 64;

    for (int n = 0; n < NN; n++) {
        // stage full h into smem: 512 threads x 8 float4, high MLP
#pragma unroll
        for (int i = 0; i < 8; i++) {
            int f = tid + i*512;
            float4 v = __ldcg((const float4*)hp + f);
            *(float4*)(sh + 4*f) = v;
        }
        __syncthreads();

        float sr0 = 0.f, sz0 = 0.f, sn0 = 0.f;
        float sr1 = 0.f, sz1 = 0.f, sn1 = 0.f;
#pragma unroll 4
        for (int k = k0; k < k0 + 64; k += 4) {
            float h0 = sh[(k+0)*BB + b];
            float h1 = sh[(k+1)*BB + b];
            float h2 = sh[(k+2)*BB + b];
            float h3 = sh[(k+3)*BB + b];
            float4 a;
            a = *(const float4*)(wr0 + k); sr0 += a.x*h0 + a.y*h1 + a.z*h2 + a.w*h3;
            a = *(const float4*)(wz0 + k); sz0 += a.x*h0 + a.y*h1 + a.z*h2 + a.w*h3;
            a = *(const float4*)(wn0 + k); sn0 += a.x*h0 + a.y*h1 + a.z*h2 + a.w*h3;
            a = *(const float4*)(wr1 + k); sr1 += a.x*h0 + a.y*h1 + a.z*h2 + a.w*h3;
            a = *(const float4*)(wz1 + k); sz1 += a.x*h0 + a.y*h1 + a.z*h2 + a.w*h3;
            a = *(const float4*)(wn1 + k); sn1 += a.x*h0 + a.y*h1 + a.z*h2 + a.w*h3;
        }
        part[((0*4 + u0    )*8 + kq)*32 + b] = sr0;
        part[((1*4 + u0    )*8 + kq)*32 + b] = sz0;
        part[((2*4 + u0    )*8 + kq)*32 + b] = sn0;
        part[((0*4 + u0 + 1)*8 + kq)*32 + b] = sr1;
        part[((1*4 + u0 + 1)*8 + kq)*32 + b] = sz1;
        part[((2*4 + u0 + 1)*8 + kq)*32 + b] = sn1;
        __syncthreads();

        if (kq == 0) {
#pragma unroll
            for (int u = 0; u < 2; u++) {
                int jgl = u0 + u;
                int jg  = bk*4 + jgl;
                float sr = 0.f, sz = 0.f, sn = 0.f;
#pragma unroll
                for (int q = 0; q < 8; q++) {
                    sr += part[((0*4 + jgl)*8 + q)*32 + b];
                    sz += part[((1*4 + jgl)*8 + q)*32 + b];
                    sn += part[((2*4 + jgl)*8 + q)*32 + b];
                }
                float hold = sh[jg*BB + b];
                const float* gi = g_gi + ((long)(n*BB + b))*(3*HH);
                float rr = 1.f/(1.f + expf(-(gi[jg]        + sr + sbv[0*4 + jgl])));
                float zz = 1.f/(1.f + expf(-(gi[HH + jg]   + sz + sbv[1*4 + jgl])));
                float nn = tanhf(gi[2*HH + jg] + rr*(sn + sbv[2*4 + jgl]));
                float hn = (1.f - zz)*nn + zz*hold;
                __stcg(hc + jg*BB + b, hn);
                g_rnn[((long)(n*BB + b))*HH + jg] = hn;
                if (n == NN-1) hid[b*HH + jg] = hn;
            }
        }
        if (n < NN-1) gru_barrier(bk, (unsigned)(n + 2));
        float* t = hp; hp = hc; hc = t;
    }
    // NOTE: no flag reset here — done by k_flagreset after this kernel exits.
}

// ---------------- tf32 mma GEMM (concat path, cvt at use) ----------------
__device__ __forceinline__ const float* concat_src(int m, int k) {
    if (k < HH)        return g_rnn  + (long)m*HH + k;
    if (k < 2*HH)      return g_ctx1 + (long)m*HH + (k - HH);
    if (k < 3*HH)      return g_ctx2 + (long)m*HH + (k - 2*HH);
    return g_ctx3 + (long)m*KK + (k - 3*HH);
}

template<int ASRC>
__global__ __launch_bounds__(128, 2)
void k_gemm_tf32(const float* __restrict__ A, const float* __restrict__ W,
                 const float* __restrict__ bias, float* __restrict__ C,
                 int Kd, int ldC, int act) {
    __shared__ __align__(16) float As[2][128][20];
    __shared__ __align__(16) float Bs[2][128][20];
    int tid = threadIdx.x;
    int warp = tid >> 5, lane = tid & 31;
    int wm = warp & 1, wnp = warp >> 1;
    int lq = lane >> 2, lr = lane & 3;
    int m0 = blockIdx.y * 128, n0 = blockIdx.x * 128;

    float acc[4][8][4];
#pragma unroll
    for (int i = 0; i < 4; i++)
#pragma unroll
        for (int j = 0; j < 8; j++)
#pragma unroll
            for (int c = 0; c < 4; c++) acc[i][j][c] = 0.f;

    const int NK = Kd / 16;
#pragma unroll
    for (int i = 0; i < 4; i++) {
        int idx = i*128 + tid, row = idx >> 2, kc = idx & 3;
        const float* asrc = ASRC ? concat_src(m0+row, kc*4)
                                 : A + (long)(m0+row)*Kd + kc*4;
        cpa16(smem_u32(&As[0][row][kc*4]), asrc);
        cpa16(smem_u32(&Bs[0][row][kc*4]), W + (long)(n0+row)*Kd + kc*4);
    }
    asm volatile("cp.async.commit_group;");

    int buf = 0;
    for (int ks = 0; ks < NK; ks++) {
        asm volatile("cp.async.wait_group 0;");
        __syncthreads();
        if (ks + 1 < NK) {
#pragma unroll
            for (int i = 0; i < 4; i++) {
                int idx = i*128 + tid, row = idx >> 2, kc = idx & 3;
                int kpos = (ks+1)*16 + kc*4;
                const float* asrc = ASRC ? concat_src(m0+row, kpos)
                                         : A + (long)(m0+row)*Kd + kpos;
                cpa16(smem_u32(&As[buf^1][row][kc*4]), asrc);
                cpa16(smem_u32(&Bs[buf^1][row][kc*4]), W + (long)(n0+row)*Kd + kpos);
            }
            asm volatile("cp.async.commit_group;");
        }
#pragma unroll
        for (int kk = 0; kk < 16; kk += 8) {
            uint32_t af[4][4], bf[8][2];
#pragma unroll
            for (int ms = 0; ms < 4; ms++) {
                int rb = wm*64 + ms*16;
                af[ms][0] = f2tf(As[buf][rb + lq    ][kk + lr    ]);
                af[ms][1] = f2tf(As[buf][rb + lq + 8][kk + lr    ]);
                af[ms][2] = f2tf(As[buf][rb + lq    ][kk + lr + 4]);
                af[ms][3] = f2tf(As[buf][rb + lq + 8][kk + lr + 4]);
            }
#pragma unroll
            for (int ns = 0; ns < 8; ns++) {
                int nb = wnp*64 + ns*8;
                bf[ns][0] = f2tf(Bs[buf][nb + lq][kk + lr    ]);
                bf[ns][1] = f2tf(Bs[buf][nb + lq][kk + lr + 4]);
            }
#pragma unroll
            for (int ms = 0; ms < 4; ms++)
#pragma unroll
                for (int ns = 0; ns < 8; ns++)
                    mma_tf32(acc[ms][ns][0], acc[ms][ns][1], acc[ms][ns][2], acc[ms][ns][3],
                             af[ms][0], af[ms][1], af[ms][2], af[ms][3],
                             bf[ns][0], bf[ns][1]);
        }
        buf ^= 1;
    }
#pragma unroll
    for (int ms = 0; ms < 4; ms++) {
        int row = m0 + wm*64 + ms*16 + lq;
#pragma unroll
        for (int ns = 0; ns < 8; ns++) {
            int col = n0 + wnp*64 + ns*8 + lr*2;
            float b0 = bias[col], b1 = bias[col+1];
            float v00 = acc[ms][ns][0] + b0, v01 = acc[ms][ns][1] + b1;
            float v10 = acc[ms][ns][2] + b0, v11 = acc[ms][ns][3] + b1;
            if (act) { v00 = tanhf(v00); v01 = tanhf(v01); v10 = tanhf(v10); v11 = tanhf(v11); }
            *(float2*)(C + (long)row*ldC + col)     = make_float2(v00, v01);
            *(float2*)(C + (long)(row+8)*ldC + col) = make_float2(v10, v11);
        }
    }
}

// split-precision tf32 GEMM (fp32-accurate) for gi
__global__ __launch_bounds__(256)
void k_gemm_tf32s(const float* __restrict__ A, const float* __restrict__ W,
                  const float* __restrict__ bias, float* __restrict__ C,
                  int Kd, int ldC) {
    __shared__ __align__(16) float As[2][128][20];
    __shared__ __align__(16) float Bs[2][128][20];
    int tid = threadIdx.x;
    int warp = tid >> 5, lane = tid & 31;
    int wm = warp & 1, wn = warp >> 1;
    int lq = lane >> 2, lr = lane & 3;
    int m0 = blockIdx.y * 128, n0 = blockIdx.x * 128;

    float acc[4][4][4];
#pragma unroll
    for (int i = 0; i < 4; i++)
#pragma unroll
        for (int j = 0; j < 4; j++)
#pragma unroll
            for (int c = 0; c < 4; c++) acc[i][j][c] = 0.f;

    const int NK = Kd / 16;
#pragma unroll
    for (int i = 0; i < 2; i++) {
        int idx = i*256 + tid, row = idx >> 2, kc = idx & 3;
        cpa16(smem_u32(&As[0][row][kc*4]), A + (long)(m0+row)*Kd + kc*4);
        cpa16(smem_u32(&Bs[0][row][kc*4]), W + (long)(n0+row)*Kd + kc*4);
    }
    asm volatile("cp.async.commit_group;");

    int buf = 0;
    for (int ks = 0; ks < NK; ks++) {
        asm volatile("cp.async.wait_group 0;");
        __syncthreads();
        if (ks + 1 < NK) {
#pragma unroll
            for (int i = 0; i < 2; i++) {
                int idx = i*256 + tid, row = idx >> 2, kc = idx & 3;
                int kpos = (ks+1)*16 + kc*4;
                cpa16(smem_u32(&As[buf^1][row][kc*4]), A + (long)(m0+row)*Kd + kpos);
                cpa16(smem_u32(&Bs[buf^1][row][kc*4]), W + (long)(n0+row)*Kd + kpos);
            }
            asm volatile("cp.async.commit_group;");
        }
#pragma unroll
        for (int kk = 0; kk < 16; kk += 8) {
            uint32_t ah[4][4], al[4][4], bh[4][2], bl[4][2];
#pragma unroll
            for (int ms = 0; ms < 4; ms++) {
                int rb = wm*64 + ms*16;
                split_tf32(As[buf][rb + lq    ][kk + lr    ], ah[ms][0], al[ms][0]);
                split_tf32(As[buf][rb + lq + 8][kk + lr    ], ah[ms][1], al[ms][1]);
                split_tf32(As[buf][rb + lq    ][kk + lr + 4], ah[ms][2], al[ms][2]);
                split_tf32(As[buf][rb + lq + 8][kk + lr + 4], ah[ms][3], al[ms][3]);
            }
#pragma unroll
            for (int ns = 0; ns < 4; ns++) {
                int nb = wn*32 + ns*8;
                split_tf32(Bs[buf][nb + lq][kk + lr    ], bh[ns][0], bl[ns][0]);
                split_tf32(Bs[buf][nb + lq][kk + lr + 4], bh[ns][1], bl[ns][1]);
            }
#pragma unroll
            for (int ms = 0; ms < 4; ms++)
#pragma unroll
                for (int ns = 0; ns < 4; ns++) {
                    mma_tf32(acc[ms][ns][0], acc[ms][ns][1], acc[ms][ns][2], acc[ms][ns][3],
                             ah[ms][0], ah[ms][1], ah[ms][2], ah[ms][3], bh[ns][0], bh[ns][1]);
                    mma_tf32(acc[ms][ns][0], acc[ms][ns][1], acc[ms][ns][2], acc[ms][ns][3],
                             ah[ms][0], ah[ms][1], ah[ms][2], ah[ms][3], bl[ns][0], bl[ns][1]);
                    mma_tf32(acc[ms][ns][0], acc[ms][ns][1], acc[ms][ns][2], acc[ms][ns][3],
                             al[ms][0], al[ms][1], al[ms][2], al[ms][3], bh[ns][0], bh[ns][1]);
                }
        }
        buf ^= 1;
    }
#pragma unroll
    for (int ms = 0; ms < 4; ms++) {
        int row = m0 + wm*64 + ms*16 + lq;
#pragma unroll
        for (int ns = 0; ns < 4; ns++) {
            int col = n0 + wn*32 + ns*8 + lr*2;
            float b0 = bias[col], b1 = bias[col+1];
            *(float2*)(C + (long)row*ldC + col)     = make_float2(acc[ms][ns][0] + b0, acc[ms][ns][1] + b1);
            *(float2*)(C + (long)(row+8)*ldC + col) = make_float2(acc[ms][ns][2] + b0, acc[ms][ns][3] + b1);
        }
    }
}

// ---------------- uvec: stage 1 + stage 2 ----------------
__global__ void k_uvec_p(const float* __restrict__ attnW, const float* __restrict__ attnv,
                         const float* __restrict__ attnb, const float* __restrict__ attrW,
                         const float* __restrict__ attrv, const float* __restrict__ attrb) {
    __shared__ float red[4][64];
    int blk = blockIdx.x;
    int tid = threadIdx.x;
    if (blk < 416) {
        int hb = blk / 26, cb = blk - hb*26;
        int tx = tid & 63, hy = tid >> 6;
        int col = cb*64 + tx;
        const float* W; const float* v; int ld; int c;
        if (col < 2*HH) { W = attnW; v = attnv; ld = 2*HH;    c = col; }
        else            { W = attrW; v = attrv; ld = HH + KK; c = col - 2*HH; }
        int h0 = hb*32;
        float acc = 0.f;
#pragma unroll
        for (int t = 0; t < 8; t++) {
            int h = h0 + hy + t*4;
            acc += W[(long)h*ld + c] * v[h];
        }
        red[hy][tx] = acc;
        __syncthreads();
        if (hy == 0) g_upart[hb][col] = red[0][tx] + red[1][tx] + red[2][tx] + red[3][tx];
    } else {
        int w = tid >> 5, lane = tid & 31;
        if (w < 2) {
            const float* bp = w ? attrb : attnb;
            const float* vp = w ? attrv : attnv;
            float s = 0.f;
            for (int h = lane; h < HH; h += 32) s += bp[h]*vp[h];
#pragma unroll
            for (int o = 16; o > 0; o >>= 1) s += __shfl_xor_sync(0xffffffffu, s, o);
            if (lane == 0) g_bv[w] = s;
        }
    }
}

__global__ void k_uvec_r() {
    int i = blockIdx.x * blockDim.x + threadIdx.x;
    if (i >= UCOLS) return;
    float s = 0.f;
#pragma unroll
    for (int hb = 0; hb < 16; hb++) s += g_upart[hb][i];
    if (i < HH)            g_u1[i] = s;
    else if (i < 2*HH)     g_u1e[i - HH] = s;
    else if (i < 3*HH)     g_u3[i - 2*HH] = s;
    else                   g_u3e[i - 3*HH] = s;
}

// all scalar attention dot products
__global__ void k_ac(const float* __restrict__ enc1, const float* __restrict__ enc2,
                     const float* __restrict__ enc3) {
    int gw = (blockIdx.x * blockDim.x + threadIdx.x) >> 5;
    int lane = threadIdx.x & 31;
    const int E_A = M2, E_C1 = E_A + TT*BB, E_C2 = E_C1 + SS*BB, E_C3 = E_C2 + AA*BB;
    if (gw >= E_C3) return;
    if (gw < E_A) {
        const float4* x = (const float4*)(g_rnn + (long)gw*HH);
        const float4* u1 = (const float4*)g_u1;
        const float4* u3 = (const float4*)g_u3;
        float s1 = 0.f, s3 = 0.f;
#pragma unroll
        for (int k = lane; k < HH/4; k += 32) {
            float4 xv = x[k], a = u1[k], b = u3[k];
            s1 += xv.x*a.x + xv.y*a.y + xv.z*a.z + xv.w*a.w;
            s3 += xv.x*b.x + xv.y*b.y + xv.z*b.z + xv.w*b.w;
        }
#pragma unroll
        for (int o = 16; o > 0; o >>= 1) {
            s1 += __shfl_xor_sync(0xffffffffu, s1, o);
            s3 += __shfl_xor_sync(0xffffffffu, s3, o);
        }
        if (lane == 0) { g_a1[gw] = s1 + g_bv[0]; g_a3[gw] = s3 + g_bv[1]; }
        return;
    }
    const float* x; const float* u; float* dst; int len = HH;
    if (gw < E_C1)      { int m = gw - E_A;   x = enc1 + (long)m*HH; u = g_u1e; dst = g_c1 + m; }
    else if (gw < E_C2) { int m = gw - E_C1;  x = enc2 + (long)m*HH; u = g_u1e; dst = g_c2 + m; }
    else                { int m = gw - E_C2;  x = enc3 + (long)m*KK; u = g_u3e; dst = g_c3 + m; len = KK; }
    const float4* x4 = (const float4*)x;
    const float4* u4 = (const float4*)u;
    float s = 0.f;
    for (int k = lane; k < len/4; k += 32) {
        float4 xv = x4[k], uv = u4[k];
        s += xv.x*uv.x + xv.y*uv.y + xv.z*uv.z + xv.w*uv.w;
    }
#pragma unroll
    for (int o = 16; o > 0; o >>= 1) s += __shfl_xor_sync(0xffffffffu, s, o);
    if (lane == 0) *dst = s;
}

__global__ void k_softmax1(float* __restrict__ aw1) {
    int bn = blockIdx.x;
    int b = bn / NN, n = bn - b*NN;
    int t = threadIdx.x;
    float e  = tanhf(g_a1[n*BB + b] + g_c1[t*BB + b]);
    float ex = expf(e);
    __shared__ float red[8];
    __shared__ float stot;
    float s = ex;
#pragma unroll
    for (int o = 16; o > 0; o >>= 1) s += __shfl_xor_sync(0xffffffffu, s, o);
    if ((t & 31) == 0) red[t >> 5] = s;
    __syncthreads();
    if (t == 0) { float tt = 0.f; for (int i = 0; i < 8; i++) tt += red[i]; stot = tt; }
    __syncthreads();
    aw1[(long)bn*TT + t] = ex / stot;
}

__global__ void k_softmax2(float* __restrict__ aw2) {
    int gw = (blockIdx.x * blockDim.x + threadIdx.x) >> 5;
    if (gw >= BB*NN) return;
    int b = gw / NN, n = gw - b*NN;
    int s = threadIdx.x & 31;
    float e  = tanhf(g_a1[n*BB + b] + g_c2[s*BB + b]);
    float ex = expf(e);
    float tot = ex;
#pragma unroll
    for (int o = 16; o > 0; o >>= 1) tot += __shfl_xor_sync(0xffffffffu, tot, o);
    aw2[(long)gw*SS + s] = ex / tot;
}

__global__ void k_softmax3(float* __restrict__ aw3) {
    int bn = blockIdx.x * blockDim.x + threadIdx.x;
    if (bn >= BB*NN) return;
    int b = bn / NN, n = bn - b*NN;
    float ex[AA]; float tot = 0.f;
#pragma unroll
    for (int a = 0; a < AA; a++) {
        ex[a] = expf(tanhf(g_a3[n*BB + b] + g_c3[a*BB + b]));
        tot += ex[a];
    }
#pragma unroll
    for (int a = 0; a < AA; a++) aw3[(long)bn*AA + a] = ex[a] / tot;
}

// tiled ctx
__global__ void k_ctx_t(const float* __restrict__ aw, const float* __restrict__ enc,
                        float* __restrict__ dst, int L, int D) {
    int b  = blockIdx.x;
    int h0 = blockIdx.y * 64;
    int tid = threadIdx.x;
    __shared__ float AWs[64][33];
    __shared__ float Es[32][68];
    int tx = tid & 15, ty = tid >> 4;
    float acc[4][4] = {};
    for (int t0 = 0; t0 < L; t0 += 32) {
        {
            int row = tid >> 2, c0 = (tid & 3) * 8;
            const float* ap = aw + ((long)b*NN + row)*L + t0 + c0;
            float4 v0 = *(const float4*)ap;
            float4 v1 = *(const float4*)(ap + 4);
            AWs[row][c0+0]=v0.x; AWs[row][c0+1]=v0.y; AWs[row][c0+2]=v0.z; AWs[row][c0+3]=v0.w;
            AWs[row][c0+4]=v1.x; AWs[row][c0+5]=v1.y; AWs[row][c0+6]=v1.z; AWs[row][c0+7]=v1.w;
        }
        {
            int row = tid >> 3, c0 = (tid & 7) * 8;
            const float* ep = enc + (((long)(t0+row))*BB + b)*D + h0 + c0;
            float4 v0 = *(const float4*)ep;
            float4 v1 = *(const float4*)(ep + 4);
            Es[row][c0+0]=v0.x; Es[row][c0+1]=v0.y; Es[row][c0+2]=v0.z; Es[row][c0+3]=v0.w;
            Es[row][c0+4]=v1.x; Es[row][c0+5]=v1.y; Es[row][c0+6]=v1.z; Es[row][c0+7]=v1.w;
        }
        __syncthreads();
#pragma unroll
        for (int tt = 0; tt < 32; tt++) {
            float a[4], e[4];
#pragma unroll
            for (int i = 0; i < 4; i++) { a[i] = AWs[ty*4+i][tt]; e[i] = Es[tt][tx*4+i]; }
#pragma unroll
            for (int i = 0; i < 4; i++)
#pragma unroll
                for (int j = 0; j < 4; j++) acc[i][j] += a[i]*e[j];
        }
        __syncthreads();
    }
#pragma unroll
    for (int i = 0; i < 4; i++) {
        int n = ty*4 + i;
#pragma unroll
        for (int j = 0; j < 4; j++)
            dst[(((long)n)*BB + b)*D + h0 + tx*4 + j] = acc[i][j];
    }
}

// naive ctx (L=5, D=128)
__global__ void k_ctx(const float* __restrict__ aw, const float* __restrict__ enc,
                      float* __restrict__ dst, int L, int D) {
    int i = blockIdx.x * blockDim.x + threadIdx.x;
    if (i >= M2*KK) return;
    int m = i / D, h = i - m*D;
    int n = m / BB, b = m - n*BB;
    const float* awp = aw + ((long)b*NN + n)*L;
    float s = 0.f;
    for (int t = 0; t < L; t++) s += awp[t]*enc[((long)t*BB + b)*D + h];
    dst[i] = s;
}

__global__ void k_e4(const float* __restrict__ enc4, const float* __restrict__ projW,
                     const float* __restrict__ projb) {
    int i = blockIdx.x * blockDim.x + threadIdx.x;
    if (i >= BB*AN) return;
    int b = i / AN, j = i - b*AN;
    float s = projb[j];
    for (int k = 0; k < AN; k++) s += enc4[(0*BB + b)*AN + k]*projW[j*2*AN + k];
    for (int k = 0; k < AN; k++) s += enc4[(1*BB + b)*AN + k]*projW[j*2*AN + AN + k];
    g_e4[i] = s;
}

__global__ void k_gate2(const float* __restrict__ gateW, const float* __restrict__ gateb,
                        float* __restrict__ gateout) {
    int m0 = blockIdx.x * 4;
    int tid = threadIdx.x;
    __shared__ float xs[4][GIN + 12];
#pragma unroll
    for (int r = 0; r < 4; r++) {
        int m = m0 + r, b = m & 31;
        for (int k = tid; k < GIN; k += 256) {
            float v;
            if (k < HH)        v = g_emb[(long)m*HH + k];
            else if (k < 2*HH) v = g_rnn[(long)m*HH + k - HH];
            else               v = g_e4[b*AN + k - 2*HH];
            xs[r][k] = v;
        }
    }
    __syncthreads();
    int w = tid >> 5, lane = tid & 31;
    for (int o = w; o < 4*AN; o += 8) {
        int r = o & 3, j = o >> 2;
        const float* wj = gateW + (long)j*GIN;
        float s = 0.f;
        for (int k = lane; k < GIN; k += 32) s += xs[r][k]*wj[k];
#pragma unroll
        for (int of = 16; of > 0; of >>= 1) s += __shfl_xor_sync(0xffffffffu, s, of);
        if (lane == 0) gateout[(long)(m0+r)*AN + j] = tanhf(s + gateb[j]);
    }
}

__global__ void k_chain(const int* __restrict__ ids) {
    __shared__ int sid[NASP];
    int tid = threadIdx.x;
    int j = blockIdx.x * 256 + tid;
    for (int k = tid; k < NASP; k += 256) sid[k] = ids[k];
    __syncthreads();
    if (j >= NASP) return;
    int v = sid[j];
    int fst = 1, nxt = -1;
    for (int j2 = 0; j2 < NASP; j2++) {
        int w = sid[j2];
        if (w == v) {
            if (j2 < j) fst = 0;
            else if (j2 > j && nxt < 0) nxt = j2;
        }
    }
    g_first[j] = fst;
    g_next[j]  = nxt;
}

__global__ void k_scatter(const float* __restrict__ gate, const int* __restrict__ ids,
                          float* __restrict__ out0) {
    long i = (long)blockIdx.x * blockDim.x + threadIdx.x;
    if (i >= (long)M2*NASP) return;
    int m = (int)(i / NASP);
    int j = (int)(i - (long)m*NASP);
    if (!g_first[j]) return;
    float s = 0.f;
    int jj = j;
    while (jj >= 0) { s += gate[(long)m*AN + (jj % AN)]; jj = g_next[jj]; }
    out0[(long)m*VV + ids[j]] += s;
}

// ---------------- launcher ----------------
extern "C" void kernel_launch(void* const* d_in, const int* in_sizes, int n_in,
                              void* d_out, int out_size) {
    const int*   seq   = (const int*)  d_in[0];
    const float* lasth = (const float*)d_in[1];
    const float* enc1  = (const float*)d_in[2];
    const float* enc2  = (const float*)d_in[3];
    const float* enc3  = (const float*)d_in[4];
    const float* enc4  = (const float*)d_in[5];
    const int*   asp   = (const int*)  d_in[6];
    const float* emb   = (const float*)d_in[7];
    const float* Wih   = (const float*)d_in[8];
    const float* Whh   = (const float*)d_in[9];
    const float* bih   = (const float*)d_in[10];
    const float* bhh   = (const float*)d_in[11];
    const float* attnW = (const float*)d_in[12];
    const float* attnb = (const float*)d_in[13];
    const float* attnv = (const float*)d_in[14];
    const float* attrW = (const float*)d_in[15];
    const float* attrb = (const float*)d_in[16];
    const float* attrv = (const float*)d_in[17];
    const float* concW = (const float*)d_in[18];
    const float* concb = (const float*)d_in[19];
    const float* outW  = (const float*)d_in[20];
    const float* outb  = (const float*)d_in[21];
    const float* gateW = (const float*)d_in[22];
    const float* gateb = (const float*)d_in[23];
    const float* projW = (const float*)d_in[24];
    const float* projb = (const float*)d_in[25];
    float* out = (float*)d_out;

    const long O_HID  = (long)M2*VV;
    const long O_AW1  = O_HID + (long)BB*HH;
    const long O_AW2  = O_AW1 + (long)BB*NN*TT;
    const long O_AW3  = O_AW2 + (long)BB*NN*SS;
    const long O_GATE = O_AW3 + (long)BB*NN*AA;

    float *p_emb, *p_gi, *p_cout, *p_ctx1, *p_ctx2, *p_ctx3;
    uint32_t *p_wt, *p_at;
    cudaGetSymbolAddress((void**)&p_emb,  g_emb);
    cudaGetSymbolAddress((void**)&p_gi,   g_gi);
    cudaGetSymbolAddress((void**)&p_cout, g_cout);
    cudaGetSymbolAddress((void**)&p_ctx1, g_ctx1);
    cudaGetSymbolAddress((void**)&p_ctx2, g_ctx2);
    cudaGetSymbolAddress((void**)&p_ctx3, g_ctx3);
    cudaGetSymbolAddress((void**)&p_wt,   g_wt);
    cudaGetSymbolAddress((void**)&p_at,   g_at);

    const int GRU_SMEM = (6144 + 16384 + 3072 + 16) * 4;   // ~100KB
    cudaFuncSetAttribute(k_gru_all, cudaFuncAttributeMaxDynamicSharedMemorySize, GRU_SMEM);

    // 0) W pre-round + fragment pack
    k_pack_w<<<(int)(((long)(VV/128)*64*8*32 + 255)/256), 256>>>(outW);

    // 1) embedding
    k_embed<<<(M2*HH + 255)/256, 256>>>(seq, emb);

    // 2) gi = embedded @ Wih^T + bih (split-tf32, fp32-accurate)
    k_gemm_tf32s<<<dim3((3*HH)/128, M2/128), 256>>>(p_emb, Wih, bih, p_gi, HH, 3*HH);

    // 3) persistent GRU v4 (flag barrier) + flag reset at launch boundary
    k_gru_all<<<GRU_BLOCKS, 512, GRU_SMEM>>>(lasth, Whh, bhh, out + O_HID);
    k_flagreset<<<1, 128>>>();

    // 4) attention vectors + scalar dots
    k_uvec_p<<<417, 256>>>(attnW, attnv, attnb, attrW, attrv, attrb);
    k_uvec_r<<<(UCOLS + 255)/256, 256>>>();
    {
        int warps = M2 + TT*BB + SS*BB + AA*BB;
        k_ac<<<(warps*32 + 255)/256, 256>>>(enc1, enc2, enc3);
    }

    // 5) softmaxes
    k_softmax1<<<BB*NN, TT>>>(out + O_AW1);
    k_softmax2<<<(BB*NN*32 + 255)/256, 256>>>(out + O_AW2);
    k_softmax3<<<(BB*NN + 255)/256, 256>>>(out + O_AW3);

    // 6) contexts
    k_ctx_t<<<dim3(BB, HH/64), 256>>>(out + O_AW1, enc1, p_ctx1, TT, HH);
    k_ctx_t<<<dim3(BB, HH/64), 256>>>(out + O_AW2, enc2, p_ctx2, SS, HH);
    k_ctx  <<<(M2*KK + 255)/256, 256>>>(out + O_AW3, enc3, p_ctx3, AA, KK);

    // 7) concat GEMM (tf32) -> A pack -> packed tf32 big GEMM
    k_gemm_tf32<1><<<dim3(HH/128, M2/128), 128>>>(nullptr, concW, concb, p_cout, CIN, HH, 1);
    k_pack_a<<<(int)(((long)(M2/128)*64*8*32 + 255)/256), 256>>>(p_cout);
    k_gemm_tf32p<<<dim3(M2/128, VV/128), 128>>>((const uint4*)p_at, (const uint4*)p_wt, outb, out);

    // 8) gate path
    k_e4<<<(BB*AN + 255)/256, 256>>>(enc4, projW, projb);
    k_gate2<<<M2/4, 256>>>(gateW, gateb, out + O_GATE);

    // 9) deterministic scatter-add
    k_chain<<<(NASP + 255)/256, 256>>>(asp);
    k_scatter<<<(int)(((long)M2*NASP + 255)/256), 256>>>(out + O_GATE, asp, out);
}

// round 13
// speedup vs baseline: 3.6815x; 1.0378x over previous
#include <cuda_runtime.h>
#include <cuda_bf16.h>
#include <math.h>
#include <stdint.h>

#define NN 64
#define BB 32
#define HH 512
#define KK 128
#define VV 32000
#define TT 256
#define SS 32
#define AA 5
#define AN 20
#define M2 (NN*BB)          // 2048 rows
#define CIN (3*HH+KK)       // 1664
#define GIN (2*HH+AN)       // 1044
#define NASP 2000
#define GRU_BLOCKS 128
#define SIDE_BLOCKS 20
#define UCOLS (2*HH + HH + KK)   // 1664 projected columns

// ---------------- scratch (static device globals; no runtime alloc) ----------------
__device__ __align__(16) float g_emb[M2*HH];
__device__ __align__(16) float g_gi[M2*3*HH];
__device__ __align__(16) float g_hA[HH*BB];
__device__ __align__(16) float g_hB[HH*BB];
__device__ __align__(16) float g_rnn[M2*HH];
__device__ __align__(16) float g_u1[HH];
__device__ __align__(16) float g_u1e[HH];
__device__ __align__(16) float g_u3[HH];
__device__ __align__(16) float g_u3e[KK];
__device__ float g_bv[2];
__device__ float g_a1[M2], g_a3[M2];
__device__ float g_c1[TT*BB], g_c2[SS*BB], g_c3[AA*BB];
__device__ __align__(16) float g_ctx1[M2*HH];
__device__ __align__(16) float g_ctx2[M2*HH];
__device__ __align__(16) float g_ctx3[M2*KK];
__device__ __align__(16) float g_cout[M2*HH];
__device__ __align__(16) uint32_t g_wt[VV*HH];      // 65.5 MB pre-rounded, fragment-packed W
__device__ __align__(16) uint32_t g_at[M2*HH];      // 4 MB fragment-packed A
__device__ float g_e4[BB*AN];
__device__ int g_first[NASP], g_next[NASP];
__device__ __align__(128) unsigned g_flag[GRU_BLOCKS*32] = {0};   // one padded flag per block

// ---------------- contention-free flag barrier (GRU blocks only; monotonic steps) ----------------
__device__ __forceinline__ void gru_barrier(int bk, unsigned step) {
    __syncthreads();
    if (threadIdx.x == 0) {
        asm volatile("st.release.gpu.global.u32 [%0], %1;"
                     :: "l"(&g_flag[bk*32]), "r"(step) : "memory");
    }
    if (threadIdx.x < GRU_BLOCKS) {
        unsigned v;
        do {
            asm volatile("ld.acquire.gpu.global.u32 %0, [%1];"
                         : "=r"(v) : "l"(&g_flag[threadIdx.x*32]) : "memory");
        } while (v < step);
    }
    __syncthreads();
}

__global__ void k_flagreset() {
    if (threadIdx.x < GRU_BLOCKS) g_flag[threadIdx.x*32] = 0u;
}

// ---------------- helpers ----------------
__device__ __forceinline__ uint32_t smem_u32(const void* p) {
    uint32_t a;
    asm("{ .reg .u64 t; cvta.to.shared.u64 t, %1; cvt.u32.u64 %0, t; }" : "=r"(a) : "l"(p));
    return a;
}
__device__ __forceinline__ uint32_t f2tf(float x) {
    uint32_t u; asm("cvt.rna.tf32.f32 %0, %1;" : "=r"(u) : "f"(x)); return u;
}
__device__ __forceinline__ void split_tf32(float x, uint32_t& hi, uint32_t& lo) {
    hi = f2tf(x);
    float r = x - __uint_as_float(hi);
    lo = f2tf(r);
}
__device__ __forceinline__ void mma_tf32(float& c0, float& c1, float& c2, float& c3,
                                         uint32_t a0, uint32_t a1, uint32_t a2, uint32_t a3,
                                         uint32_t b0, uint32_t b1) {
    asm volatile("mma.sync.aligned.m16n8k8.row.col.f32.tf32.tf32.f32 "
                 "{%0,%1,%2,%3},{%4,%5,%6,%7},{%8,%9},{%0,%1,%2,%3};"
                 : "+f"(c0), "+f"(c1), "+f"(c2), "+f"(c3)
                 : "r"(a0), "r"(a1), "r"(a2), "r"(a3), "r"(b0), "r"(b1));
}
__device__ __forceinline__ void cpa16(uint32_t saddr, const void* gaddr) {
    asm volatile("cp.async.cg.shared.global [%0], [%1], 16;" :: "r"(saddr), "l"(gaddr));
}

// ---------------- kernels ----------------

__global__ void k_embed(const int* __restrict__ seq, const float* __restrict__ emb) {
    int i = blockIdx.x * blockDim.x + threadIdx.x;
    if (i < M2*HH) {
        int m = i / HH, h = i - m*HH;
        g_emb[i] = emb[(long)seq[m]*HH + h];
    }
}

// A pack for the big GEMM
__global__ void k_pack_a(const float* __restrict__ A) {
    long i = (long)blockIdx.x * 256 + threadIdx.x;
    if (i >= (long)(M2/128)*64*8*32) return;
    int lane = (int)(i & 31), mf = (int)((i >> 5) & 7), s = (int)((i >> 8) & 63);
    long mb = i >> 14;
    int lq = lane >> 2, lr = lane & 3;
    int k = s*8 + lr;
    long me = mb*128 + mf*16 + lq;
    uint4 v;
    v.x = f2tf(A[me*HH + k]);
    v.y = f2tf(A[(me+8)*HH + k]);
    v.z = f2tf(A[me*HH + k + 4]);
    v.w = f2tf(A[(me+8)*HH + k + 4]);
    ((uint4*)g_at)[i] = v;
}

// ---------------- packed tf32 GEMM: C[M2,VV] = A[M2,HH] * W[VV,HH]^T + bias ----------------
__global__ __launch_bounds__(128, 2)
void k_gemm_tf32p(const uint4* __restrict__ At, const uint4* __restrict__ Wt,
                  const float* __restrict__ bias, float* __restrict__ C) {
    __shared__ __align__(16) uint4 As[2][512];
    __shared__ __align__(16) uint4 Bs[2][512];
    int tid = threadIdx.x;
    int warp = tid >> 5, lane = tid & 31;
    int wm = warp & 1, wnp = warp >> 1;
    int lq = lane >> 2, lr = lane & 3;
    int m0 = blockIdx.x * 128, n0 = blockIdx.y * 128;
    const uint4* Ab = At + (long)blockIdx.x * 16384;
    const uint4* Bb = Wt + (long)blockIdx.y * 16384;

    float acc[4][8][4];
#pragma unroll
    for (int i = 0; i < 4; i++)
#pragma unroll
        for (int j = 0; j < 8; j++)
#pragma unroll
            for (int c = 0; c < 4; c++) acc[i][j][c] = 0.f;

#pragma unroll
    for (int i = 0; i < 4; i++) {
        cpa16(smem_u32(&As[0][i*128 + tid]), Ab + i*128 + tid);
        cpa16(smem_u32(&Bs[0][i*128 + tid]), Bb + i*128 + tid);
    }
    asm volatile("cp.async.commit_group;");

    int buf = 0;
    const int NK = HH / 16;    // 32 k16 tiles
    for (int c = 0; c < NK; c++) {
        asm volatile("cp.async.wait_group 0;" ::: "memory");
        __syncthreads();
        if (c + 1 < NK) {
            const uint4* an = Ab + (c+1)*512;
            const uint4* bn = Bb + (c+1)*512;
#pragma unroll
            for (int i = 0; i < 4; i++) {
                cpa16(smem_u32(&As[buf^1][i*128 + tid]), an + i*128 + tid);
                cpa16(smem_u32(&Bs[buf^1][i*128 + tid]), bn + i*128 + tid);
            }
            asm volatile("cp.async.commit_group;");
        }
#pragma unroll
        for (int kk = 0; kk < 2; kk++) {
            uint4 av[4], bv[4];
#pragma unroll
            for (int ms = 0; ms < 4; ms++)
                av[ms] = As[buf][kk*256 + (wm*4 + ms)*32 + lane];
#pragma unroll
            for (int p = 0; p < 4; p++)
                bv[p] = Bs[buf][kk*256 + (wnp*4 + p)*32 + lane];
#pragma unroll
            for (int ms = 0; ms < 4; ms++)
#pragma unroll
                for (int p = 0; p < 4; p++) {
                    mma_tf32(acc[ms][2*p][0], acc[ms][2*p][1], acc[ms][2*p][2], acc[ms][2*p][3],
                             av[ms].x, av[ms].y, av[ms].z, av[ms].w, bv[p].x, bv[p].y);
                    mma_tf32(acc[ms][2*p+1][0], acc[ms][2*p+1][1], acc[ms][2*p+1][2], acc[ms][2*p+1][3],
                             av[ms].x, av[ms].y, av[ms].z, av[ms].w, bv[p].z, bv[p].w);
                }
        }
        buf ^= 1;
    }
#pragma unroll
    for (int ms = 0; ms < 4; ms++) {
        int row = m0 + wm*64 + ms*16 + lq;
#pragma unroll
        for (int ns = 0; ns < 8; ns++) {
            int col = n0 + wnp*64 + ns*8 + lr*2;
            float b0 = bias[col], b1 = bias[col+1];
            *(float2*)(C + (long)row*VV + col)     = make_float2(acc[ms][ns][0] + b0, acc[ms][ns][1] + b1);
            *(float2*)(C + (long)(row+8)*VV + col) = make_float2(acc[ms][ns][2] + b0, acc[ms][ns][3] + b1);
        }
    }
}

// ---------------- mega kernel: persistent GRU (blocks 0..127) + side work (128..147) ----------------
__global__ __launch_bounds__(512, 1)
void k_gru_all(const float* __restrict__ lasth, const float* __restrict__ Whh,
               const float* __restrict__ bhh, float* __restrict__ hid,
               const float* __restrict__ outW,
               const float* __restrict__ attnW, const float* __restrict__ attnv,
               const float* __restrict__ attnb, const float* __restrict__ attrW,
               const float* __restrict__ attrv, const float* __restrict__ attrb,
               const float* __restrict__ enc4, const float* __restrict__ projW,
               const float* __restrict__ projb, const int* __restrict__ asp) {
    extern __shared__ __align__(16) float dsm[];
    int tid = threadIdx.x, bk = blockIdx.x;

    if (bk >= GRU_BLOCKS) {
        // ===================== side work on 20 spare SMs =====================
        int sb = bk - GRU_BLOCKS;
        // (a) W fragment pack (grid-strided over side blocks)
        const long TOTW = (long)(VV/128)*64*8*32;
        for (long i = (long)sb*512 + tid; i < TOTW; i += (long)SIDE_BLOCKS*512) {
            int lane = (int)(i & 31), fp = (int)((i >> 5) & 7), s = (int)((i >> 8) & 63);
            long nb = i >> 14;
            int lq = lane >> 2, lr = lane & 3;
            int k = s*8 + lr;
            long ne = nb*128 + fp*16 + lq;
            uint4 v;
            v.x = f2tf(outW[ne*HH + k]);
            v.y = f2tf(outW[ne*HH + k + 4]);
            v.z = f2tf(outW[(ne+8)*HH + k]);
            v.w = f2tf(outW[(ne+8)*HH + k + 4]);
            ((uint4*)g_wt)[i] = v;
        }
        // (b) uvec: full-column warp dots (no partials)
        {
            int gw2 = sb*16 + (tid >> 5);
            int lane = tid & 31;
            for (int t = gw2; t < UCOLS + 2; t += SIDE_BLOCKS*16) {
                float s = 0.f;
                if (t < UCOLS) {
                    const float* W; const float* v; int ld; int c;
                    if (t < 2*HH) { W = attnW; v = attnv; ld = 2*HH;    c = t; }
                    else          { W = attrW; v = attrv; ld = HH + KK; c = t - 2*HH; }
                    for (int h = lane; h < HH; h += 32) s += W[(long)h*ld + c]*v[h];
#pragma unroll
                    for (int o = 16; o > 0; o >>= 1) s += __shfl_xor_sync(0xffffffffu, s, o);
                    if (lane == 0) {
                        if (t < HH)            g_u1[t] = s;
                        else if (t < 2*HH)     g_u1e[t - HH] = s;
                        else if (t < 3*HH)     g_u3[t - 2*HH] = s;
                        else                   g_u3e[t - 3*HH] = s;
                    }
                } else {
                    int w = t - UCOLS;   // 0 or 1
                    const float* bp = w ? attrb : attnb;
                    const float* vp = w ? attrv : attnv;
                    for (int h = lane; h < HH; h += 32) s += bp[h]*vp[h];
#pragma unroll
                    for (int o = 16; o > 0; o >>= 1) s += __shfl_xor_sync(0xffffffffu, s, o);
                    if (lane == 0) g_bv[w] = s;
                }
            }
        }
        // (c) e4 projection (block sb==0)
        if (sb == 0) {
            for (int i = tid; i < BB*AN; i += 512) {
                int b = i / AN, j = i - b*AN;
                float s = projb[j];
                for (int k = 0; k < AN; k++) s += enc4[(0*BB + b)*AN + k]*projW[j*2*AN + k];
                for (int k = 0; k < AN; k++) s += enc4[(1*BB + b)*AN + k]*projW[j*2*AN + AN + k];
                g_e4[i] = s;
            }
        }
        // (d) duplicate-chain (block sb==1), smem lockstep scan
        if (sb == 1) {
            int* sid = (int*)dsm;
            for (int k = tid; k < NASP; k += 512) sid[k] = asp[k];
            __syncthreads();
            for (int j = tid; j < NASP; j += 512) {
                int v = sid[j];
                int fst = 1, nxt = -1;
                for (int j2 = 0; j2 < NASP; j2++) {
                    int w = sid[j2];
                    if (w == v) {
                        if (j2 < j) fst = 0;
                        else if (j2 > j && nxt < 0) nxt = j2;
                    }
                }
                g_first[j] = fst;
                g_next[j]  = nxt;
            }
        }
        return;
    }

    // ===================== persistent GRU =====================
    float* sw   = dsm;                    // 6144
    float* sh   = dsm + 6144;             // 16384
    float* part = dsm + 6144 + 16384;     // 3072
    float* sbv  = part + 3072;            // 12

    int b  = tid & 31;
    int ju = (tid >> 5) & 1;
    int kq = tid >> 6;                    // 0..7

    for (int r = 0; r < 12; r++) {
        int g = r / 4, j = r % 4;
        int rowi = g*HH + bk*4 + j;
        for (int k = tid; k < HH; k += 512) sw[(g*4 + j)*HH + k] = Whh[(long)rowi*HH + k];
    }
    if (tid < 12) sbv[tid] = bhh[(tid/4)*HH + bk*4 + (tid%4)];

    if (tid < 128) {
        int idx = bk*128 + tid;
        int k = idx >> 5, bb = idx & 31;
        __stcg(&g_hA[idx], lasth[bb*HH + k]);
    }
    gru_barrier(bk, 1u);

    float* hp = g_hA;
    float* hc = g_hB;
    int u0 = ju*2;                        // units u0, u0+1
    const float* wr0 = sw + (0*4 + u0    )*HH;
    const float* wr1 = sw + (0*4 + u0 + 1)*HH;
    const float* wz0 = sw + (1*4 + u0    )*HH;
    const float* wz1 = sw + (1*4 + u0 + 1)*HH;
    const float* wn0 = sw + (2*4 + u0    )*HH;
    const float* wn1 = sw + (2*4 + u0 + 1)*HH;
    int k0 = kq * 64;

    for (int n = 0; n < NN; n++) {
#pragma unroll
        for (int i = 0; i < 8; i++) {
            int f = tid + i*512;
            float4 v = __ldcg((const float4*)hp + f);
            *(float4*)(sh + 4*f) = v;
        }
        __syncthreads();

        float sr0 = 0.f, sz0 = 0.f, sn0 = 0.f;
        float sr1 = 0.f, sz1 = 0.f, sn1 = 0.f;
#pragma unroll 4
        for (int k = k0; k < k0 + 64; k += 4) {
            float h0 = sh[(k+0)*BB + b];
            float h1 = sh[(k+1)*BB + b];
            float h2 = sh[(k+2)*BB + b];
            float h3 = sh[(k+3)*BB + b];
            float4 a;
            a = *(const float4*)(wr0 + k); sr0 += a.x*h0 + a.y*h1 + a.z*h2 + a.w*h3;
            a = *(const float4*)(wz0 + k); sz0 += a.x*h0 + a.y*h1 + a.z*h2 + a.w*h3;
            a = *(const float4*)(wn0 + k); sn0 += a.x*h0 + a.y*h1 + a.z*h2 + a.w*h3;
            a = *(const float4*)(wr1 + k); sr1 += a.x*h0 + a.y*h1 + a.z*h2 + a.w*h3;
            a = *(const float4*)(wz1 + k); sz1 += a.x*h0 + a.y*h1 + a.z*h2 + a.w*h3;
            a = *(const float4*)(wn1 + k); sn1 += a.x*h0 + a.y*h1 + a.z*h2 + a.w*h3;
        }
        part[((0*4 + u0    )*8 + kq)*32 + b] = sr0;
        part[((1*4 + u0    )*8 + kq)*32 + b] = sz0;
        part[((2*4 + u0    )*8 + kq)*32 + b] = sn0;
        part[((0*4 + u0 + 1)*8 + kq)*32 + b] = sr1;
        part[((1*4 + u0 + 1)*8 + kq)*32 + b] = sz1;
        part[((2*4 + u0 + 1)*8 + kq)*32 + b] = sn1;
        __syncthreads();

        if (kq < 2) {                     // split epilogue: kq==0 -> unit u0, kq==1 -> unit u0+1
            int jgl = u0 + kq;
            int jg  = bk*4 + jgl;
            float sr = 0.f, sz = 0.f, sn = 0.f;
#pragma unroll
            for (int q = 0; q < 8; q++) {
                sr += part[((0*4 + jgl)*8 + q)*32 + b];
                sz += part[((1*4 + jgl)*8 + q)*32 + b];
                sn += part[((2*4 + jgl)*8 + q)*32 + b];
            }
            float hold = sh[jg*BB + b];
            const float* gi = g_gi + ((long)(n*BB + b))*(3*HH);
            float rr = 1.f/(1.f + expf(-(gi[jg]        + sr + sbv[0*4 + jgl])));
            float zz = 1.f/(1.f + expf(-(gi[HH + jg]   + sz + sbv[1*4 + jgl])));
            float nn = tanhf(gi[2*HH + jg] + rr*(sn + sbv[2*4 + jgl]));
            float hn = (1.f - zz)*nn + zz*hold;
            __stcg(hc + jg*BB + b, hn);
            g_rnn[((long)(n*BB + b))*HH + jg] = hn;
            if (n == NN-1) hid[b*HH + jg] = hn;
        }
        if (n < NN-1) gru_barrier(bk, (unsigned)(n + 2));
        float* t = hp; hp = hc; hc = t;
    }
}

// ---------------- tf32 mma GEMM (concat path, cvt at use) ----------------
__device__ __forceinline__ const float* concat_src(int m, int k) {
    if (k < HH)        return g_rnn  + (long)m*HH + k;
    if (k < 2*HH)      return g_ctx1 + (long)m*HH + (k - HH);
    if (k < 3*HH)      return g_ctx2 + (long)m*HH + (k - 2*HH);
    return g_ctx3 + (long)m*KK + (k - 3*HH);
}

template<int ASRC>
__global__ __launch_bounds__(128, 2)
void k_gemm_tf32(const float* __restrict__ A, const float* __restrict__ W,
                 const float* __restrict__ bias, float* __restrict__ C,
                 int Kd, int ldC, int act) {
    __shared__ __align__(16) float As[2][128][20];
    __shared__ __align__(16) float Bs[2][128][20];
    int tid = threadIdx.x;
    int warp = tid >> 5, lane = tid & 31;
    int wm = warp & 1, wnp = warp >> 1;
    int lq = lane >> 2, lr = lane & 3;
    int m0 = blockIdx.y * 128, n0 = blockIdx.x * 128;

    float acc[4][8][4];
#pragma unroll
    for (int i = 0; i < 4; i++)
#pragma unroll
        for (int j = 0; j < 8; j++)
#pragma unroll
            for (int c = 0; c < 4; c++) acc[i][j][c] = 0.f;

    const int NK = Kd / 16;
#pragma unroll
    for (int i = 0; i < 4; i++) {
        int idx = i*128 + tid, row = idx >> 2, kc = idx & 3;
        const float* asrc = ASRC ? concat_src(m0+row, kc*4)
                                 : A + (long)(m0+row)*Kd + kc*4;
        cpa16(smem_u32(&As[0][row][kc*4]), asrc);
        cpa16(smem_u32(&Bs[0][row][kc*4]), W + (long)(n0+row)*Kd + kc*4);
    }
    asm volatile("cp.async.commit_group;");

    int buf = 0;
    for (int ks = 0; ks < NK; ks++) {
        asm volatile("cp.async.wait_group 0;");
        __syncthreads();
        if (ks + 1 < NK) {
#pragma unroll
            for (int i = 0; i < 4; i++) {
                int idx = i*128 + tid, row = idx >> 2, kc = idx & 3;
                int kpos = (ks+1)*16 + kc*4;
                const float* asrc = ASRC ? concat_src(m0+row, kpos)
                                         : A + (long)(m0+row)*Kd + kpos;
                cpa16(smem_u32(&As[buf^1][row][kc*4]), asrc);
                cpa16(smem_u32(&Bs[buf^1][row][kc*4]), W + (long)(n0+row)*Kd + kpos);
            }
            asm volatile("cp.async.commit_group;");
        }
#pragma unroll
        for (int kk = 0; kk < 16; kk += 8) {
            uint32_t af[4][4], bf[8][2];
#pragma unroll
            for (int ms = 0; ms < 4; ms++) {
                int rb = wm*64 + ms*16;
                af[ms][0] = f2tf(As[buf][rb + lq    ][kk + lr    ]);
                af[ms][1] = f2tf(As[buf][rb + lq + 8][kk + lr    ]);
                af[ms][2] = f2tf(As[buf][rb + lq    ][kk + lr + 4]);
                af[ms][3] = f2tf(As[buf][rb + lq + 8][kk + lr + 4]);
            }
#pragma unroll
            for (int ns = 0; ns < 8; ns++) {
                int nb = wnp*64 + ns*8;
                bf[ns][0] = f2tf(Bs[buf][nb + lq][kk + lr    ]);
                bf[ns][1] = f2tf(Bs[buf][nb + lq][kk + lr + 4]);
            }
#pragma unroll
            for (int ms = 0; ms < 4; ms++)
#pragma unroll
                for (int ns = 0; ns < 8; ns++)
                    mma_tf32(acc[ms][ns][0], acc[ms][ns][1], acc[ms][ns][2], acc[ms][ns][3],
                             af[ms][0], af[ms][1], af[ms][2], af[ms][3],
                             bf[ns][0], bf[ns][1]);
        }
        buf ^= 1;
    }
#pragma unroll
    for (int ms = 0; ms < 4; ms++) {
        int row = m0 + wm*64 + ms*16 + lq;
#pragma unroll
        for (int ns = 0; ns < 8; ns++) {
            int col = n0 + wnp*64 + ns*8 + lr*2;
            float b0 = bias[col], b1 = bias[col+1];
            float v00 = acc[ms][ns][0] + b0, v01 = acc[ms][ns][1] + b1;
            float v10 = acc[ms][ns][2] + b0, v11 = acc[ms][ns][3] + b1;
            if (act) { v00 = tanhf(v00); v01 = tanhf(v01); v10 = tanhf(v10); v11 = tanhf(v11); }
            *(float2*)(C + (long)row*ldC + col)     = make_float2(v00, v01);
            *(float2*)(C + (long)(row+8)*ldC + col) = make_float2(v10, v11);
        }
    }
}

// split-precision tf32 GEMM (fp32-accurate) for gi
__global__ __launch_bounds__(256)
void k_gemm_tf32s(const float* __restrict__ A, const float* __restrict__ W,
                  const float* __restrict__ bias, float* __restrict__ C,
                  int Kd, int ldC) {
    __shared__ __align__(16) float As[2][128][20];
    __shared__ __align__(16) float Bs[2][128][20];
    int tid = threadIdx.x;
    int warp = tid >> 5, lane = tid & 31;
    int wm = warp & 1, wn = warp >> 1;
    int lq = lane >> 2, lr = lane & 3;
    int m0 = blockIdx.y * 128, n0 = blockIdx.x * 128;

    float acc[4][4][4];
#pragma unroll
    for (int i = 0; i < 4; i++)
#pragma unroll
        for (int j = 0; j < 4; j++)
#pragma unroll
            for (int c = 0; c < 4; c++) acc[i][j][c] = 0.f;

    const int NK = Kd / 16;
#pragma unroll
    for (int i = 0; i < 2; i++) {
        int idx = i*256 + tid, row = idx >> 2, kc = idx & 3;
        cpa16(smem_u32(&As[0][row][kc*4]), A + (long)(m0+row)*Kd + kc*4);
        cpa16(smem_u32(&Bs[0][row][kc*4]), W + (long)(n0+row)*Kd + kc*4);
    }
    asm volatile("cp.async.commit_group;");

    int buf = 0;
    for (int ks = 0; ks < NK; ks++) {
        asm volatile("cp.async.wait_group 0;");
        __syncthreads();
        if (ks + 1 < NK) {
#pragma unroll
            for (int i = 0; i < 2; i++) {
                int idx = i*256 + tid, row = idx >> 2, kc = idx & 3;
                int kpos = (ks+1)*16 + kc*4;
                cpa16(smem_u32(&As[buf^1][row][kc*4]), A + (long)(m0+row)*Kd + kpos);
                cpa16(smem_u32(&Bs[buf^1][row][kc*4]), W + (long)(n0+row)*Kd + kpos);
            }
            asm volatile("cp.async.commit_group;");
        }
#pragma unroll
        for (int kk = 0; kk < 16; kk += 8) {
            uint32_t ah[4][4], al[4][4], bh[4][2], bl[4][2];
#pragma unroll
            for (int ms = 0; ms < 4; ms++) {
                int rb = wm*64 + ms*16;
                split_tf32(As[buf][rb + lq    ][kk + lr    ], ah[ms][0], al[ms][0]);
                split_tf32(As[buf][rb + lq + 8][kk + lr    ], ah[ms][1], al[ms][1]);
                split_tf32(As[buf][rb + lq    ][kk + lr + 4], ah[ms][2], al[ms][2]);
                split_tf32(As[buf][rb + lq + 8][kk + lr + 4], ah[ms][3], al[ms][3]);
            }
#pragma unroll
            for (int ns = 0; ns < 4; ns++) {
                int nb = wn*32 + ns*8;
                split_tf32(Bs[buf][nb + lq][kk + lr    ], bh[ns][0], bl[ns][0]);
                split_tf32(Bs[buf][nb + lq][kk + lr + 4], bh[ns][1], bl[ns][1]);
            }
#pragma unroll
            for (int ms = 0; ms < 4; ms++)
#pragma unroll
                for (int ns = 0; ns < 4; ns++) {
                    mma_tf32(acc[ms][ns][0], acc[ms][ns][1], acc[ms][ns][2], acc[ms][ns][3],
                             ah[ms][0], ah[ms][1], ah[ms][2], ah[ms][3], bh[ns][0], bh[ns][1]);
                    mma_tf32(acc[ms][ns][0], acc[ms][ns][1], acc[ms][ns][2], acc[ms][ns][3],
                             ah[ms][0], ah[ms][1], ah[ms][2], ah[ms][3], bl[ns][0], bl[ns][1]);
                    mma_tf32(acc[ms][ns][0], acc[ms][ns][1], acc[ms][ns][2], acc[ms][ns][3],
                             al[ms][0], al[ms][1], al[ms][2], al[ms][3], bh[ns][0], bh[ns][1]);
                }
        }
        buf ^= 1;
    }
#pragma unroll
    for (int ms = 0; ms < 4; ms++) {
        int row = m0 + wm*64 + ms*16 + lq;
#pragma unroll
        for (int ns = 0; ns < 4; ns++) {
            int col = n0 + wn*32 + ns*8 + lr*2;
            float b0 = bias[col], b1 = bias[col+1];
            *(float2*)(C + (long)row*ldC + col)     = make_float2(acc[ms][ns][0] + b0, acc[ms][ns][1] + b1);
            *(float2*)(C + (long)(row+8)*ldC + col) = make_float2(acc[ms][ns][2] + b0, acc[ms][ns][3] + b1);
        }
    }
}

// all scalar attention dot products
__global__ void k_ac(const float* __restrict__ enc1, const float* __restrict__ enc2,
                     const float* __restrict__ enc3) {
    int gw = (blockIdx.x * blockDim.x + threadIdx.x) >> 5;
    int lane = threadIdx.x & 31;
    const int E_A = M2, E_C1 = E_A + TT*BB, E_C2 = E_C1 + SS*BB, E_C3 = E_C2 + AA*BB;
    if (gw >= E_C3) return;
    if (gw < E_A) {
        const float4* x = (const float4*)(g_rnn + (long)gw*HH);
        const float4* u1 = (const float4*)g_u1;
        const float4* u3 = (const float4*)g_u3;
        float s1 = 0.f, s3 = 0.f;
#pragma unroll
        for (int k = lane; k < HH/4; k += 32) {
            float4 xv = x[k], a = u1[k], b = u3[k];
            s1 += xv.x*a.x + xv.y*a.y + xv.z*a.z + xv.w*a.w;
            s3 += xv.x*b.x + xv.y*b.y + xv.z*b.z + xv.w*b.w;
        }
#pragma unroll
        for (int o = 16; o > 0; o >>= 1) {
            s1 += __shfl_xor_sync(0xffffffffu, s1, o);
            s3 += __shfl_xor_sync(0xffffffffu, s3, o);
        }
        if (lane == 0) { g_a1[gw] = s1 + g_bv[0]; g_a3[gw] = s3 + g_bv[1]; }
        return;
    }
    const float* x; const float* u; float* dst; int len = HH;
    if (gw < E_C1)      { int m = gw - E_A;   x = enc1 + (long)m*HH; u = g_u1e; dst = g_c1 + m; }
    else if (gw < E_C2) { int m = gw - E_C1;  x = enc2 + (long)m*HH; u = g_u1e; dst = g_c2 + m; }
    else                { int m = gw - E_C2;  x = enc3 + (long)m*KK; u = g_u3e; dst = g_c3 + m; len = KK; }
    const float4* x4 = (const float4*)x;
    const float4* u4 = (const float4*)u;
    float s = 0.f;
    for (int k = lane; k < len/4; k += 32) {
        float4 xv = x4[k], uv = u4[k];
        s += xv.x*uv.x + xv.y*uv.y + xv.z*uv.z + xv.w*uv.w;
    }
#pragma unroll
    for (int o = 16; o > 0; o >>= 1) s += __shfl_xor_sync(0xffffffffu, s, o);
    if (lane == 0) *dst = s;
}

__global__ void k_softmax1(float* __restrict__ aw1) {
    int bn = blockIdx.x;
    int b = bn / NN, n = bn - b*NN;
    int t = threadIdx.x;
    float e  = tanhf(g_a1[n*BB + b] + g_c1[t*BB + b]);
    float ex = expf(e);
    __shared__ float red[8];
    __shared__ float stot;
    float s = ex;
#pragma unroll
    for (int o = 16; o > 0; o >>= 1) s += __shfl_xor_sync(0xffffffffu, s, o);
    if ((t & 31) == 0) red[t >> 5] = s;
    __syncthreads();
    if (t == 0) { float tt = 0.f; for (int i = 0; i < 8; i++) tt += red[i]; stot = tt; }
    __syncthreads();
    aw1[(long)bn*TT + t] = ex / stot;
}

__global__ void k_softmax2(float* __restrict__ aw2) {
    int gw = (blockIdx.x * blockDim.x + threadIdx.x) >> 5;
    if (gw >= BB*NN) return;
    int b = gw / NN, n = gw - b*NN;
    int s = threadIdx.x & 31;
    float e  = tanhf(g_a1[n*BB + b] + g_c2[s*BB + b]);
    float ex = expf(e);
    float tot = ex;
#pragma unroll
    for (int o = 16; o > 0; o >>= 1) tot += __shfl_xor_sync(0xffffffffu, tot, o);
    aw2[(long)gw*SS + s] = ex / tot;
}

__global__ void k_softmax3(float* __restrict__ aw3) {
    int bn = blockIdx.x * blockDim.x + threadIdx.x;
    if (bn >= BB*NN) return;
    int b = bn / NN, n = bn - b*NN;
    float ex[AA]; float tot = 0.f;
#pragma unroll
    for (int a = 0; a < AA; a++) {
        ex[a] = expf(tanhf(g_a3[n*BB + b] + g_c3[a*BB + b]));
        tot += ex[a];
    }
#pragma unroll
    for (int a = 0; a < AA; a++) aw3[(long)bn*AA + a] = ex[a] / tot;
}

// tiled ctx
__global__ void k_ctx_t(const float* __restrict__ aw, const float* __restrict__ enc,
                        float* __restrict__ dst, int L, int D) {
    int b  = blockIdx.x;
    int h0 = blockIdx.y * 64;
    int tid = threadIdx.x;
    __shared__ float AWs[64][33];
    __shared__ float Es[32][68];
    int tx = tid & 15, ty = tid >> 4;
    float acc[4][4] = {};
    for (int t0 = 0; t0 < L; t0 += 32) {
        {
            int row = tid >> 2, c0 = (tid & 3) * 8;
            const float* ap = aw + ((long)b*NN + row)*L + t0 + c0;
            float4 v0 = *(const float4*)ap;
            float4 v1 = *(const float4*)(ap + 4);
            AWs[row][c0+0]=v0.x; AWs[row][c0+1]=v0.y; AWs[row][c0+2]=v0.z; AWs[row][c0+3]=v0.w;
            AWs[row][c0+4]=v1.x; AWs[row][c0+5]=v1.y; AWs[row][c0+6]=v1.z; AWs[row][c0+7]=v1.w;
        }
        {
            int row = tid >> 3, c0 = (tid & 7) * 8;
            const float* ep = enc + (((long)(t0+row))*BB + b)*D + h0 + c0;
            float4 v0 = *(const float4*)ep;
            float4 v1 = *(const float4*)(ep + 4);
            Es[row][c0+0]=v0.x; Es[row][c0+1]=v0.y; Es[row][c0+2]=v0.z; Es[row][c0+3]=v0.w;
            Es[row][c0+4]=v1.x; Es[row][c0+5]=v1.y; Es[row][c0+6]=v1.z; Es[row][c0+7]=v1.w;
        }
        __syncthreads();
#pragma unroll
        for (int tt = 0; tt < 32; tt++) {
            float a[4], e[4];
#pragma unroll
            for (int i = 0; i < 4; i++) { a[i] = AWs[ty*4+i][tt]; e[i] = Es[tt][tx*4+i]; }
#pragma unroll
            for (int i = 0; i < 4; i++)
#pragma unroll
                for (int j = 0; j < 4; j++) acc[i][j] += a[i]*e[j];
        }
        __syncthreads();
    }
#pragma unroll
    for (int i = 0; i < 4; i++) {
        int n = ty*4 + i;
#pragma unroll
        for (int j = 0; j < 4; j++)
            dst[(((long)n)*BB + b)*D + h0 + tx*4 + j] = acc[i][j];
    }
}

// naive ctx (L=5, D=128)
__global__ void k_ctx(const float* __restrict__ aw, const float* __restrict__ enc,
                      float* __restrict__ dst, int L, int D) {
    int i = blockIdx.x * blockDim.x + threadIdx.x;
    if (i >= M2*KK) return;
    int m = i / D, h = i - m*D;
    int n = m / BB, b = m - n*BB;
    const float* awp = aw + ((long)b*NN + n)*L;
    float s = 0.f;
    for (int t = 0; t < L; t++) s += awp[t]*enc[((long)t*BB + b)*D + h];
    dst[i] = s;
}

__global__ void k_gate2(const float* __restrict__ gateW, const float* __restrict__ gateb,
                        float* __restrict__ gateout) {
    int m0 = blockIdx.x * 4;
    int tid = threadIdx.x;
    __shared__ float xs[4][GIN + 12];
#pragma unroll
    for (int r = 0; r < 4; r++) {
        int m = m0 + r, b = m & 31;
        for (int k = tid; k < GIN; k += 256) {
            float v;
            if (k < HH)        v = g_emb[(long)m*HH + k];
            else if (k < 2*HH) v = g_rnn[(long)m*HH + k - HH];
            else               v = g_e4[b*AN + k - 2*HH];
            xs[r][k] = v;
        }
    }
    __syncthreads();
    int w = tid >> 5, lane = tid & 31;
    for (int o = w; o < 4*AN; o += 8) {
        int r = o & 3, j = o >> 2;
        const float* wj = gateW + (long)j*GIN;
        float s = 0.f;
        for (int k = lane; k < GIN; k += 32) s += xs[r][k]*wj[k];
#pragma unroll
        for (int of = 16; of > 0; of >>= 1) s += __shfl_xor_sync(0xffffffffu, s, of);
        if (lane == 0) gateout[(long)(m0+r)*AN + j] = tanhf(s + gateb[j]);
    }
}

__global__ void k_scatter(const float* __restrict__ gate, const int* __restrict__ ids,
                          float* __restrict__ out0) {
    long i = (long)blockIdx.x * blockDim.x + threadIdx.x;
    if (i >= (long)M2*NASP) return;
    int m = (int)(i / NASP);
    int j = (int)(i - (long)m*NASP);
    if (!g_first[j]) return;
    float s = 0.f;
    int jj = j;
    while (jj >= 0) { s += gate[(long)m*AN + (jj % AN)]; jj = g_next[jj]; }
    out0[(long)m*VV + ids[j]] += s;
}

// ---------------- launcher ----------------
extern "C" void kernel_launch(void* const* d_in, const int* in_sizes, int n_in,
                              void* d_out, int out_size) {
    const int*   seq   = (const int*)  d_in[0];
    const float* lasth = (const float*)d_in[1];
    const float* enc1  = (const float*)d_in[2];
    const float* enc2  = (const float*)d_in[3];
    const float* enc3  = (const float*)d_in[4];
    const float* enc4  = (const float*)d_in[5];
    const int*   asp   = (const int*)  d_in[6];
    const float* emb   = (const float*)d_in[7];
    const float* Wih   = (const float*)d_in[8];
    const float* Whh   = (const float*)d_in[9];
    const float* bih   = (const float*)d_in[10];
    const float* bhh   = (const float*)d_in[11];
    const float* attnW = (const float*)d_in[12];
    const float* attnb = (const float*)d_in[13];
    const float* attnv = (const float*)d_in[14];
    const float* attrW = (const float*)d_in[15];
    const float* attrb = (const float*)d_in[16];
    const float* attrv = (const float*)d_in[17];
    const float* concW = (const float*)d_in[18];
    const float* concb = (const float*)d_in[19];
    const float* outW  = (const float*)d_in[20];
    const float* outb  = (const float*)d_in[21];
    const float* gateW = (const float*)d_in[22];
    const float* gateb = (const float*)d_in[23];
    const float* projW = (const float*)d_in[24];
    const float* projb = (const float*)d_in[25];
    float* out = (float*)d_out;

    const long O_HID  = (long)M2*VV;
    const long O_AW1  = O_HID + (long)BB*HH;
    const long O_AW2  = O_AW1 + (long)BB*NN*TT;
    const long O_AW3  = O_AW2 + (long)BB*NN*SS;
    const long O_GATE = O_AW3 + (long)BB*NN*AA;

    float *p_emb, *p_gi, *p_cout, *p_ctx1, *p_ctx2, *p_ctx3;
    uint32_t *p_wt, *p_at;
    cudaGetSymbolAddress((void**)&p_emb,  g_emb);
    cudaGetSymbolAddress((void**)&p_gi,   g_gi);
    cudaGetSymbolAddress((void**)&p_cout, g_cout);
    cudaGetSymbolAddress((void**)&p_ctx1, g_ctx1);
    cudaGetSymbolAddress((void**)&p_ctx2, g_ctx2);
    cudaGetSymbolAddress((void**)&p_ctx3, g_ctx3);
    cudaGetSymbolAddress((void**)&p_wt,   g_wt);
    cudaGetSymbolAddress((void**)&p_at,   g_at);

    const int GRU_SMEM = (6144 + 16384 + 3072 + 16) * 4;   // ~100KB
    cudaFuncSetAttribute(k_gru_all, cudaFuncAttributeMaxDynamicSharedMemorySize, GRU_SMEM);

    // 1) embedding
    k_embed<<<(M2*HH + 255)/256, 256>>>(seq, emb);

    // 2) gi = embedded @ Wih^T + bih (split-tf32, fp32-accurate)
    k_gemm_tf32s<<<dim3((3*HH)/128, M2/128), 256>>>(p_emb, Wih, bih, p_gi, HH, 3*HH);

    // 3) mega kernel: persistent GRU (128 blocks) + side work (pack_w, uvec, e4, chain) on 20 spare SMs
    k_gru_all<<<GRU_BLOCKS + SIDE_BLOCKS, 512, GRU_SMEM>>>(
        lasth, Whh, bhh, out + O_HID,
        outW, attnW, attnv, attnb, attrW, attrv, attrb, enc4, projW, projb, asp);
    k_flagreset<<<1, 128>>>();

    // 4) scalar attention dots (uses u vectors produced by side blocks)
    {
        int warps = M2 + TT*BB + SS*BB + AA*BB;
        k_ac<<<(warps*32 + 255)/256, 256>>>(enc1, enc2, enc3);
    }

    // 5) softmaxes
    k_softmax1<<<BB*NN, TT>>>(out + O_AW1);
    k_softmax2<<<(BB*NN*32 + 255)/256, 256>>>(out + O_AW2);
    k_softmax3<<<(BB*NN + 255)/256, 256>>>(out + O_AW3);

    // 6) contexts
    k_ctx_t<<<dim3(BB, HH/64), 256>>>(out + O_AW1, enc1, p_ctx1, TT, HH);
    k_ctx_t<<<dim3(BB, HH/64), 256>>>(out + O_AW2, enc2, p_ctx2, SS, HH);
    k_ctx  <<<(M2*KK + 255)/256, 256>>>(out + O_AW3, enc3, p_ctx3, AA, KK);

    // 7) concat GEMM (tf32) -> A pack -> packed tf32 big GEMM
    k_gemm_tf32<1><<<dim3(HH/128, M2/128), 128>>>(nullptr, concW, concb, p_cout, CIN, HH, 1);
    k_pack_a<<<(int)(((long)(M2/128)*64*8*32 + 255)/256), 256>>>(p_cout);
    k_gemm_tf32p<<<dim3(M2/128, VV/128), 128>>>((const uint4*)p_at, (const uint4*)p_wt, outb, out);

    // 8) gate path (e4 already computed by side blocks)
    k_gate2<<<M2/4, 256>>>(gateW, gateb, out + O_GATE);

    // 9) deterministic scatter-add (chain already computed by side blocks)
    k_scatter<<<(int)(((long)M2*NASP + 255)/256), 256>>>(out + O_GATE, asp, out);
}